// round 7
// baseline (speedup 1.0000x reference)
#include <cuda_runtime.h>
#include <cuda_fp16.h>
#include <math.h>
#include <stdint.h>

// ---------------------------------------------------------------------------
// Problem constants (GRID fixed: [[1,48,48],[1,32,64],[2,24,40]])
// ---------------------------------------------------------------------------
#define NTOK    6272
#define DMODEL  1152
#define HEADS   16
#define HDIM    72
#define IDIM    4304
#define DOUT    2048
#define MROWS   1568
#define MD4     4608
#define QKVW    3456
#define CIN     1536

// ---------------------------------------------------------------------------
// Scratch buffers
// ---------------------------------------------------------------------------
__device__ float  g_x    [NTOK * DMODEL];        // residual (fp32)
__device__ __half g_pix  [NTOK * CIN];           // pixel fp16
__device__ __half g_hh   [NTOK * DMODEL];        // LN out fp16
__device__ __half g_qkvh [NTOK * QKVW];          // qkv fp16
__device__ __half g_attnh[NTOK * DMODEL];        // attn out fp16
__device__ __half g_mlph [NTOK * IDIM];          // mlp hidden fp16
__device__ float  g_cos  [NTOK * 36];
__device__ float  g_sin  [NTOK * 36];

// packed fp16 weights: word[kk][n] = (W[2kk][n], W[2kk+1][n]); sizes in words
#define WS_PATCH (1536ULL / 2 * 1152)
#define WS_QKV   (1152ULL / 2 * 3456)
#define WS_PROJ  (1152ULL / 2 * 1152)
#define WS_FC1   (1152ULL / 2 * 4304)
#define WS_FC2   (4304ULL / 2 * 1152)
#define WS_MFC1  (4608ULL / 2 * 4608)
#define WS_MFC2  (4608ULL / 2 * 2048)
#define WO_PATCH 0ULL
#define WO_QKV   (WO_PATCH + WS_PATCH)
#define WO_PROJ  (WO_QKV + 2 * WS_QKV)
#define WO_FC1   (WO_PROJ + 2 * WS_PROJ)
#define WO_FC2   (WO_FC1 + 2 * WS_FC1)
#define WO_MFC1  (WO_FC2 + 2 * WS_FC2)
#define WO_MFC2  (WO_MFC1 + WS_MFC1)
#define WW_TOTAL (WO_MFC2 + WS_MFC2)
__device__ uint32_t g_wt[WW_TOTAL];

// ---------------------------------------------------------------------------
__device__ __forceinline__ void token_pos(int n, int& row, int& col, int& ih, int& iw)
{
    int local, h, w;
    if (n < 2304)      { local = n;          h = 48; w = 48; }
    else if (n < 4352) { local = n - 2304;   h = 32; w = 64; }
    else               { local = n - 4352;   h = 24; w = 40; }
    int rem = local % (h * w);
    int wb_cnt = w >> 1;
    int blk = rem >> 2, within = rem & 3;
    int hb = blk / wb_cnt, wb = blk % wb_cnt;
    row = hb * 2 + (within >> 1);
    col = wb * 2 + (within & 1);
    ih = h; iw = w;
}

__global__ void cossin_kernel()
{
    int idx = blockIdx.x * blockDim.x + threadIdx.x;
    if (idx >= NTOK * 36) return;
    int n = idx / 36, d = idx % 36;
    int row, col, ih, iw;
    token_pos(n, row, col, ih, iw);
    int j = (d < 18) ? d : d - 18;
    double p = (d < 18) ? (double)row : (double)col;
    double inv = 1.0 / pow(10000.0, (2.0 * (double)j) / 36.0);
    double ang = p * inv;
    g_cos[idx] = (float)cos(ang);
    g_sin[idx] = (float)sin(ang);
}

__global__ void posadd_kernel(const float* __restrict__ pos_table)
{
    int n = blockIdx.x;
    int row, col, ih, iw;
    token_pos(n, row, col, ih, iw);
    double hi = 47.0 * (double)row / (double)(ih - 1);
    double wi = 47.0 * (double)col / (double)(iw - 1);
    int hf = (int)floor(hi), wf = (int)floor(wi);
    float dh = (float)(hi - (double)hf), dw = (float)(wi - (double)wf);
    int hc = min(hf + 1, 47), wc = min(wf + 1, 47);
    float w00 = (1.f - dh) * (1.f - dw);
    float w01 = (1.f - dh) * dw;
    float w10 = dh * (1.f - dw);
    float w11 = dh * dw;
    const float* p00 = pos_table + (size_t)(hf * 48 + wf) * DMODEL;
    const float* p01 = pos_table + (size_t)(hf * 48 + wc) * DMODEL;
    const float* p10 = pos_table + (size_t)(hc * 48 + wf) * DMODEL;
    const float* p11 = pos_table + (size_t)(hc * 48 + wc) * DMODEL;
    float* xr = g_x + (size_t)n * DMODEL;
    for (int d = threadIdx.x; d < DMODEL; d += blockDim.x)
        xr[d] += p00[d] * w00 + p01[d] * w01 + p10[d] * w10 + p11[d] * w11;
}

__device__ __forceinline__ uint32_t pack_h2(float lo, float hi)
{
    __half2 h = __floats2half2_rn(lo, hi);
    return *reinterpret_cast<uint32_t*>(&h);
}

// fp32 -> fp16 elementwise
__global__ void conv_h(const float* __restrict__ in, __half* __restrict__ out, int n)
{
    int i = blockIdx.x * blockDim.x + threadIdx.x;
    if (i < n) out[i] = __float2half_rn(in[i]);
}

// W [K,N] fp32 -> packed word[kk][n] = (W[2kk][n], W[2kk+1][n])   (streaming)
__global__ void wpack(const float* __restrict__ W, uint32_t* __restrict__ out,
                      int K, int N)
{
    long long i = (long long)blockIdx.x * blockDim.x + threadIdx.x;
    long long tot = (long long)(K >> 1) * N;
    if (i >= tot) return;
    int n = (int)(i % N);
    long long kk = i / N;
    float a = W[(size_t)(2 * kk) * N + n];
    float b = W[(size_t)(2 * kk + 1) * N + n];
    out[i] = pack_h2(a, b);
}

__device__ __forceinline__ float warp_sum(float v)
{
#pragma unroll
    for (int o = 16; o > 0; o >>= 1) v += __shfl_xor_sync(0xffffffffu, v, o);
    return v;
}

// LayerNorm fp32 in -> fp16 out
__global__ void ln_h(const float* __restrict__ in, __half* __restrict__ out,
                     const float* __restrict__ s, const float* __restrict__ b)
{
    __shared__ float sh[9];
    __shared__ float stat[2];
    int n = blockIdx.x;
    const float* xr = in + (size_t)n * DMODEL;
    int t = threadIdx.x, wid = t >> 5, lane = t & 31;

    float vals[4];
    float lsum = 0.f;
#pragma unroll
    for (int i = 0; i < 4; i++) { vals[i] = xr[t + i * 288]; lsum += vals[i]; }
    float ws = warp_sum(lsum);
    if (lane == 0) sh[wid] = ws;
    __syncthreads();
    if (t == 0) {
        float tot = 0.f;
#pragma unroll
        for (int i = 0; i < 9; i++) tot += sh[i];
        stat[0] = tot * (1.0f / DMODEL);
    }
    __syncthreads();
    float mu = stat[0];
    float lvar = 0.f;
#pragma unroll
    for (int i = 0; i < 4; i++) { float d = vals[i] - mu; lvar += d * d; }
    ws = warp_sum(lvar);
    __syncthreads();
    if (lane == 0) sh[wid] = ws;
    __syncthreads();
    if (t == 0) {
        float tot = 0.f;
#pragma unroll
        for (int i = 0; i < 9; i++) tot += sh[i];
        stat[1] = rsqrtf(tot * (1.0f / DMODEL) + 1e-6f);
    }
    __syncthreads();
    float r = stat[1];
    __half* orow = out + (size_t)n * DMODEL;
#pragma unroll
    for (int i = 0; i < 4; i++) {
        int d = t + i * 288;
        orow[d] = __float2half_rn((vals[i] - mu) * r * s[d] + b[d]);
    }
}

// RoPE in-place on fp16 qkv
__global__ void rope_h()
{
    int n = blockIdx.x;
    int t = threadIdx.x;
    int h = t / 36, d = t % 36;
    float c = g_cos[n * 36 + d];
    float s = g_sin[n * 36 + d];
    __half* q = g_qkvh + (size_t)n * QKVW + h * HDIM;
    __half* k = q + DMODEL;
    float q0 = __half2float(q[d]), q1 = __half2float(q[d + 36]);
    q[d]      = __float2half_rn(q0 * c - q1 * s);
    q[d + 36] = __float2half_rn(q1 * c + q0 * s);
    float k0 = __half2float(k[d]), k1 = __half2float(k[d + 36]);
    k[d]      = __float2half_rn(k0 * c - k1 * s);
    k[d + 36] = __float2half_rn(k1 * c + k0 * s);
}

// ---------------------------------------------------------------------------
// mma helper
// ---------------------------------------------------------------------------
__device__ __forceinline__ void mma_f16(float c[4],
                                        uint32_t a0, uint32_t a1, uint32_t a2, uint32_t a3,
                                        uint32_t b0, uint32_t b1)
{
    asm volatile(
        "mma.sync.aligned.m16n8k16.row.col.f32.f16.f16.f32 "
        "{%0,%1,%2,%3}, {%4,%5,%6,%7}, {%8,%9}, {%0,%1,%2,%3};\n"
        : "+f"(c[0]), "+f"(c[1]), "+f"(c[2]), "+f"(c[3])
        : "r"(a0), "r"(a1), "r"(a2), "r"(a3), "r"(b0), "r"(b1));
}

__device__ __forceinline__ float gelu_tanh(float x)
{
    float x3 = x * x * x;
    return 0.5f * x * (1.f + tanhf(0.7978845608028654f * (x + 0.044715f * x3)));
}

// ---------------------------------------------------------------------------
// GEMM v4: A fp16 [M,K] row-major; Bw packed words [K/2][N]; C fp32/fp16.
//   Block 256x128, BK=16, 4 stages cp.async.  8 warps 4(M) x 2(N) = 64x64.
//   A via ldmatrix (row stride 12 words); B frags via LDS.32
//   (row stride 136 words -> banks (8q+g) all distinct).
//   Stage layout (words): A [0,3072), B [3072,4160).  4 stages = 66560 B.
// ---------------------------------------------------------------------------
#define EPI_BIAS      1
#define EPI_BIAS_GELU 2
#define EPI_BIAS_RES  3

#define G4_STG   4160
#define G4_BOFF  3072
#define G4_SMEM  (4 * G4_STG * 4)

template<int EPI, bool OUTH>
__global__ void __launch_bounds__(256)
gemm4(const __half* __restrict__ A, int lda,
      const uint32_t* __restrict__ Bw, int Nw,
      void* __restrict__ Cv, int ldc,
      const float* __restrict__ bias,
      const float* __restrict__ Res, int ldr,
      int Md, int Nd, int Kd)
{
    extern __shared__ uint32_t smbuf[];

    const int tid  = threadIdx.x;
    const int brow = blockIdx.y * 256;
    const int bcol = blockIdx.x * 128;
    const int w    = tid >> 5;
    const int lane = tid & 31;
    const int g    = lane >> 2;
    const int q    = lane & 3;
    const int wm   = w & 3;                  // 4 warps M
    const int wn   = w >> 2;                 // 2 warps N

    float acc[4][8][4];
#pragma unroll
    for (int i = 0; i < 4; i++)
#pragma unroll
        for (int j = 0; j < 8; j++)
#pragma unroll
            for (int r = 0; r < 4; r++) acc[i][j][r] = 0.f;

    uint32_t smbase = (uint32_t)__cvta_generic_to_shared(smbuf);

    // A cp.async: 2 chunks/thread/stage
    int arow[2], ak8[2], aval[2];
    const __half* ga[2];
    uint32_t sa[2];
#pragma unroll
    for (int i = 0; i < 2; i++) {
        int c = tid + i * 256;
        arow[i] = c >> 1;
        ak8[i]  = (c & 1) * 8;
        long long gr = brow + arow[i];
        aval[i] = (gr < Md) ? 16 : 0;
        ga[i] = A + gr * lda + ak8[i];
        sa[i] = smbase + (uint32_t)(arow[i] * 12 + (ak8[i] >> 1)) * 4;
    }
    // B cp.async: 1 chunk/thread/stage
    const int bkk = tid >> 5;                // 0..7
    const int bn4 = (tid & 31) * 4;          // 0..124
    const int bval = (bcol + bn4 < Nd) ? 16 : 0;
    const uint32_t* gb = Bw + (long long)bkk * Nw + bcol + bn4;
    const uint32_t sb = smbase + (uint32_t)(G4_BOFF + bkk * 136 + bn4) * 4;

    const int nt = Kd >> 4;

    // prologue: stages 0..2
#pragma unroll
    for (int s = 0; s < 3; s++) {
        uint32_t off = (uint32_t)(s * G4_STG) * 4;
        int k0 = s * 16;
#pragma unroll
        for (int i = 0; i < 2; i++)
            asm volatile("cp.async.cg.shared.global [%0], [%1], 16, %2;"
                         :: "r"(sa[i] + off), "l"(ga[i] + k0), "r"(aval[i]));
        asm volatile("cp.async.cg.shared.global [%0], [%1], 16, %2;"
                     :: "r"(sb + off), "l"(gb + (long long)s * 8 * Nw), "r"(bval));
        asm volatile("cp.async.commit_group;");
    }

    // ldmatrix A lane addressing
    const int a_row = wm * 64 + (lane & 15);
    const int a_kw  = (lane >> 4) * 4;
    const uint32_t abase = smbase + (uint32_t)(a_row * 12 + a_kw) * 4;
    // B fragment word indices
    const int bw0 = G4_BOFF + q * 136 + wn * 64 + g;
    const int bw1 = bw0 + 4 * 136;

    for (int kt = 0; kt < nt; kt++) {
        asm volatile("cp.async.wait_group 2;");
        __syncthreads();
        const uint32_t soff = (uint32_t)((kt & 3) * G4_STG) * 4;
        const uint32_t* stg = smbuf + (kt & 3) * G4_STG;

        uint32_t af[4][4], bfr[8][2];
#pragma unroll
        for (int mt = 0; mt < 4; mt++)
            asm volatile("ldmatrix.sync.aligned.m8n8.x4.shared.b16 {%0,%1,%2,%3}, [%4];"
                         : "=r"(af[mt][0]), "=r"(af[mt][1]), "=r"(af[mt][2]), "=r"(af[mt][3])
                         : "r"(abase + soff + (uint32_t)(mt * 16 * 12) * 4));
#pragma unroll
        for (int ntl = 0; ntl < 8; ntl++) {
            bfr[ntl][0] = stg[bw0 + ntl * 8];
            bfr[ntl][1] = stg[bw1 + ntl * 8];
        }

#pragma unroll
        for (int mt = 0; mt < 4; mt++)
#pragma unroll
            for (int j = 0; j < 8; j++)
                mma_f16(acc[mt][j],
                        af[mt][0], af[mt][1], af[mt][2], af[mt][3],
                        bfr[j][0], bfr[j][1]);

        int ktn = kt + 3;
        if (ktn < nt) {
            uint32_t doff = (uint32_t)((ktn & 3) * G4_STG) * 4;
            int k0 = ktn * 16;
#pragma unroll
            for (int i = 0; i < 2; i++)
                asm volatile("cp.async.cg.shared.global [%0], [%1], 16, %2;"
                             :: "r"(sa[i] + doff), "l"(ga[i] + k0), "r"(aval[i]));
            asm volatile("cp.async.cg.shared.global [%0], [%1], 16, %2;"
                         :: "r"(sb + doff), "l"(gb + (long long)ktn * 8 * Nw), "r"(bval));
        }
        asm volatile("cp.async.commit_group;");
    }

    // epilogue
    float*  Cf = (float*)Cv;
    __half* Ch = (__half*)Cv;
#pragma unroll
    for (int mt = 0; mt < 4; mt++) {
#pragma unroll
        for (int hh = 0; hh < 2; hh++) {
            int r = brow + wm * 64 + mt * 16 + g + 8 * hh;
            if (r >= Md) continue;
#pragma unroll
            for (int j = 0; j < 8; j++) {
                int c = bcol + wn * 64 + j * 8 + 2 * q;
                if (c >= Nd) continue;
                float v0 = acc[mt][j][hh * 2];
                float v1 = acc[mt][j][hh * 2 + 1];
                v0 += bias[c]; v1 += bias[c + 1];
                if (EPI == EPI_BIAS_GELU) { v0 = gelu_tanh(v0); v1 = gelu_tanh(v1); }
                if (EPI == EPI_BIAS_RES)  {
                    v0 += Res[(long long)r * ldr + c];
                    v1 += Res[(long long)r * ldr + c + 1];
                }
                if (OUTH) {
                    __half2 hv = __floats2half2_rn(v0, v1);
                    *reinterpret_cast<__half2*>(Ch + (long long)r * ldc + c) = hv;
                } else {
                    *reinterpret_cast<float2*>(Cf + (long long)r * ldc + c) = make_float2(v0, v1);
                }
            }
        }
    }
}

// ---------------------------------------------------------------------------
// Fused flash attention, fp16 in/out (unchanged from R6).
// ---------------------------------------------------------------------------
#define QS_OFF   0
#define QS_ST    44
#define KS_OFF   (QS_OFF + 128 * QS_ST)
#define KS_ST    72
#define VS_OFF   (KS_OFF + 40 * KS_ST)
#define VS_ST    104
#define PS_OFF   (VS_OFF + 32 * VS_ST)
#define PS_ST    36
#define MS_OFF   (PS_OFF + 128 * PS_ST)
#define LS_OFF   (MS_OFF + 128)
#define AL_OFF   (LS_OFF + 128)
#define RED_OFF  (AL_OFF + 128)
#define FA_WORDS (RED_OFF + 512)
#define FA_BYTES (FA_WORDS * 4)

__global__ void __launch_bounds__(256, 1)
flash_h(const __half* __restrict__ qkv, __half* __restrict__ attn)
{
    extern __shared__ uint32_t smem[];
    uint32_t* Qs = smem + QS_OFF;
    uint32_t* Ks = smem + KS_OFF;
    uint32_t* Vs = smem + VS_OFF;
    uint32_t* Ps = smem + PS_OFF;
    float* m_s  = (float*)(smem + MS_OFF);
    float* l_s  = (float*)(smem + LS_OFF);
    float* al_s = (float*)(smem + AL_OFF);
    float* red  = (float*)(smem + RED_OFF);

    int t = blockIdx.x;
    int head = blockIdx.y;
    int st, S, q0;
    if (t < 18)      { st = 0;    S = 2304; q0 = t * 128; }
    else if (t < 34) { st = 2304; S = 2048; q0 = (t - 18) * 128; }
    else if (t < 42) { st = 4352; S = 960;  q0 = (t - 34) * 128; }
    else             { st = 5312; S = 960;  q0 = (t - 42) * 128; }

    const int tid = threadIdx.x;
    const int w = tid >> 5, lane = tid & 31;
    const int g = lane >> 2, q = lane & 3;
    const int wm  = w & 1, wn  = w >> 1;
    const int wm2 = w & 3, wn2 = w >> 2;

    const float scale = 0.11785113019775793f;

    for (int s = tid; s < 128 * 9; s += 256) {
        int row = s / 9, w8 = s % 9;
        uint4 v = make_uint4(0, 0, 0, 0);
        if (q0 + row < S)
            v = *reinterpret_cast<const uint4*>(
                qkv + (size_t)(st + q0 + row) * QKVW + head * HDIM + w8 * 8);
        *reinterpret_cast<uint4*>(&Qs[row * QS_ST + w8 * 4]) = v;
    }
    for (int s = tid; s < 512; s += 256) {
        int row = s >> 2, kk = 36 + (s & 3);
        Qs[row * QS_ST + kk] = 0;
    }
    if (tid < 256) Ks[(36 + (tid >> 6)) * KS_ST + (tid & 63)] = 0;
    if (tid < 256) Vs[(tid >> 3) * VS_ST + 72 + (tid & 7)] = 0;
    if (tid < 128) { m_s[tid] = -1e30f; l_s[tid] = 0.f; }

    float O[2][5][4];
#pragma unroll
    for (int i = 0; i < 2; i++)
#pragma unroll
        for (int j = 0; j < 5; j++)
#pragma unroll
            for (int r = 0; r < 4; r++) O[i][j][r] = 0.f;

    const int nkv = S >> 6;
    for (int j = 0; j < nkv; j++) {
        __syncthreads();
        const int kv0 = j * 64;
        for (int s = tid; s < 64 * 9; s += 256) {
            int kv = s / 9, w8 = s % 9;
            uint4 v = *reinterpret_cast<const uint4*>(
                qkv + (size_t)(st + kv0 + kv) * QKVW + DMODEL + head * HDIM + w8 * 8);
            Ks[(w8 * 4 + 0) * KS_ST + kv] = v.x;
            Ks[(w8 * 4 + 1) * KS_ST + kv] = v.y;
            Ks[(w8 * 4 + 2) * KS_ST + kv] = v.z;
            Ks[(w8 * 4 + 3) * KS_ST + kv] = v.w;
        }
        for (int s = tid; s < 64 * 9; s += 256) {
            int kv = s / 9, w8 = s % 9;
            uint4 v = *reinterpret_cast<const uint4*>(
                qkv + (size_t)(st + kv0 + kv) * QKVW + 2 * DMODEL + head * HDIM + w8 * 8);
            uint16_t hx[8];
            *reinterpret_cast<uint4*>(hx) = v;
            uint16_t* Vh = reinterpret_cast<uint16_t*>(Vs);
            int base = ((kv >> 1) * VS_ST + w8 * 8) * 2 + (kv & 1);
#pragma unroll
            for (int i = 0; i < 8; i++) Vh[base + 2 * i] = hx[i];
        }
        __syncthreads();

        float acc_s[4][2][4];
#pragma unroll
        for (int a = 0; a < 4; a++)
#pragma unroll
            for (int b = 0; b < 2; b++)
#pragma unroll
                for (int r = 0; r < 4; r++) acc_s[a][b][r] = 0.f;

#pragma unroll
        for (int i = 0; i < 5; i++) {
            int kb = i * 8;
            uint32_t af[4][4], bf[2][2];
#pragma unroll
            for (int mt = 0; mt < 4; mt++) {
                int mb = wm * 64 + mt * 16;
                af[mt][0] = Qs[(mb + g    ) * QS_ST + kb + q    ];
                af[mt][1] = Qs[(mb + g + 8) * QS_ST + kb + q    ];
                af[mt][2] = Qs[(mb + g    ) * QS_ST + kb + q + 4];
                af[mt][3] = Qs[(mb + g + 8) * QS_ST + kb + q + 4];
            }
#pragma unroll
            for (int nt = 0; nt < 2; nt++) {
                int nb = wn * 16 + nt * 8;
                bf[nt][0] = Ks[(kb + q    ) * KS_ST + nb + g];
                bf[nt][1] = Ks[(kb + q + 4) * KS_ST + nb + g];
            }
#pragma unroll
            for (int mt = 0; mt < 4; mt++)
#pragma unroll
                for (int nt = 0; nt < 2; nt++)
                    mma_f16(acc_s[mt][nt],
                            af[mt][0], af[mt][1], af[mt][2], af[mt][3],
                            bf[nt][0], bf[nt][1]);
        }
#pragma unroll
        for (int a = 0; a < 4; a++)
#pragma unroll
            for (int b = 0; b < 2; b++)
#pragma unroll
                for (int r = 0; r < 4; r++) acc_s[a][b][r] *= scale;

#pragma unroll
        for (int mt = 0; mt < 4; mt++) {
#pragma unroll
            for (int h = 0; h < 2; h++) {
                float rmx = fmaxf(fmaxf(acc_s[mt][0][2 * h], acc_s[mt][0][2 * h + 1]),
                                  fmaxf(acc_s[mt][1][2 * h], acc_s[mt][1][2 * h + 1]));
                rmx = fmaxf(rmx, __shfl_xor_sync(0xffffffffu, rmx, 1));
                rmx = fmaxf(rmx, __shfl_xor_sync(0xffffffffu, rmx, 2));
                if (q == 0)
                    red[wn * 128 + wm * 64 + mt * 16 + g + 8 * h] = rmx;
            }
        }
        __syncthreads();
        if (tid < 128) {
            float tm = fmaxf(fmaxf(red[tid], red[128 + tid]),
                             fmaxf(red[256 + tid], red[384 + tid]));
            float mo = m_s[tid];
            float mn = fmaxf(mo, tm);
            al_s[tid] = __expf(mo - mn);
            m_s[tid]  = mn;
        }
        __syncthreads();

#pragma unroll
        for (int mt = 0; mt < 4; mt++) {
#pragma unroll
            for (int h = 0; h < 2; h++) {
                int row = wm * 64 + mt * 16 + g + 8 * h;
                float mn = m_s[row];
                float rs = 0.f;
#pragma unroll
                for (int nt = 0; nt < 2; nt++) {
                    int nb = wn * 16 + nt * 8;
                    float p0 = __expf(acc_s[mt][nt][2 * h    ] - mn);
                    float p1 = __expf(acc_s[mt][nt][2 * h + 1] - mn);
                    rs += p0 + p1;
                    Ps[row * PS_ST + (nb >> 1) + q] = pack_h2(p0, p1);
                }
                rs += __shfl_xor_sync(0xffffffffu, rs, 1);
                rs += __shfl_xor_sync(0xffffffffu, rs, 2);
                if (q == 0) red[wn * 128 + row] = rs;
            }
        }
#pragma unroll
        for (int mt = 0; mt < 2; mt++) {
#pragma unroll
            for (int h = 0; h < 2; h++) {
                int row = wm2 * 32 + mt * 16 + g + 8 * h;
                float a = al_s[row];
#pragma unroll
                for (int nt = 0; nt < 5; nt++) {
                    O[mt][nt][2 * h + 0] *= a;
                    O[mt][nt][2 * h + 1] *= a;
                }
            }
        }
        __syncthreads();
        if (tid < 128)
            l_s[tid] = l_s[tid] * al_s[tid] +
                       red[tid] + red[128 + tid] + red[256 + tid] + red[384 + tid];

#pragma unroll
        for (int i = 0; i < 4; i++) {
            int kb = i * 8;
            uint32_t af[2][4], bf[5][2];
#pragma unroll
            for (int mt = 0; mt < 2; mt++) {
                int mb = wm2 * 32 + mt * 16;
                af[mt][0] = Ps[(mb + g    ) * PS_ST + kb + q    ];
                af[mt][1] = Ps[(mb + g + 8) * PS_ST + kb + q    ];
                af[mt][2] = Ps[(mb + g    ) * PS_ST + kb + q + 4];
                af[mt][3] = Ps[(mb + g + 8) * PS_ST + kb + q + 4];
            }
#pragma unroll
            for (int nt = 0; nt < 5; nt++) {
                int nb = wn2 * 40 + nt * 8;
                bf[nt][0] = Vs[(kb + q    ) * VS_ST + nb + g];
                bf[nt][1] = Vs[(kb + q + 4) * VS_ST + nb + g];
            }
#pragma unroll
            for (int mt = 0; mt < 2; mt++)
#pragma unroll
                for (int nt = 0; nt < 5; nt++)
                    mma_f16(O[mt][nt],
                            af[mt][0], af[mt][1], af[mt][2], af[mt][3],
                            bf[nt][0], bf[nt][1]);
        }
    }
    __syncthreads();

#pragma unroll
    for (int mt = 0; mt < 2; mt++) {
#pragma unroll
        for (int h = 0; h < 2; h++) {
            int r = wm2 * 32 + mt * 16 + g + 8 * h;
            if (q0 + r >= S) continue;
            float inv = 1.0f / l_s[r];
#pragma unroll
            for (int nt = 0; nt < 5; nt++) {
                int c = wn2 * 40 + nt * 8 + 2 * q;
                if (c >= HDIM) continue;
                __half2 hv = __floats2half2_rn(O[mt][nt][2 * h] * inv,
                                               O[mt][nt][2 * h + 1] * inv);
                *reinterpret_cast<__half2*>(
                    attn + (size_t)(st + q0 + r) * DMODEL + head * HDIM + c) = hv;
            }
        }
    }
}

// ---------------------------------------------------------------------------
// Host launcher
// ---------------------------------------------------------------------------
#define SYMF(p, s) do { void* _t; cudaGetSymbolAddress(&_t, s); p = (float*)_t; } while (0)
#define SYMH(p, s) do { void* _t; cudaGetSymbolAddress(&_t, s); p = (__half*)_t; } while (0)
#define SYMW(p, s) do { void* _t; cudaGetSymbolAddress(&_t, s); p = (uint32_t*)_t; } while (0)

static inline dim3 ggrid4(int Md, int Nd) {
    return dim3((Nd + 127) / 128, (Md + 255) / 256);
}
static inline int pgrid(long long K, long long N) {
    return (int)(((K / 2) * N + 255) / 256);
}

extern "C" void kernel_launch(void* const* d_in, const int* in_sizes, int n_in,
                              void* d_out, int out_size)
{
    (void)in_sizes; (void)n_in; (void)out_size;
    const float* pixel    = (const float*)d_in[0];
    const float* patch_w  = (const float*)d_in[2];
    const float* patch_b  = (const float*)d_in[3];
    const float* pos_tab  = (const float*)d_in[4];
    const float* ln1_s    = (const float*)d_in[5];
    const float* ln1_b    = (const float*)d_in[6];
    const float* qkv_w    = (const float*)d_in[7];
    const float* qkv_b    = (const float*)d_in[8];
    const float* proj_w   = (const float*)d_in[9];
    const float* proj_b   = (const float*)d_in[10];
    const float* ln2_s    = (const float*)d_in[11];
    const float* ln2_b    = (const float*)d_in[12];
    const float* fc1_w    = (const float*)d_in[13];
    const float* fc1_b    = (const float*)d_in[14];
    const float* fc2_w    = (const float*)d_in[15];
    const float* fc2_b    = (const float*)d_in[16];
    const float* m_ln_s   = (const float*)d_in[17];
    const float* m_ln_b   = (const float*)d_in[18];
    const float* m_fc1_w  = (const float*)d_in[19];
    const float* m_fc1_b  = (const float*)d_in[20];
    const float* m_fc2_w  = (const float*)d_in[21];
    const float* m_fc2_b  = (const float*)d_in[22];
    float* out = (float*)d_out;

    float *x;
    __half *pix, *hh, *qkvh, *attnh, *mlph;
    uint32_t *wt;
    SYMF(x, g_x);
    SYMH(pix, g_pix); SYMH(hh, g_hh); SYMH(qkvh, g_qkvh);
    SYMH(attnh, g_attnh); SYMH(mlph, g_mlph);
    SYMW(wt, g_wt);

    static bool attr_set = false;
    if (!attr_set) {
        cudaFuncSetAttribute(flash_h,
                             cudaFuncAttributeMaxDynamicSharedMemorySize, FA_BYTES);
        cudaFuncSetAttribute(gemm4<EPI_BIAS, false>,
                             cudaFuncAttributeMaxDynamicSharedMemorySize, G4_SMEM);
        cudaFuncSetAttribute(gemm4<EPI_BIAS, true>,
                             cudaFuncAttributeMaxDynamicSharedMemorySize, G4_SMEM);
        cudaFuncSetAttribute(gemm4<EPI_BIAS_GELU, true>,
                             cudaFuncAttributeMaxDynamicSharedMemorySize, G4_SMEM);
        cudaFuncSetAttribute(gemm4<EPI_BIAS_RES, false>,
                             cudaFuncAttributeMaxDynamicSharedMemorySize, G4_SMEM);
        attr_set = true;
    }

    // ---- weight packing (streaming convert, no transpose)
    conv_h<<<(NTOK * CIN + 255) / 256, 256>>>(pixel, pix, NTOK * CIN);
    wpack<<<pgrid(CIN, DMODEL), 256>>>(patch_w, wt + WO_PATCH, CIN, DMODEL);
    for (int l = 0; l < 2; l++) {
        wpack<<<pgrid(DMODEL, QKVW), 256>>>(
            qkv_w + (size_t)l * DMODEL * QKVW, wt + WO_QKV + l * WS_QKV, DMODEL, QKVW);
        wpack<<<pgrid(DMODEL, DMODEL), 256>>>(
            proj_w + (size_t)l * DMODEL * DMODEL, wt + WO_PROJ + l * WS_PROJ, DMODEL, DMODEL);
        wpack<<<pgrid(DMODEL, IDIM), 256>>>(
            fc1_w + (size_t)l * DMODEL * IDIM, wt + WO_FC1 + l * WS_FC1, DMODEL, IDIM);
        wpack<<<pgrid(IDIM, DMODEL), 256>>>(
            fc2_w + (size_t)l * IDIM * DMODEL, wt + WO_FC2 + l * WS_FC2, IDIM, DMODEL);
    }
    wpack<<<pgrid(MD4, MD4), 256>>>(m_fc1_w, wt + WO_MFC1, MD4, MD4);
    wpack<<<pgrid(MD4, DOUT), 256>>>(m_fc2_w, wt + WO_MFC2, MD4, DOUT);

    cossin_kernel<<<(NTOK * 36 + 255) / 256, 256>>>();

    // Patch embed -> x (fp32)
    gemm4<EPI_BIAS, false><<<ggrid4(NTOK, DMODEL), 256, G4_SMEM>>>(
        pix, CIN, wt + WO_PATCH, DMODEL, x, DMODEL,
        patch_b, nullptr, 0, NTOK, DMODEL, CIN);

    posadd_kernel<<<NTOK, 288>>>(pos_tab);

    for (int l = 0; l < 2; l++) {
        ln_h<<<NTOK, 288>>>(x, hh, ln1_s + l * DMODEL, ln1_b + l * DMODEL);

        gemm4<EPI_BIAS, true><<<ggrid4(NTOK, QKVW), 256, G4_SMEM>>>(
            hh, DMODEL, wt + WO_QKV + l * WS_QKV, QKVW, qkvh, QKVW,
            qkv_b + (size_t)l * QKVW, nullptr, 0, NTOK, QKVW, DMODEL);

        rope_h<<<NTOK, 576>>>();

        flash_h<<<dim3(50, HEADS), 256, FA_BYTES>>>(qkvh, attnh);

        gemm4<EPI_BIAS_RES, false><<<ggrid4(NTOK, DMODEL), 256, G4_SMEM>>>(
            attnh, DMODEL, wt + WO_PROJ + l * WS_PROJ, DMODEL, x, DMODEL,
            proj_b + (size_t)l * DMODEL, x, DMODEL, NTOK, DMODEL, DMODEL);

        ln_h<<<NTOK, 288>>>(x, hh, ln2_s + l * DMODEL, ln2_b + l * DMODEL);

        gemm4<EPI_BIAS_GELU, true><<<ggrid4(NTOK, IDIM), 256, G4_SMEM>>>(
            hh, DMODEL, wt + WO_FC1 + l * WS_FC1, IDIM, mlph, IDIM,
            fc1_b + (size_t)l * IDIM, nullptr, 0, NTOK, IDIM, DMODEL);

        gemm4<EPI_BIAS_RES, false><<<ggrid4(NTOK, DMODEL), 256, G4_SMEM>>>(
            mlph, IDIM, wt + WO_FC2 + l * WS_FC2, DMODEL, x, DMODEL,
            fc2_b + (size_t)l * DMODEL, x, DMODEL, NTOK, DMODEL, IDIM);
    }

    // merger
    ln_h<<<NTOK, 288>>>(x, hh, m_ln_s, m_ln_b);   // hh viewed as [1568][4608]

    gemm4<EPI_BIAS_GELU, true><<<ggrid4(MROWS, MD4), 256, G4_SMEM>>>(
        hh, MD4, wt + WO_MFC1, MD4, mlph, MD4,
        m_fc1_b, nullptr, 0, MROWS, MD4, MD4);

    gemm4<EPI_BIAS, false><<<ggrid4(MROWS, DOUT), 256, G4_SMEM>>>(
        mlph, MD4, wt + WO_MFC2, DOUT, out, DOUT,
        m_fc2_b, nullptr, 0, MROWS, DOUT, MD4);
}

// round 8
// speedup vs baseline: 1.2266x; 1.2266x over previous
#include <cuda_runtime.h>
#include <cuda_fp16.h>
#include <math.h>
#include <stdint.h>

// ---------------------------------------------------------------------------
// Problem constants (GRID fixed: [[1,48,48],[1,32,64],[2,24,40]])
// ---------------------------------------------------------------------------
#define NTOK    6272
#define DMODEL  1152
#define HEADS   16
#define HDIM    72
#define IDIM    4304
#define DOUT    2048
#define MROWS   1568
#define MD4     4608
#define QKVW    3456
#define CIN     1536

// ---------------------------------------------------------------------------
// Scratch buffers
// ---------------------------------------------------------------------------
__device__ float  g_x    [NTOK * DMODEL];        // residual (fp32)
__device__ __half g_pix  [NTOK * CIN];           // pixel fp16
__device__ __half g_hh   [NTOK * DMODEL];        // LN out fp16
__device__ __half g_qkvh [NTOK * QKVW];          // qkv fp16
__device__ __half g_attnh[NTOK * DMODEL];        // attn out fp16
__device__ __half g_mlph [NTOK * IDIM];          // mlp hidden fp16
__device__ float  g_cos  [NTOK * 36];
__device__ float  g_sin  [NTOK * 36];

// transposed fp16 weights, packed
#define SZ_PATCH (1152ULL * 1536)
#define SZ_QKV   (3456ULL * 1152)
#define SZ_PROJ  (1152ULL * 1152)
#define SZ_FC1   (4304ULL * 1152)
#define SZ_FC2   (1152ULL * 4304)
#define SZ_MFC1  (4608ULL * 4608)
#define SZ_MFC2  (2048ULL * 4608)
#define OFF_PATCH 0ULL
#define OFF_QKV   (OFF_PATCH + SZ_PATCH)
#define OFF_PROJ  (OFF_QKV + 2 * SZ_QKV)
#define OFF_FC1   (OFF_PROJ + 2 * SZ_PROJ)
#define OFF_FC2   (OFF_FC1 + 2 * SZ_FC1)
#define OFF_MFC1  (OFF_FC2 + 2 * SZ_FC2)
#define OFF_MFC2  (OFF_MFC1 + SZ_MFC1)
#define WT_TOTAL  (OFF_MFC2 + SZ_MFC2)
__device__ __half g_wt[WT_TOTAL];

// ---------------------------------------------------------------------------
__device__ __forceinline__ void token_pos(int n, int& row, int& col, int& ih, int& iw)
{
    int local, h, w;
    if (n < 2304)      { local = n;          h = 48; w = 48; }
    else if (n < 4352) { local = n - 2304;   h = 32; w = 64; }
    else               { local = n - 4352;   h = 24; w = 40; }
    int rem = local % (h * w);
    int wb_cnt = w >> 1;
    int blk = rem >> 2, within = rem & 3;
    int hb = blk / wb_cnt, wb = blk % wb_cnt;
    row = hb * 2 + (within >> 1);
    col = wb * 2 + (within & 1);
    ih = h; iw = w;
}

__global__ void cossin_kernel()
{
    int idx = blockIdx.x * blockDim.x + threadIdx.x;
    if (idx >= NTOK * 36) return;
    int n = idx / 36, d = idx % 36;
    int row, col, ih, iw;
    token_pos(n, row, col, ih, iw);
    int j = (d < 18) ? d : d - 18;
    double p = (d < 18) ? (double)row : (double)col;
    double inv = 1.0 / pow(10000.0, (2.0 * (double)j) / 36.0);
    double ang = p * inv;
    g_cos[idx] = (float)cos(ang);
    g_sin[idx] = (float)sin(ang);
}

__global__ void posadd_kernel(const float* __restrict__ pos_table)
{
    int n = blockIdx.x;
    int row, col, ih, iw;
    token_pos(n, row, col, ih, iw);
    double hi = 47.0 * (double)row / (double)(ih - 1);
    double wi = 47.0 * (double)col / (double)(iw - 1);
    int hf = (int)floor(hi), wf = (int)floor(wi);
    float dh = (float)(hi - (double)hf), dw = (float)(wi - (double)wf);
    int hc = min(hf + 1, 47), wc = min(wf + 1, 47);
    float w00 = (1.f - dh) * (1.f - dw);
    float w01 = (1.f - dh) * dw;
    float w10 = dh * (1.f - dw);
    float w11 = dh * dw;
    const float* p00 = pos_table + (size_t)(hf * 48 + wf) * DMODEL;
    const float* p01 = pos_table + (size_t)(hf * 48 + wc) * DMODEL;
    const float* p10 = pos_table + (size_t)(hc * 48 + wf) * DMODEL;
    const float* p11 = pos_table + (size_t)(hc * 48 + wc) * DMODEL;
    float* xr = g_x + (size_t)n * DMODEL;
    for (int d = threadIdx.x; d < DMODEL; d += blockDim.x)
        xr[d] += p00[d] * w00 + p01[d] * w01 + p10[d] * w10 + p11[d] * w11;
}

// fp32 -> fp16 elementwise
__global__ void conv_h(const float* __restrict__ in, __half* __restrict__ out, int n)
{
    int i = blockIdx.x * blockDim.x + threadIdx.x;
    if (i < n) out[i] = __float2half_rn(in[i]);
}

// W [K,N] fp32 -> Wt [N,K] fp16 (tiled transpose)
__global__ void wt_t(const float* __restrict__ W, __half* __restrict__ Wt, int K, int N)
{
    __shared__ float tile[32][33];
    int nt = blockIdx.x * 32, kt = blockIdx.y * 32;
    int tx = threadIdx.x, ty = threadIdx.y;
#pragma unroll
    for (int j = 0; j < 4; j++) {
        int k = kt + ty + j * 8;
        if (k < K && nt + tx < N)
            tile[ty + j * 8][tx] = W[(size_t)k * N + nt + tx];
    }
    __syncthreads();
#pragma unroll
    for (int j = 0; j < 4; j++) {
        int n = nt + ty + j * 8;
        if (n < N && kt + tx < K)
            Wt[(size_t)n * K + kt + tx] = __float2half_rn(tile[tx][ty + j * 8]);
    }
}

__device__ __forceinline__ float warp_sum(float v)
{
#pragma unroll
    for (int o = 16; o > 0; o >>= 1) v += __shfl_xor_sync(0xffffffffu, v, o);
    return v;
}

// LayerNorm fp32 in -> fp16 out
__global__ void ln_h(const float* __restrict__ in, __half* __restrict__ out,
                     const float* __restrict__ s, const float* __restrict__ b)
{
    __shared__ float sh[9];
    __shared__ float stat[2];
    int n = blockIdx.x;
    const float* xr = in + (size_t)n * DMODEL;
    int t = threadIdx.x, wid = t >> 5, lane = t & 31;

    float vals[4];
    float lsum = 0.f;
#pragma unroll
    for (int i = 0; i < 4; i++) { vals[i] = xr[t + i * 288]; lsum += vals[i]; }
    float ws = warp_sum(lsum);
    if (lane == 0) sh[wid] = ws;
    __syncthreads();
    if (t == 0) {
        float tot = 0.f;
#pragma unroll
        for (int i = 0; i < 9; i++) tot += sh[i];
        stat[0] = tot * (1.0f / DMODEL);
    }
    __syncthreads();
    float mu = stat[0];
    float lvar = 0.f;
#pragma unroll
    for (int i = 0; i < 4; i++) { float d = vals[i] - mu; lvar += d * d; }
    ws = warp_sum(lvar);
    __syncthreads();
    if (lane == 0) sh[wid] = ws;
    __syncthreads();
    if (t == 0) {
        float tot = 0.f;
#pragma unroll
        for (int i = 0; i < 9; i++) tot += sh[i];
        stat[1] = rsqrtf(tot * (1.0f / DMODEL) + 1e-6f);
    }
    __syncthreads();
    float r = stat[1];
    __half* orow = out + (size_t)n * DMODEL;
#pragma unroll
    for (int i = 0; i < 4; i++) {
        int d = t + i * 288;
        orow[d] = __float2half_rn((vals[i] - mu) * r * s[d] + b[d]);
    }
}

// RoPE in-place on fp16 qkv
__global__ void rope_h()
{
    int n = blockIdx.x;
    int t = threadIdx.x;
    int h = t / 36, d = t % 36;
    float c = g_cos[n * 36 + d];
    float s = g_sin[n * 36 + d];
    __half* q = g_qkvh + (size_t)n * QKVW + h * HDIM;
    __half* k = q + DMODEL;
    float q0 = __half2float(q[d]), q1 = __half2float(q[d + 36]);
    q[d]      = __float2half_rn(q0 * c - q1 * s);
    q[d + 36] = __float2half_rn(q1 * c + q0 * s);
    float k0 = __half2float(k[d]), k1 = __half2float(k[d + 36]);
    k[d]      = __float2half_rn(k0 * c - k1 * s);
    k[d + 36] = __float2half_rn(k1 * c + k0 * s);
}

// ---------------------------------------------------------------------------
// mma / misc helpers
// ---------------------------------------------------------------------------
__device__ __forceinline__ void mma_f16(float c[4],
                                        uint32_t a0, uint32_t a1, uint32_t a2, uint32_t a3,
                                        uint32_t b0, uint32_t b1)
{
    asm volatile(
        "mma.sync.aligned.m16n8k16.row.col.f32.f16.f16.f32 "
        "{%0,%1,%2,%3}, {%4,%5,%6,%7}, {%8,%9}, {%0,%1,%2,%3};\n"
        : "+f"(c[0]), "+f"(c[1]), "+f"(c[2]), "+f"(c[3])
        : "r"(a0), "r"(a1), "r"(a2), "r"(a3), "r"(b0), "r"(b1));
}

// fast gelu: HW tanh approx (MUFU.TANH), abs err ~6e-4 on tanh
__device__ __forceinline__ float gelu_tanh(float x)
{
    float u = 0.7978845608028654f * (x + 0.044715f * x * x * x);
    float t;
    asm("tanh.approx.f32 %0, %1;" : "=f"(t) : "f"(u));
    return 0.5f * x * (1.f + t);
}

__device__ __forceinline__ uint32_t pack_h2(float lo, float hi)
{
    __half2 h = __floats2half2_rn(lo, hi);
    return *reinterpret_cast<uint32_t*>(&h);
}

// ---------------------------------------------------------------------------
// GEMM v3: A fp16 [M,K] row-major, Bt fp16 [N,K] row-major, C fp32 or fp16.
//   Block 128x128, BK=16, 4 stages, cp.async + ldmatrix.
//   8 warps 2(M) x 4(N): warp tile 64x32.
//   smem rows padded to 24 halfs (12 words): ldmatrix phases hit all 32 banks.
//   launch_bounds(256,2): cap regs at 128 so 2 CTAs/SM cover cp.async waits.
// ---------------------------------------------------------------------------
#define EPI_BIAS      1
#define EPI_BIAS_GELU 2
#define EPI_BIAS_RES  3

template<int EPI, bool OUTH>
__global__ void __launch_bounds__(256, 2)
gemm3(const __half* __restrict__ A, int lda,
      const __half* __restrict__ Bt, int ldb,
      void* __restrict__ Cv, int ldc,
      const float* __restrict__ bias,
      const float* __restrict__ Res, int ldr,
      int Md, int Nd, int Kd)
{
    __shared__ uint32_t smbuf[4 * 3072];     // 48 KB: 4 stages x (A 1536w + B 1536w)

    const int tid  = threadIdx.x;
    const int brow = blockIdx.y * 128;
    const int bcol = blockIdx.x * 128;
    const int w    = tid >> 5;
    const int lane = tid & 31;
    const int g    = lane >> 2;
    const int q    = lane & 3;
    const int wm   = w & 1;                  // 2 warps M
    const int wn   = w >> 1;                 // 4 warps N

    // cp.async coords: one A chunk + one B chunk (16B) per thread per stage
    const int crow = tid >> 1;
    const int ck8  = (tid & 1) * 8;
    const long long ar = brow + crow;
    const long long br = bcol + crow;
    const int aval = (ar < Md) ? 16 : 0;
    const int bval = (br < Nd) ? 16 : 0;
    uint32_t smbase = (uint32_t)__cvta_generic_to_shared(smbuf);
    const uint32_t sa = smbase + (uint32_t)(crow * 12 + (ck8 >> 1)) * 4;
    const uint32_t sb = smbase + (uint32_t)(1536 + crow * 12 + (ck8 >> 1)) * 4;
    const __half* ga = A  + ar * lda + ck8;
    const __half* gb = Bt + br * ldb + ck8;

    float acc[4][4][4];
#pragma unroll
    for (int i = 0; i < 4; i++)
#pragma unroll
        for (int j = 0; j < 4; j++)
#pragma unroll
            for (int r = 0; r < 4; r++) acc[i][j][r] = 0.f;

    const int nt = Kd >> 4;

    // prologue: stages 0..2
#pragma unroll
    for (int s = 0; s < 3; s++) {
        uint32_t off = (uint32_t)s * 3072 * 4;
        int k0 = s * 16;
        asm volatile("cp.async.cg.shared.global [%0], [%1], 16, %2;"
                     :: "r"(sa + off), "l"(ga + k0), "r"(aval));
        asm volatile("cp.async.cg.shared.global [%0], [%1], 16, %2;"
                     :: "r"(sb + off), "l"(gb + k0), "r"(bval));
        asm volatile("cp.async.commit_group;");
    }

    // ldmatrix lane addressing
    const int a_row = wm * 64 + (lane & 15);
    const int a_kw  = (lane >> 4) * 4;
    const int b_row = wn * 32 + (lane & 7) + ((lane >> 4) << 3);
    const int b_kw  = ((lane >> 3) & 1) * 4;
    const uint32_t abase = smbase + (uint32_t)(a_row * 12 + a_kw) * 4;
    const uint32_t bbase = smbase + (uint32_t)(1536 + b_row * 12 + b_kw) * 4;

    for (int kt = 0; kt < nt; kt++) {
        asm volatile("cp.async.wait_group 2;");
        __syncthreads();
        uint32_t soff = (uint32_t)(kt & 3) * 3072 * 4;

        uint32_t af[4][4], bf[2][4];
#pragma unroll
        for (int mt = 0; mt < 4; mt++)
            asm volatile("ldmatrix.sync.aligned.m8n8.x4.shared.b16 {%0,%1,%2,%3}, [%4];"
                         : "=r"(af[mt][0]), "=r"(af[mt][1]), "=r"(af[mt][2]), "=r"(af[mt][3])
                         : "r"(abase + soff + (uint32_t)(mt * 16 * 12) * 4));
#pragma unroll
        for (int ng = 0; ng < 2; ng++)
            asm volatile("ldmatrix.sync.aligned.m8n8.x4.shared.b16 {%0,%1,%2,%3}, [%4];"
                         : "=r"(bf[ng][0]), "=r"(bf[ng][1]), "=r"(bf[ng][2]), "=r"(bf[ng][3])
                         : "r"(bbase + soff + (uint32_t)(ng * 16 * 12) * 4));

#pragma unroll
        for (int mt = 0; mt < 4; mt++)
#pragma unroll
            for (int j = 0; j < 4; j++)
                mma_f16(acc[mt][j],
                        af[mt][0], af[mt][1], af[mt][2], af[mt][3],
                        bf[j >> 1][(j & 1) * 2], bf[j >> 1][(j & 1) * 2 + 1]);

        int ktn = kt + 3;
        if (ktn < nt) {
            uint32_t doff = (uint32_t)(ktn & 3) * 3072 * 4;
            int k0 = ktn * 16;
            asm volatile("cp.async.cg.shared.global [%0], [%1], 16, %2;"
                         :: "r"(sa + doff), "l"(ga + k0), "r"(aval));
            asm volatile("cp.async.cg.shared.global [%0], [%1], 16, %2;"
                         :: "r"(sb + doff), "l"(gb + k0), "r"(bval));
        }
        asm volatile("cp.async.commit_group;");
    }

    // epilogue (Nd is even; c always even -> pair stores safe)
    float*  Cf = (float*)Cv;
    __half* Ch = (__half*)Cv;
#pragma unroll
    for (int mt = 0; mt < 4; mt++) {
#pragma unroll
        for (int hh = 0; hh < 2; hh++) {
            int r = brow + wm * 64 + mt * 16 + g + 8 * hh;
            if (r >= Md) continue;
#pragma unroll
            for (int j = 0; j < 4; j++) {
                int c = bcol + wn * 32 + j * 8 + 2 * q;
                if (c >= Nd) continue;
                float v0 = acc[mt][j][hh * 2];
                float v1 = acc[mt][j][hh * 2 + 1];
                v0 += bias[c]; v1 += bias[c + 1];
                if (EPI == EPI_BIAS_GELU) { v0 = gelu_tanh(v0); v1 = gelu_tanh(v1); }
                if (EPI == EPI_BIAS_RES)  {
                    v0 += Res[(long long)r * ldr + c];
                    v1 += Res[(long long)r * ldr + c + 1];
                }
                if (OUTH) {
                    __half2 hv = __floats2half2_rn(v0, v1);
                    *reinterpret_cast<__half2*>(Ch + (long long)r * ldc + c) = hv;
                } else {
                    *reinterpret_cast<float2*>(Cf + (long long)r * ldc + c) = make_float2(v0, v1);
                }
            }
        }
    }
}

// ---------------------------------------------------------------------------
// Fused flash attention, fp16 in/out, m16n8k16, online softmax (fp32 stats).
// ---------------------------------------------------------------------------
#define QS_OFF   0
#define QS_ST    44
#define KS_OFF   (QS_OFF + 128 * QS_ST)
#define KS_ST    72
#define VS_OFF   (KS_OFF + 40 * KS_ST)
#define VS_ST    104
#define PS_OFF   (VS_OFF + 32 * VS_ST)
#define PS_ST    36
#define MS_OFF   (PS_OFF + 128 * PS_ST)
#define LS_OFF   (MS_OFF + 128)
#define AL_OFF   (LS_OFF + 128)
#define RED_OFF  (AL_OFF + 128)
#define FA_WORDS (RED_OFF + 512)
#define FA_BYTES (FA_WORDS * 4)

__global__ void __launch_bounds__(256, 1)
flash_h(const __half* __restrict__ qkv, __half* __restrict__ attn)
{
    extern __shared__ uint32_t smem[];
    uint32_t* Qs = smem + QS_OFF;
    uint32_t* Ks = smem + KS_OFF;
    uint32_t* Vs = smem + VS_OFF;
    uint32_t* Ps = smem + PS_OFF;
    float* m_s  = (float*)(smem + MS_OFF);
    float* l_s  = (float*)(smem + LS_OFF);
    float* al_s = (float*)(smem + AL_OFF);
    float* red  = (float*)(smem + RED_OFF);

    int t = blockIdx.x;
    int head = blockIdx.y;
    int st, S, q0;
    if (t < 18)      { st = 0;    S = 2304; q0 = t * 128; }
    else if (t < 34) { st = 2304; S = 2048; q0 = (t - 18) * 128; }
    else if (t < 42) { st = 4352; S = 960;  q0 = (t - 34) * 128; }
    else             { st = 5312; S = 960;  q0 = (t - 42) * 128; }

    const int tid = threadIdx.x;
    const int w = tid >> 5, lane = tid & 31;
    const int g = lane >> 2, q = lane & 3;
    const int wm  = w & 1, wn  = w >> 1;
    const int wm2 = w & 3, wn2 = w >> 2;

    const float scale = 0.11785113019775793f;

    for (int s = tid; s < 128 * 9; s += 256) {
        int row = s / 9, w8 = s % 9;
        uint4 v = make_uint4(0, 0, 0, 0);
        if (q0 + row < S)
            v = *reinterpret_cast<const uint4*>(
                qkv + (size_t)(st + q0 + row) * QKVW + head * HDIM + w8 * 8);
        *reinterpret_cast<uint4*>(&Qs[row * QS_ST + w8 * 4]) = v;
    }
    for (int s = tid; s < 512; s += 256) {
        int row = s >> 2, kk = 36 + (s & 3);
        Qs[row * QS_ST + kk] = 0;
    }
    if (tid < 256) Ks[(36 + (tid >> 6)) * KS_ST + (tid & 63)] = 0;
    if (tid < 256) Vs[(tid >> 3) * VS_ST + 72 + (tid & 7)] = 0;
    if (tid < 128) { m_s[tid] = -1e30f; l_s[tid] = 0.f; }

    float O[2][5][4];
#pragma unroll
    for (int i = 0; i < 2; i++)
#pragma unroll
        for (int j = 0; j < 5; j++)
#pragma unroll
            for (int r = 0; r < 4; r++) O[i][j][r] = 0.f;

    const int nkv = S >> 6;
    for (int j = 0; j < nkv; j++) {
        __syncthreads();
        const int kv0 = j * 64;
        for (int s = tid; s < 64 * 9; s += 256) {
            int kv = s / 9, w8 = s % 9;
            uint4 v = *reinterpret_cast<const uint4*>(
                qkv + (size_t)(st + kv0 + kv) * QKVW + DMODEL + head * HDIM + w8 * 8);
            Ks[(w8 * 4 + 0) * KS_ST + kv] = v.x;
            Ks[(w8 * 4 + 1) * KS_ST + kv] = v.y;
            Ks[(w8 * 4 + 2) * KS_ST + kv] = v.z;
            Ks[(w8 * 4 + 3) * KS_ST + kv] = v.w;
        }
        for (int s = tid; s < 64 * 9; s += 256) {
            int kv = s / 9, w8 = s % 9;
            uint4 v = *reinterpret_cast<const uint4*>(
                qkv + (size_t)(st + kv0 + kv) * QKVW + 2 * DMODEL + head * HDIM + w8 * 8);
            uint16_t hx[8];
            *reinterpret_cast<uint4*>(hx) = v;
            uint16_t* Vh = reinterpret_cast<uint16_t*>(Vs);
            int base = ((kv >> 1) * VS_ST + w8 * 8) * 2 + (kv & 1);
#pragma unroll
            for (int i = 0; i < 8; i++) Vh[base + 2 * i] = hx[i];
        }
        __syncthreads();

        float acc_s[4][2][4];
#pragma unroll
        for (int a = 0; a < 4; a++)
#pragma unroll
            for (int b = 0; b < 2; b++)
#pragma unroll
                for (int r = 0; r < 4; r++) acc_s[a][b][r] = 0.f;

#pragma unroll
        for (int i = 0; i < 5; i++) {
            int kb = i * 8;
            uint32_t af[4][4], bf[2][2];
#pragma unroll
            for (int mt = 0; mt < 4; mt++) {
                int mb = wm * 64 + mt * 16;
                af[mt][0] = Qs[(mb + g    ) * QS_ST + kb + q    ];
                af[mt][1] = Qs[(mb + g + 8) * QS_ST + kb + q    ];
                af[mt][2] = Qs[(mb + g    ) * QS_ST + kb + q + 4];
                af[mt][3] = Qs[(mb + g + 8) * QS_ST + kb + q + 4];
            }
#pragma unroll
            for (int nt = 0; nt < 2; nt++) {
                int nb = wn * 16 + nt * 8;
                bf[nt][0] = Ks[(kb + q    ) * KS_ST + nb + g];
                bf[nt][1] = Ks[(kb + q + 4) * KS_ST + nb + g];
            }
#pragma unroll
            for (int mt = 0; mt < 4; mt++)
#pragma unroll
                for (int nt = 0; nt < 2; nt++)
                    mma_f16(acc_s[mt][nt],
                            af[mt][0], af[mt][1], af[mt][2], af[mt][3],
                            bf[nt][0], bf[nt][1]);
        }
#pragma unroll
        for (int a = 0; a < 4; a++)
#pragma unroll
            for (int b = 0; b < 2; b++)
#pragma unroll
                for (int r = 0; r < 4; r++) acc_s[a][b][r] *= scale;

#pragma unroll
        for (int mt = 0; mt < 4; mt++) {
#pragma unroll
            for (int h = 0; h < 2; h++) {
                float rmx = fmaxf(fmaxf(acc_s[mt][0][2 * h], acc_s[mt][0][2 * h + 1]),
                                  fmaxf(acc_s[mt][1][2 * h], acc_s[mt][1][2 * h + 1]));
                rmx = fmaxf(rmx, __shfl_xor_sync(0xffffffffu, rmx, 1));
                rmx = fmaxf(rmx, __shfl_xor_sync(0xffffffffu, rmx, 2));
                if (q == 0)
                    red[wn * 128 + wm * 64 + mt * 16 + g + 8 * h] = rmx;
            }
        }
        __syncthreads();
        if (tid < 128) {
            float tm = fmaxf(fmaxf(red[tid], red[128 + tid]),
                             fmaxf(red[256 + tid], red[384 + tid]));
            float mo = m_s[tid];
            float mn = fmaxf(mo, tm);
            al_s[tid] = __expf(mo - mn);
            m_s[tid]  = mn;
        }
        __syncthreads();

#pragma unroll
        for (int mt = 0; mt < 4; mt++) {
#pragma unroll
            for (int h = 0; h < 2; h++) {
                int row = wm * 64 + mt * 16 + g + 8 * h;
                float mn = m_s[row];
                float rs = 0.f;
#pragma unroll
                for (int nt = 0; nt < 2; nt++) {
                    int nb = wn * 16 + nt * 8;
                    float p0 = __expf(acc_s[mt][nt][2 * h    ] - mn);
                    float p1 = __expf(acc_s[mt][nt][2 * h + 1] - mn);
                    rs += p0 + p1;
                    Ps[row * PS_ST + (nb >> 1) + q] = pack_h2(p0, p1);
                }
                rs += __shfl_xor_sync(0xffffffffu, rs, 1);
                rs += __shfl_xor_sync(0xffffffffu, rs, 2);
                if (q == 0) red[wn * 128 + row] = rs;
            }
        }
#pragma unroll
        for (int mt = 0; mt < 2; mt++) {
#pragma unroll
            for (int h = 0; h < 2; h++) {
                int row = wm2 * 32 + mt * 16 + g + 8 * h;
                float a = al_s[row];
#pragma unroll
                for (int nt = 0; nt < 5; nt++) {
                    O[mt][nt][2 * h + 0] *= a;
                    O[mt][nt][2 * h + 1] *= a;
                }
            }
        }
        __syncthreads();
        if (tid < 128)
            l_s[tid] = l_s[tid] * al_s[tid] +
                       red[tid] + red[128 + tid] + red[256 + tid] + red[384 + tid];

#pragma unroll
        for (int i = 0; i < 4; i++) {
            int kb = i * 8;
            uint32_t af[2][4], bf[5][2];
#pragma unroll
            for (int mt = 0; mt < 2; mt++) {
                int mb = wm2 * 32 + mt * 16;
                af[mt][0] = Ps[(mb + g    ) * PS_ST + kb + q    ];
                af[mt][1] = Ps[(mb + g + 8) * PS_ST + kb + q    ];
                af[mt][2] = Ps[(mb + g    ) * PS_ST + kb + q + 4];
                af[mt][3] = Ps[(mb + g + 8) * PS_ST + kb + q + 4];
            }
#pragma unroll
            for (int nt = 0; nt < 5; nt++) {
                int nb = wn2 * 40 + nt * 8;
                bf[nt][0] = Vs[(kb + q    ) * VS_ST + nb + g];
                bf[nt][1] = Vs[(kb + q + 4) * VS_ST + nb + g];
            }
#pragma unroll
            for (int mt = 0; mt < 2; mt++)
#pragma unroll
                for (int nt = 0; nt < 5; nt++)
                    mma_f16(O[mt][nt],
                            af[mt][0], af[mt][1], af[mt][2], af[mt][3],
                            bf[nt][0], bf[nt][1]);
        }
    }
    __syncthreads();

#pragma unroll
    for (int mt = 0; mt < 2; mt++) {
#pragma unroll
        for (int h = 0; h < 2; h++) {
            int r = wm2 * 32 + mt * 16 + g + 8 * h;
            if (q0 + r >= S) continue;
            float inv = 1.0f / l_s[r];
#pragma unroll
            for (int nt = 0; nt < 5; nt++) {
                int c = wn2 * 40 + nt * 8 + 2 * q;
                if (c >= HDIM) continue;
                __half2 hv = __floats2half2_rn(O[mt][nt][2 * h] * inv,
                                               O[mt][nt][2 * h + 1] * inv);
                *reinterpret_cast<__half2*>(
                    attn + (size_t)(st + q0 + r) * QKVW * 0 + (size_t)(st + q0 + r) * DMODEL + head * HDIM + c) = hv;
            }
        }
    }
}

// ---------------------------------------------------------------------------
// Host launcher
// ---------------------------------------------------------------------------
#define SYMF(p, s) do { void* _t; cudaGetSymbolAddress(&_t, s); p = (float*)_t; } while (0)
#define SYMH(p, s) do { void* _t; cudaGetSymbolAddress(&_t, s); p = (__half*)_t; } while (0)

static inline dim3 ggrid3(int Md, int Nd) {
    return dim3((Nd + 127) / 128, (Md + 127) / 128);
}
static inline dim3 tgrid(int K, int N) {
    return dim3((N + 31) / 32, (K + 31) / 32);
}

extern "C" void kernel_launch(void* const* d_in, const int* in_sizes, int n_in,
                              void* d_out, int out_size)
{
    (void)in_sizes; (void)n_in; (void)out_size;
    const float* pixel    = (const float*)d_in[0];
    const float* patch_w  = (const float*)d_in[2];
    const float* patch_b  = (const float*)d_in[3];
    const float* pos_tab  = (const float*)d_in[4];
    const float* ln1_s    = (const float*)d_in[5];
    const float* ln1_b    = (const float*)d_in[6];
    const float* qkv_w    = (const float*)d_in[7];
    const float* qkv_b    = (const float*)d_in[8];
    const float* proj_w   = (const float*)d_in[9];
    const float* proj_b   = (const float*)d_in[10];
    const float* ln2_s    = (const float*)d_in[11];
    const float* ln2_b    = (const float*)d_in[12];
    const float* fc1_w    = (const float*)d_in[13];
    const float* fc1_b    = (const float*)d_in[14];
    const float* fc2_w    = (const float*)d_in[15];
    const float* fc2_b    = (const float*)d_in[16];
    const float* m_ln_s   = (const float*)d_in[17];
    const float* m_ln_b   = (const float*)d_in[18];
    const float* m_fc1_w  = (const float*)d_in[19];
    const float* m_fc1_b  = (const float*)d_in[20];
    const float* m_fc2_w  = (const float*)d_in[21];
    const float* m_fc2_b  = (const float*)d_in[22];
    float* out = (float*)d_out;

    float *x;
    __half *pix, *hh, *qkvh, *attnh, *mlph, *wt;
    SYMF(x, g_x);
    SYMH(pix, g_pix); SYMH(hh, g_hh); SYMH(qkvh, g_qkvh);
    SYMH(attnh, g_attnh); SYMH(mlph, g_mlph); SYMH(wt, g_wt);

    static bool attr_set = false;
    if (!attr_set) {
        cudaFuncSetAttribute(flash_h,
                             cudaFuncAttributeMaxDynamicSharedMemorySize, FA_BYTES);
        attr_set = true;
    }

    // ---- weight conversion / transposition (device-side, every replay)
    conv_h<<<(NTOK * CIN + 255) / 256, 256>>>(pixel, pix, NTOK * CIN);
    wt_t<<<tgrid(CIN, DMODEL), dim3(32, 8)>>>(patch_w, wt + OFF_PATCH, CIN, DMODEL);
    for (int l = 0; l < 2; l++) {
        wt_t<<<tgrid(DMODEL, QKVW), dim3(32, 8)>>>(
            qkv_w + (size_t)l * DMODEL * QKVW, wt + OFF_QKV + l * SZ_QKV, DMODEL, QKVW);
        wt_t<<<tgrid(DMODEL, DMODEL), dim3(32, 8)>>>(
            proj_w + (size_t)l * DMODEL * DMODEL, wt + OFF_PROJ + l * SZ_PROJ, DMODEL, DMODEL);
        wt_t<<<tgrid(DMODEL, IDIM), dim3(32, 8)>>>(
            fc1_w + (size_t)l * DMODEL * IDIM, wt + OFF_FC1 + l * SZ_FC1, DMODEL, IDIM);
        wt_t<<<tgrid(IDIM, DMODEL), dim3(32, 8)>>>(
            fc2_w + (size_t)l * IDIM * DMODEL, wt + OFF_FC2 + l * SZ_FC2, IDIM, DMODEL);
    }
    wt_t<<<tgrid(MD4, MD4), dim3(32, 8)>>>(m_fc1_w, wt + OFF_MFC1, MD4, MD4);
    wt_t<<<tgrid(MD4, DOUT), dim3(32, 8)>>>(m_fc2_w, wt + OFF_MFC2, MD4, DOUT);

    cossin_kernel<<<(NTOK * 36 + 255) / 256, 256>>>();

    // Patch embed -> x (fp32)
    gemm3<EPI_BIAS, false><<<ggrid3(NTOK, DMODEL), 256>>>(
        pix, CIN, wt + OFF_PATCH, CIN, x, DMODEL,
        patch_b, nullptr, 0, NTOK, DMODEL, CIN);

    posadd_kernel<<<NTOK, 288>>>(pos_tab);

    for (int l = 0; l < 2; l++) {
        ln_h<<<NTOK, 288>>>(x, hh, ln1_s + l * DMODEL, ln1_b + l * DMODEL);

        gemm3<EPI_BIAS, true><<<ggrid3(NTOK, QKVW), 256>>>(
            hh, DMODEL, wt + OFF_QKV + l * SZ_QKV, DMODEL, qkvh, QKVW,
            qkv_b + (size_t)l * QKVW, nullptr, 0, NTOK, QKVW, DMODEL);

        rope_h<<<NTOK, 576>>>();

        flash_h<<<dim3(50, HEADS), 256, FA_BYTES>>>(qkvh, attnh);

        gemm3<EPI_BIAS_RES, false><<<ggrid3(NTOK, DMODEL), 256>>>(
            attnh, DMODEL, wt + OFF_PROJ + l * SZ_PROJ, DMODEL, x, DMODEL,
            proj_b + (size_t)l * DMODEL, x, DMODEL, NTOK, DMODEL, DMODEL);

        ln_h<<<NTOK, 288>>>(x, hh, ln2_s + l * DMODEL, ln2_b + l * DMODEL);

        gemm3<EPI_BIAS_GELU, true><<<ggrid3(NTOK, IDIM), 256>>>(
            hh, DMODEL, wt + OFF_FC1 + l * SZ_FC1, DMODEL, mlph, IDIM,
            fc1_b + (size_t)l * IDIM, nullptr, 0, NTOK, IDIM, DMODEL);

        gemm3<EPI_BIAS_RES, false><<<ggrid3(NTOK, DMODEL), 256>>>(
            mlph, IDIM, wt + OFF_FC2 + l * SZ_FC2, IDIM, x, DMODEL,
            fc2_b + (size_t)l * DMODEL, x, DMODEL, NTOK, DMODEL, IDIM);
    }

    // merger
    ln_h<<<NTOK, 288>>>(x, hh, m_ln_s, m_ln_b);   // hh viewed as [1568][4608]

    gemm3<EPI_BIAS_GELU, true><<<ggrid3(MROWS, MD4), 256>>>(
        hh, MD4, wt + OFF_MFC1, MD4, mlph, MD4,
        m_fc1_b, nullptr, 0, MROWS, MD4, MD4);

    gemm3<EPI_BIAS, false><<<ggrid3(MROWS, DOUT), 256>>>(
        mlph, MD4, wt + OFF_MFC2, MD4, out, DOUT,
        m_fc2_b, nullptr, 0, MROWS, DOUT, MD4);
}

// round 10
// speedup vs baseline: 1.3395x; 1.0920x over previous
#include <cuda_runtime.h>
#include <cuda_fp16.h>
#include <math.h>
#include <stdint.h>

// ---------------------------------------------------------------------------
// Problem constants (GRID fixed: [[1,48,48],[1,32,64],[2,24,40]])
// ---------------------------------------------------------------------------
#define NTOK    6272
#define DMODEL  1152
#define HEADS   16
#define HDIM    72
#define IDIM    4304
#define DOUT    2048
#define MROWS   1568
#define MD4     4608
#define QKVW    3456
#define CIN     1536

// ---------------------------------------------------------------------------
// Scratch buffers
// ---------------------------------------------------------------------------
__device__ float  g_x    [NTOK * DMODEL];        // residual (fp32)
__device__ __half g_pix  [NTOK * CIN];           // pixel fp16
__device__ __half g_hh   [NTOK * DMODEL];        // LN out fp16
__device__ __half g_qkvh [NTOK * QKVW];          // qkv fp16
__device__ __half g_attnh[NTOK * DMODEL];        // attn out fp16
__device__ __half g_mlph [NTOK * IDIM];          // mlp hidden fp16
__device__ float  g_cos  [NTOK * 36];
__device__ float  g_sin  [NTOK * 36];

// fp16 weights, natural [K,N] layout (no transpose)
#define SZ_PATCH (1536ULL * 1152)
#define SZ_QKV   (1152ULL * 3456)
#define SZ_PROJ  (1152ULL * 1152)
#define SZ_FC1   (1152ULL * 4304)
#define SZ_FC2   (4304ULL * 1152)
#define SZ_MFC1  (4608ULL * 4608)
#define SZ_MFC2  (4608ULL * 2048)
#define OFF_PATCH 0ULL
#define OFF_QKV   (OFF_PATCH + SZ_PATCH)
#define OFF_PROJ  (OFF_QKV + 2 * SZ_QKV)
#define OFF_FC1   (OFF_PROJ + 2 * SZ_PROJ)
#define OFF_FC2   (OFF_FC1 + 2 * SZ_FC1)
#define OFF_MFC1  (OFF_FC2 + 2 * SZ_FC2)
#define OFF_MFC2  (OFF_MFC1 + SZ_MFC1)
#define WT_TOTAL  (OFF_MFC2 + SZ_MFC2)
__device__ __half g_wt[WT_TOTAL];

// ---------------------------------------------------------------------------
__device__ __forceinline__ void token_pos(int n, int& row, int& col, int& ih, int& iw)
{
    int local, h, w;
    if (n < 2304)      { local = n;          h = 48; w = 48; }
    else if (n < 4352) { local = n - 2304;   h = 32; w = 64; }
    else               { local = n - 4352;   h = 24; w = 40; }
    int rem = local % (h * w);
    int wb_cnt = w >> 1;
    int blk = rem >> 2, within = rem & 3;
    int hb = blk / wb_cnt, wb = blk % wb_cnt;
    row = hb * 2 + (within >> 1);
    col = wb * 2 + (within & 1);
    ih = h; iw = w;
}

__global__ void cossin_kernel()
{
    int idx = blockIdx.x * blockDim.x + threadIdx.x;
    if (idx >= NTOK * 36) return;
    int n = idx / 36, d = idx % 36;
    int row, col, ih, iw;
    token_pos(n, row, col, ih, iw);
    int j = (d < 18) ? d : d - 18;
    double p = (d < 18) ? (double)row : (double)col;
    double inv = 1.0 / pow(10000.0, (2.0 * (double)j) / 36.0);
    double ang = p * inv;
    g_cos[idx] = (float)cos(ang);
    g_sin[idx] = (float)sin(ang);
}

__global__ void posadd_kernel(const float* __restrict__ pos_table)
{
    int n = blockIdx.x;
    int row, col, ih, iw;
    token_pos(n, row, col, ih, iw);
    double hi = 47.0 * (double)row / (double)(ih - 1);
    double wi = 47.0 * (double)col / (double)(iw - 1);
    int hf = (int)floor(hi), wf = (int)floor(wi);
    float dh = (float)(hi - (double)hf), dw = (float)(wi - (double)wf);
    int hc = min(hf + 1, 47), wc = min(wf + 1, 47);
    float w00 = (1.f - dh) * (1.f - dw);
    float w01 = (1.f - dh) * dw;
    float w10 = dh * (1.f - dw);
    float w11 = dh * dw;
    const float* p00 = pos_table + (size_t)(hf * 48 + wf) * DMODEL;
    const float* p01 = pos_table + (size_t)(hf * 48 + wc) * DMODEL;
    const float* p10 = pos_table + (size_t)(hc * 48 + wf) * DMODEL;
    const float* p11 = pos_table + (size_t)(hc * 48 + wc) * DMODEL;
    float* xr = g_x + (size_t)n * DMODEL;
    for (int d = threadIdx.x; d < DMODEL; d += blockDim.x)
        xr[d] += p00[d] * w00 + p01[d] * w01 + p10[d] * w10 + p11[d] * w11;
}

// fp32 -> fp16 streaming convert (vectorized 4/thread)
__global__ void conv_h4(const float* __restrict__ in, __half* __restrict__ out, int n4)
{
    int i = blockIdx.x * blockDim.x + threadIdx.x;
    if (i >= n4) return;
    float4 v = reinterpret_cast<const float4*>(in)[i];
    __half2 lo = __floats2half2_rn(v.x, v.y);
    __half2 hi = __floats2half2_rn(v.z, v.w);
    reinterpret_cast<uint2*>(out)[i] =
        make_uint2(*reinterpret_cast<uint32_t*>(&lo), *reinterpret_cast<uint32_t*>(&hi));
}

__device__ __forceinline__ float warp_sum(float v)
{
#pragma unroll
    for (int o = 16; o > 0; o >>= 1) v += __shfl_xor_sync(0xffffffffu, v, o);
    return v;
}

// LayerNorm fp32 in -> fp16 out
__global__ void ln_h(const float* __restrict__ in, __half* __restrict__ out,
                     const float* __restrict__ s, const float* __restrict__ b)
{
    __shared__ float sh[9];
    __shared__ float stat[2];
    int n = blockIdx.x;
    const float* xr = in + (size_t)n * DMODEL;
    int t = threadIdx.x, wid = t >> 5, lane = t & 31;

    float vals[4];
    float lsum = 0.f;
#pragma unroll
    for (int i = 0; i < 4; i++) { vals[i] = xr[t + i * 288]; lsum += vals[i]; }
    float ws = warp_sum(lsum);
    if (lane == 0) sh[wid] = ws;
    __syncthreads();
    if (t == 0) {
        float tot = 0.f;
#pragma unroll
        for (int i = 0; i < 9; i++) tot += sh[i];
        stat[0] = tot * (1.0f / DMODEL);
    }
    __syncthreads();
    float mu = stat[0];
    float lvar = 0.f;
#pragma unroll
    for (int i = 0; i < 4; i++) { float d = vals[i] - mu; lvar += d * d; }
    ws = warp_sum(lvar);
    __syncthreads();
    if (lane == 0) sh[wid] = ws;
    __syncthreads();
    if (t == 0) {
        float tot = 0.f;
#pragma unroll
        for (int i = 0; i < 9; i++) tot += sh[i];
        stat[1] = rsqrtf(tot * (1.0f / DMODEL) + 1e-6f);
    }
    __syncthreads();
    float r = stat[1];
    __half* orow = out + (size_t)n * DMODEL;
#pragma unroll
    for (int i = 0; i < 4; i++) {
        int d = t + i * 288;
        orow[d] = __float2half_rn((vals[i] - mu) * r * s[d] + b[d]);
    }
}

// RoPE in-place on fp16 qkv
__global__ void rope_h()
{
    int n = blockIdx.x;
    int t = threadIdx.x;
    int h = t / 36, d = t % 36;
    float c = g_cos[n * 36 + d];
    float s = g_sin[n * 36 + d];
    __half* q = g_qkvh + (size_t)n * QKVW + h * HDIM;
    __half* k = q + DMODEL;
    float q0 = __half2float(q[d]), q1 = __half2float(q[d + 36]);
    q[d]      = __float2half_rn(q0 * c - q1 * s);
    q[d + 36] = __float2half_rn(q1 * c + q0 * s);
    float k0 = __half2float(k[d]), k1 = __half2float(k[d + 36]);
    k[d]      = __float2half_rn(k0 * c - k1 * s);
    k[d + 36] = __float2half_rn(k1 * c + k0 * s);
}

// ---------------------------------------------------------------------------
// mma / misc helpers
// ---------------------------------------------------------------------------
__device__ __forceinline__ void mma_f16(float c[4],
                                        uint32_t a0, uint32_t a1, uint32_t a2, uint32_t a3,
                                        uint32_t b0, uint32_t b1)
{
    asm volatile(
        "mma.sync.aligned.m16n8k16.row.col.f32.f16.f16.f32 "
        "{%0,%1,%2,%3}, {%4,%5,%6,%7}, {%8,%9}, {%0,%1,%2,%3};\n"
        : "+f"(c[0]), "+f"(c[1]), "+f"(c[2]), "+f"(c[3])
        : "r"(a0), "r"(a1), "r"(a2), "r"(a3), "r"(b0), "r"(b1));
}

// fast gelu: HW tanh approx (MUFU.TANH)
__device__ __forceinline__ float gelu_tanh(float x)
{
    float u = 0.7978845608028654f * (x + 0.044715f * x * x * x);
    float t;
    asm("tanh.approx.f32 %0, %1;" : "=f"(t) : "f"(u));
    return 0.5f * x * (1.f + t);
}

__device__ __forceinline__ uint32_t pack_h2(float lo, float hi)
{
    __half2 h = __floats2half2_rn(lo, hi);
    return *reinterpret_cast<uint32_t*>(&h);
}

// ---------------------------------------------------------------------------
// GEMM v3t: A fp16 [M,K] row-major, B fp16 [K,N] row-major, C fp32 or fp16.
//   Block 128x128, BK=16, 4 stages, cp.async.  8 warps 2(M) x 4(N), 64x32.
//   A fragments: ldmatrix (rows padded to 24 halfs).
//   B fragments: ldmatrix.trans from [k][n] tile, rows padded to 136 halfs
//     (trans phase banks 4k+{0..3} -> all 32 banks once per 8-lane phase).
//   Stage: A 1536 words + B 1088 words = 2624 words.  4 stages = 41984 B.
// ---------------------------------------------------------------------------
#define EPI_BIAS      1
#define EPI_BIAS_GELU 2
#define EPI_BIAS_RES  3

#define G3_STG  2624            // words per stage
#define G3_BOFF 1536            // B offset within stage (words)

template<int EPI, bool OUTH>
__global__ void __launch_bounds__(256, 2)
gemm3(const __half* __restrict__ A, int lda,
      const __half* __restrict__ B, int ldb,
      void* __restrict__ Cv, int ldc,
      const float* __restrict__ bias,
      const float* __restrict__ Res, int ldr,
      int Md, int Nd, int Kd)
{
    __shared__ uint32_t smbuf[4 * G3_STG];

    const int tid  = threadIdx.x;
    const int brow = blockIdx.y * 128;
    const int bcol = blockIdx.x * 128;
    const int w    = tid >> 5;
    const int lane = tid & 31;
    const int g    = lane >> 2;
    const int q    = lane & 3;
    const int wm   = w & 1;                  // 2 warps M
    const int wn   = w >> 1;                 // 4 warps N

    uint32_t smbase = (uint32_t)__cvta_generic_to_shared(smbuf);

    // A cp.async: one 16B chunk per thread per stage
    const int acrow = tid >> 1;
    const int ack8  = (tid & 1) * 8;
    const long long ar = brow + acrow;
    const int aval = (ar < Md) ? 16 : 0;
    const uint32_t sa = smbase + (uint32_t)(acrow * 12 + (ack8 >> 1)) * 4;
    const __half* ga = A + ar * lda + ack8;

    // B cp.async: one 16B chunk per thread per stage; [16 k][128 n] tile
    const int bk   = tid >> 4;               // 0..15 (k row)
    const int bn16 = (tid & 15) * 8;         // 0..120 (n col, halfs)
    const int bval = ((bcol + bn16) < Nd) ? 16 : 0;
    const uint32_t sb = smbase + (uint32_t)G3_BOFF * 4 + (uint32_t)(bk * 272 + bn16 * 2);
    const __half* gb = B + (long long)bk * ldb + bcol + bn16;

    float acc[4][4][4];
#pragma unroll
    for (int i = 0; i < 4; i++)
#pragma unroll
        for (int j = 0; j < 4; j++)
#pragma unroll
            for (int r = 0; r < 4; r++) acc[i][j][r] = 0.f;

    const int nt = Kd >> 4;

    // prologue: stages 0..2
#pragma unroll
    for (int s = 0; s < 3; s++) {
        uint32_t off = (uint32_t)(s * G3_STG) * 4;
        int k0 = s * 16;
        asm volatile("cp.async.cg.shared.global [%0], [%1], 16, %2;"
                     :: "r"(sa + off), "l"(ga + k0), "r"(aval));
        asm volatile("cp.async.cg.shared.global [%0], [%1], 16, %2;"
                     :: "r"(sb + off), "l"(gb + (long long)k0 * ldb), "r"(bval));
        asm volatile("cp.async.commit_group;");
    }

    // A ldmatrix lane addressing (non-trans, rows m, stride 12 words)
    const int a_row = wm * 64 + (lane & 15);
    const int a_kw  = (lane >> 4) * 4;
    const uint32_t abase = smbase + (uint32_t)(a_row * 12 + a_kw) * 4;
    // B ldmatrix.trans lane addressing: k = lane&15, n = wn*32 + (lane>>4)*8
    const uint32_t bbase = smbase + (uint32_t)G3_BOFF * 4 +
        (uint32_t)((lane & 15) * 272 + (wn * 32 + (lane >> 4) * 8) * 2);

    for (int kt = 0; kt < nt; kt++) {
        asm volatile("cp.async.wait_group 2;");
        __syncthreads();
        uint32_t soff = (uint32_t)((kt & 3) * G3_STG) * 4;

        uint32_t af[4][4], bf[2][4];
#pragma unroll
        for (int mt = 0; mt < 4; mt++)
            asm volatile("ldmatrix.sync.aligned.m8n8.x4.shared.b16 {%0,%1,%2,%3}, [%4];"
                         : "=r"(af[mt][0]), "=r"(af[mt][1]), "=r"(af[mt][2]), "=r"(af[mt][3])
                         : "r"(abase + soff + (uint32_t)(mt * 16 * 12) * 4));
#pragma unroll
        for (int ng = 0; ng < 2; ng++)
            asm volatile("ldmatrix.sync.aligned.m8n8.x4.trans.shared.b16 {%0,%1,%2,%3}, [%4];"
                         : "=r"(bf[ng][0]), "=r"(bf[ng][1]), "=r"(bf[ng][2]), "=r"(bf[ng][3])
                         : "r"(bbase + soff + (uint32_t)(ng * 32)));

#pragma unroll
        for (int mt = 0; mt < 4; mt++)
#pragma unroll
            for (int j = 0; j < 4; j++)
                mma_f16(acc[mt][j],
                        af[mt][0], af[mt][1], af[mt][2], af[mt][3],
                        bf[j >> 1][(j & 1) * 2], bf[j >> 1][(j & 1) * 2 + 1]);

        int ktn = kt + 3;
        if (ktn < nt) {
            uint32_t doff = (uint32_t)((ktn & 3) * G3_STG) * 4;
            int k0 = ktn * 16;
            asm volatile("cp.async.cg.shared.global [%0], [%1], 16, %2;"
                         :: "r"(sa + doff), "l"(ga + k0), "r"(aval));
            asm volatile("cp.async.cg.shared.global [%0], [%1], 16, %2;"
                         :: "r"(sb + doff), "l"(gb + (long long)k0 * ldb), "r"(bval));
        }
        asm volatile("cp.async.commit_group;");
    }

    // epilogue (Nd is even; c always even -> pair stores safe)
    float*  Cf = (float*)Cv;
    __half* Ch = (__half*)Cv;
#pragma unroll
    for (int mt = 0; mt < 4; mt++) {
#pragma unroll
        for (int hh = 0; hh < 2; hh++) {
            int r = brow + wm * 64 + mt * 16 + g + 8 * hh;
            if (r >= Md) continue;
#pragma unroll
            for (int j = 0; j < 4; j++) {
                int c = bcol + wn * 32 + j * 8 + 2 * q;
                if (c >= Nd) continue;
                float v0 = acc[mt][j][hh * 2];
                float v1 = acc[mt][j][hh * 2 + 1];
                v0 += bias[c]; v1 += bias[c + 1];
                if (EPI == EPI_BIAS_GELU) { v0 = gelu_tanh(v0); v1 = gelu_tanh(v1); }
                if (EPI == EPI_BIAS_RES)  {
                    v0 += Res[(long long)r * ldr + c];
                    v1 += Res[(long long)r * ldr + c + 1];
                }
                if (OUTH) {
                    __half2 hv = __floats2half2_rn(v0, v1);
                    *reinterpret_cast<__half2*>(Ch + (long long)r * ldc + c) = hv;
                } else {
                    *reinterpret_cast<float2*>(Cf + (long long)r * ldc + c) = make_float2(v0, v1);
                }
            }
        }
    }
}

// ---------------------------------------------------------------------------
// Fused flash attention, fp16 in/out, m16n8k16, online softmax (fp32 stats).
// ---------------------------------------------------------------------------
#define QS_OFF   0
#define QS_ST    44
#define KS_OFF   (QS_OFF + 128 * QS_ST)
#define KS_ST    72
#define VS_OFF   (KS_OFF + 40 * KS_ST)
#define VS_ST    104
#define PS_OFF   (VS_OFF + 32 * VS_ST)
#define PS_ST    36
#define MS_OFF   (PS_OFF + 128 * PS_ST)
#define LS_OFF   (MS_OFF + 128)
#define AL_OFF   (LS_OFF + 128)
#define RED_OFF  (AL_OFF + 128)
#define FA_WORDS (RED_OFF + 512)
#define FA_BYTES (FA_WORDS * 4)

__global__ void __launch_bounds__(256, 1)
flash_h(const __half* __restrict__ qkv, __half* __restrict__ attn)
{
    extern __shared__ uint32_t smem[];
    uint32_t* Qs = smem + QS_OFF;
    uint32_t* Ks = smem + KS_OFF;
    uint32_t* Vs = smem + VS_OFF;
    uint32_t* Ps = smem + PS_OFF;
    float* m_s  = (float*)(smem + MS_OFF);
    float* l_s  = (float*)(smem + LS_OFF);
    float* al_s = (float*)(smem + AL_OFF);
    float* red  = (float*)(smem + RED_OFF);

    int t = blockIdx.x;
    int head = blockIdx.y;
    int st, S, q0;
    if (t < 18)      { st = 0;    S = 2304; q0 = t * 128; }
    else if (t < 34) { st = 2304; S = 2048; q0 = (t - 18) * 128; }
    else if (t < 42) { st = 4352; S = 960;  q0 = (t - 34) * 128; }
    else             { st = 5312; S = 960;  q0 = (t - 42) * 128; }

    const int tid = threadIdx.x;
    const int w = tid >> 5, lane = tid & 31;
    const int g = lane >> 2, q = lane & 3;
    const int wm  = w & 1, wn  = w >> 1;
    const int wm2 = w & 3, wn2 = w >> 2;

    const float scale = 0.11785113019775793f;

    for (int s = tid; s < 128 * 9; s += 256) {
        int row = s / 9, w8 = s % 9;
        uint4 v = make_uint4(0, 0, 0, 0);
        if (q0 + row < S)
            v = *reinterpret_cast<const uint4*>(
                qkv + (size_t)(st + q0 + row) * QKVW + head * HDIM + w8 * 8);
        *reinterpret_cast<uint4*>(&Qs[row * QS_ST + w8 * 4]) = v;
    }
    for (int s = tid; s < 512; s += 256) {
        int row = s >> 2, kk = 36 + (s & 3);
        Qs[row * QS_ST + kk] = 0;
    }
    if (tid < 256) Ks[(36 + (tid >> 6)) * KS_ST + (tid & 63)] = 0;
    if (tid < 256) Vs[(tid >> 3) * VS_ST + 72 + (tid & 7)] = 0;
    if (tid < 128) { m_s[tid] = -1e30f; l_s[tid] = 0.f; }

    float O[2][5][4];
#pragma unroll
    for (int i = 0; i < 2; i++)
#pragma unroll
        for (int j = 0; j < 5; j++)
#pragma unroll
            for (int r = 0; r < 4; r++) O[i][j][r] = 0.f;

    const int nkv = S >> 6;
    for (int j = 0; j < nkv; j++) {
        __syncthreads();
        const int kv0 = j * 64;
        for (int s = tid; s < 64 * 9; s += 256) {
            int kv = s / 9, w8 = s % 9;
            uint4 v = *reinterpret_cast<const uint4*>(
                qkv + (size_t)(st + kv0 + kv) * QKVW + DMODEL + head * HDIM + w8 * 8);
            Ks[(w8 * 4 + 0) * KS_ST + kv] = v.x;
            Ks[(w8 * 4 + 1) * KS_ST + kv] = v.y;
            Ks[(w8 * 4 + 2) * KS_ST + kv] = v.z;
            Ks[(w8 * 4 + 3) * KS_ST + kv] = v.w;
        }
        for (int s = tid; s < 64 * 9; s += 256) {
            int kv = s / 9, w8 = s % 9;
            uint4 v = *reinterpret_cast<const uint4*>(
                qkv + (size_t)(st + kv0 + kv) * QKVW + 2 * DMODEL + head * HDIM + w8 * 8);
            uint16_t hx[8];
            *reinterpret_cast<uint4*>(hx) = v;
            uint16_t* Vh = reinterpret_cast<uint16_t*>(Vs);
            int base = ((kv >> 1) * VS_ST + w8 * 8) * 2 + (kv & 1);
#pragma unroll
            for (int i = 0; i < 8; i++) Vh[base + 2 * i] = hx[i];
        }
        __syncthreads();

        float acc_s[4][2][4];
#pragma unroll
        for (int a = 0; a < 4; a++)
#pragma unroll
            for (int b = 0; b < 2; b++)
#pragma unroll
                for (int r = 0; r < 4; r++) acc_s[a][b][r] = 0.f;

#pragma unroll
        for (int i = 0; i < 5; i++) {
            int kb = i * 8;
            uint32_t af[4][4], bf[2][2];
#pragma unroll
            for (int mt = 0; mt < 4; mt++) {
                int mb = wm * 64 + mt * 16;
                af[mt][0] = Qs[(mb + g    ) * QS_ST + kb + q    ];
                af[mt][1] = Qs[(mb + g + 8) * QS_ST + kb + q    ];
                af[mt][2] = Qs[(mb + g    ) * QS_ST + kb + q + 4];
                af[mt][3] = Qs[(mb + g + 8) * QS_ST + kb + q + 4];
            }
#pragma unroll
            for (int nt = 0; nt < 2; nt++) {
                int nb = wn * 16 + nt * 8;
                bf[nt][0] = Ks[(kb + q    ) * KS_ST + nb + g];
                bf[nt][1] = Ks[(kb + q + 4) * KS_ST + nb + g];
            }
#pragma unroll
            for (int mt = 0; mt < 4; mt++)
#pragma unroll
                for (int nt = 0; nt < 2; nt++)
                    mma_f16(acc_s[mt][nt],
                            af[mt][0], af[mt][1], af[mt][2], af[mt][3],
                            bf[nt][0], bf[nt][1]);
        }
#pragma unroll
        for (int a = 0; a < 4; a++)
#pragma unroll
            for (int b = 0; b < 2; b++)
#pragma unroll
                for (int r = 0; r < 4; r++) acc_s[a][b][r] *= scale;

#pragma unroll
        for (int mt = 0; mt < 4; mt++) {
#pragma unroll
            for (int h = 0; h < 2; h++) {
                float rmx = fmaxf(fmaxf(acc_s[mt][0][2 * h], acc_s[mt][0][2 * h + 1]),
                                  fmaxf(acc_s[mt][1][2 * h], acc_s[mt][1][2 * h + 1]));
                rmx = fmaxf(rmx, __shfl_xor_sync(0xffffffffu, rmx, 1));
                rmx = fmaxf(rmx, __shfl_xor_sync(0xffffffffu, rmx, 2));
                if (q == 0)
                    red[wn * 128 + wm * 64 + mt * 16 + g + 8 * h] = rmx;
            }
        }
        __syncthreads();
        if (tid < 128) {
            float tm = fmaxf(fmaxf(red[tid], red[128 + tid]),
                             fmaxf(red[256 + tid], red[384 + tid]));
            float mo = m_s[tid];
            float mn = fmaxf(mo, tm);
            al_s[tid] = __expf(mo - mn);
            m_s[tid]  = mn;
        }
        __syncthreads();

#pragma unroll
        for (int mt = 0; mt < 4; mt++) {
#pragma unroll
            for (int h = 0; h < 2; h++) {
                int row = wm * 64 + mt * 16 + g + 8 * h;
                float mn = m_s[row];
                float rs = 0.f;
#pragma unroll
                for (int nt = 0; nt < 2; nt++) {
                    int nb = wn * 16 + nt * 8;
                    float p0 = __expf(acc_s[mt][nt][2 * h    ] - mn);
                    float p1 = __expf(acc_s[mt][nt][2 * h + 1] - mn);
                    rs += p0 + p1;
                    Ps[row * PS_ST + (nb >> 1) + q] = pack_h2(p0, p1);
                }
                rs += __shfl_xor_sync(0xffffffffu, rs, 1);
                rs += __shfl_xor_sync(0xffffffffu, rs, 2);
                if (q == 0) red[wn * 128 + row] = rs;
            }
        }
#pragma unroll
        for (int mt = 0; mt < 2; mt++) {
#pragma unroll
            for (int h = 0; h < 2; h++) {
                int row = wm2 * 32 + mt * 16 + g + 8 * h;
                float a = al_s[row];
#pragma unroll
                for (int nt = 0; nt < 5; nt++) {
                    O[mt][nt][2 * h + 0] *= a;
                    O[mt][nt][2 * h + 1] *= a;
                }
            }
        }
        __syncthreads();
        if (tid < 128)
            l_s[tid] = l_s[tid] * al_s[tid] +
                       red[tid] + red[128 + tid] + red[256 + tid] + red[384 + tid];

#pragma unroll
        for (int i = 0; i < 4; i++) {
            int kb = i * 8;
            uint32_t af[2][4], bf[5][2];
#pragma unroll
            for (int mt = 0; mt < 2; mt++) {
                int mb = wm2 * 32 + mt * 16;
                af[mt][0] = Ps[(mb + g    ) * PS_ST + kb + q    ];
                af[mt][1] = Ps[(mb + g + 8) * PS_ST + kb + q    ];
                af[mt][2] = Ps[(mb + g    ) * PS_ST + kb + q + 4];
                af[mt][3] = Ps[(mb + g + 8) * PS_ST + kb + q + 4];
            }
#pragma unroll
            for (int nt = 0; nt < 5; nt++) {
                int nb = wn2 * 40 + nt * 8;
                bf[nt][0] = Vs[(kb + q    ) * VS_ST + nb + g];
                bf[nt][1] = Vs[(kb + q + 4) * VS_ST + nb + g];
            }
#pragma unroll
            for (int mt = 0; mt < 2; mt++)
#pragma unroll
                for (int nt = 0; nt < 5; nt++)
                    mma_f16(O[mt][nt],
                            af[mt][0], af[mt][1], af[mt][2], af[mt][3],
                            bf[nt][0], bf[nt][1]);
        }
    }
    __syncthreads();

#pragma unroll
    for (int mt = 0; mt < 2; mt++) {
#pragma unroll
        for (int h = 0; h < 2; h++) {
            int r = wm2 * 32 + mt * 16 + g + 8 * h;
            if (q0 + r >= S) continue;
            float inv = 1.0f / l_s[r];
#pragma unroll
            for (int nt = 0; nt < 5; nt++) {
                int c = wn2 * 40 + nt * 8 + 2 * q;
                if (c >= HDIM) continue;
                __half2 hv = __floats2half2_rn(O[mt][nt][2 * h] * inv,
                                               O[mt][nt][2 * h + 1] * inv);
                *reinterpret_cast<__half2*>(
                    attn + (size_t)(st + q0 + r) * DMODEL + head * HDIM + c) = hv;
            }
        }
    }
}

// ---------------------------------------------------------------------------
// Host launcher
// ---------------------------------------------------------------------------
#define SYMF(p, s) do { void* _t; cudaGetSymbolAddress(&_t, s); p = (float*)_t; } while (0)
#define SYMH(p, s) do { void* _t; cudaGetSymbolAddress(&_t, s); p = (__half*)_t; } while (0)

static inline dim3 ggrid3(int Md, int Nd) {
    return dim3((Nd + 127) / 128, (Md + 127) / 128);
}
static inline int cgrid4(long long n) {
    return (int)((n / 4 + 255) / 256);
}

extern "C" void kernel_launch(void* const* d_in, const int* in_sizes, int n_in,
                              void* d_out, int out_size)
{
    (void)in_sizes; (void)n_in; (void)out_size;
    const float* pixel    = (const float*)d_in[0];
    const float* patch_w  = (const float*)d_in[2];
    const float* patch_b  = (const float*)d_in[3];
    const float* pos_tab  = (const float*)d_in[4];
    const float* ln1_s    = (const float*)d_in[5];
    const float* ln1_b    = (const float*)d_in[6];
    const float* qkv_w    = (const float*)d_in[7];
    const float* qkv_b    = (const float*)d_in[8];
    const float* proj_w   = (const float*)d_in[9];
    const float* proj_b   = (const float*)d_in[10];
    const float* ln2_s    = (const float*)d_in[11];
    const float* ln2_b    = (const float*)d_in[12];
    const float* fc1_w    = (const float*)d_in[13];
    const float* fc1_b    = (const float*)d_in[14];
    const float* fc2_w    = (const float*)d_in[15];
    const float* fc2_b    = (const float*)d_in[16];
    const float* m_ln_s   = (const float*)d_in[17];
    const float* m_ln_b   = (const float*)d_in[18];
    const float* m_fc1_w  = (const float*)d_in[19];
    const float* m_fc1_b  = (const float*)d_in[20];
    const float* m_fc2_w  = (const float*)d_in[21];
    const float* m_fc2_b  = (const float*)d_in[22];
    float* out = (float*)d_out;

    float *x;
    __half *pix, *hh, *qkvh, *attnh, *mlph, *wt;
    SYMF(x, g_x);
    SYMH(pix, g_pix); SYMH(hh, g_hh); SYMH(qkvh, g_qkvh);
    SYMH(attnh, g_attnh); SYMH(mlph, g_mlph); SYMH(wt, g_wt);

    static bool attr_set = false;
    if (!attr_set) {
        cudaFuncSetAttribute(flash_h,
                             cudaFuncAttributeMaxDynamicSharedMemorySize, FA_BYTES);
        attr_set = true;
    }

    // ---- streaming fp32->fp16 weight conversion (no transpose)
    conv_h4<<<cgrid4((long long)NTOK * CIN), 256>>>(pixel, pix, NTOK * CIN / 4);
    conv_h4<<<cgrid4((long long)SZ_PATCH), 256>>>(patch_w, wt + OFF_PATCH, (int)(SZ_PATCH / 4));
    for (int l = 0; l < 2; l++) {
        conv_h4<<<cgrid4((long long)SZ_QKV), 256>>>(
            qkv_w + (size_t)l * SZ_QKV, wt + OFF_QKV + l * SZ_QKV, (int)(SZ_QKV / 4));
        conv_h4<<<cgrid4((long long)SZ_PROJ), 256>>>(
            proj_w + (size_t)l * SZ_PROJ, wt + OFF_PROJ + l * SZ_PROJ, (int)(SZ_PROJ / 4));
        conv_h4<<<cgrid4((long long)SZ_FC1), 256>>>(
            fc1_w + (size_t)l * SZ_FC1, wt + OFF_FC1 + l * SZ_FC1, (int)(SZ_FC1 / 4));
        conv_h4<<<cgrid4((long long)SZ_FC2), 256>>>(
            fc2_w + (size_t)l * SZ_FC2, wt + OFF_FC2 + l * SZ_FC2, (int)(SZ_FC2 / 4));
    }
    conv_h4<<<cgrid4((long long)SZ_MFC1), 256>>>(m_fc1_w, wt + OFF_MFC1, (int)(SZ_MFC1 / 4));
    conv_h4<<<cgrid4((long long)SZ_MFC2), 256>>>(m_fc2_w, wt + OFF_MFC2, (int)(SZ_MFC2 / 4));

    cossin_kernel<<<(NTOK * 36 + 255) / 256, 256>>>();

    // Patch embed -> x (fp32)
    gemm3<EPI_BIAS, false><<<ggrid3(NTOK, DMODEL), 256>>>(
        pix, CIN, wt + OFF_PATCH, DMODEL, x, DMODEL,
        patch_b, nullptr, 0, NTOK, DMODEL, CIN);

    posadd_kernel<<<NTOK, 288>>>(pos_tab);

    for (int l = 0; l < 2; l++) {
        ln_h<<<NTOK, 288>>>(x, hh, ln1_s + l * DMODEL, ln1_b + l * DMODEL);

        gemm3<EPI_BIAS, true><<<ggrid3(NTOK, QKVW), 256>>>(
            hh, DMODEL, wt + OFF_QKV + l * SZ_QKV, QKVW, qkvh, QKVW,
            qkv_b + (size_t)l * QKVW, nullptr, 0, NTOK, QKVW, DMODEL);

        rope_h<<<NTOK, 576>>>();

        flash_h<<<dim3(50, HEADS), 256, FA_BYTES>>>(qkvh, attnh);

        gemm3<EPI_BIAS_RES, false><<<ggrid3(NTOK, DMODEL), 256>>>(
            attnh, DMODEL, wt + OFF_PROJ + l * SZ_PROJ, DMODEL, x, DMODEL,
            proj_b + (size_t)l * DMODEL, x, DMODEL, NTOK, DMODEL, DMODEL);

        ln_h<<<NTOK, 288>>>(x, hh, ln2_s + l * DMODEL, ln2_b + l * DMODEL);

        gemm3<EPI_BIAS_GELU, true><<<ggrid3(NTOK, IDIM), 256>>>(
            hh, DMODEL, wt + OFF_FC1 + l * SZ_FC1, IDIM, mlph, IDIM,
            fc1_b + (size_t)l * IDIM, nullptr, 0, NTOK, IDIM, DMODEL);

        gemm3<EPI_BIAS_RES, false><<<ggrid3(NTOK, DMODEL), 256>>>(
            mlph, IDIM, wt + OFF_FC2 + l * SZ_FC2, DMODEL, x, DMODEL,
            fc2_b + (size_t)l * DMODEL, x, DMODEL, NTOK, DMODEL, IDIM);
    }

    // merger
    ln_h<<<NTOK, 288>>>(x, hh, m_ln_s, m_ln_b);   // hh viewed as [1568][4608]

    gemm3<EPI_BIAS_GELU, true><<<ggrid3(MROWS, MD4), 256>>>(
        hh, MD4, wt + OFF_MFC1, MD4, mlph, MD4,
        m_fc1_b, nullptr, 0, MROWS, MD4, MD4);

    gemm3<EPI_BIAS, false><<<ggrid3(MROWS, DOUT), 256>>>(
        mlph, MD4, wt + OFF_MFC2, DOUT, out, DOUT,
        m_fc2_b, nullptr, 0, MROWS, DOUT, MD4);
}

// round 11
// speedup vs baseline: 1.7335x; 1.2942x over previous
#include <cuda_runtime.h>
#include <cuda_fp16.h>
#include <math.h>
#include <stdint.h>

// ---------------------------------------------------------------------------
// Problem constants (GRID fixed: [[1,48,48],[1,32,64],[2,24,40]])
// ---------------------------------------------------------------------------
#define NTOK    6272
#define DMODEL  1152
#define HEADS   16
#define HDIM    72
#define IDIM    4304
#define DOUT    2048
#define MROWS   1568
#define MD4     4608
#define QKVW    3456
#define CIN     1536

// ---------------------------------------------------------------------------
// Scratch buffers
// ---------------------------------------------------------------------------
__device__ float  g_x    [NTOK * DMODEL];        // residual (fp32)
__device__ __half g_pix  [NTOK * CIN];           // pixel fp16
__device__ __half g_hh   [NTOK * DMODEL];        // LN out fp16
__device__ __half g_qkvh [NTOK * QKVW];          // qkv fp16
__device__ __half g_attnh[NTOK * DMODEL];        // attn out fp16
__device__ __half g_mlph [NTOK * IDIM];          // mlp hidden fp16
__device__ float  g_cos  [NTOK * 36];
__device__ float  g_sin  [NTOK * 36];

// fp16 weights, natural [K,N] layout (no transpose)
#define SZ_PATCH (1536ULL * 1152)
#define SZ_QKV   (1152ULL * 3456)
#define SZ_PROJ  (1152ULL * 1152)
#define SZ_FC1   (1152ULL * 4304)
#define SZ_FC2   (4304ULL * 1152)
#define SZ_MFC1  (4608ULL * 4608)
#define SZ_MFC2  (4608ULL * 2048)
#define OFF_PATCH 0ULL
#define OFF_QKV   (OFF_PATCH + SZ_PATCH)
#define OFF_PROJ  (OFF_QKV + 2 * SZ_QKV)
#define OFF_FC1   (OFF_PROJ + 2 * SZ_PROJ)
#define OFF_FC2   (OFF_FC1 + 2 * SZ_FC1)
#define OFF_MFC1  (OFF_FC2 + 2 * SZ_FC2)
#define OFF_MFC2  (OFF_MFC1 + SZ_MFC1)
#define WT_TOTAL  (OFF_MFC2 + SZ_MFC2)
__device__ __half g_wt[WT_TOTAL];

// ---------------------------------------------------------------------------
__device__ __forceinline__ void token_pos(int n, int& row, int& col, int& ih, int& iw)
{
    int local, h, w;
    if (n < 2304)      { local = n;          h = 48; w = 48; }
    else if (n < 4352) { local = n - 2304;   h = 32; w = 64; }
    else               { local = n - 4352;   h = 24; w = 40; }
    int rem = local % (h * w);
    int wb_cnt = w >> 1;
    int blk = rem >> 2, within = rem & 3;
    int hb = blk / wb_cnt, wb = blk % wb_cnt;
    row = hb * 2 + (within >> 1);
    col = wb * 2 + (within & 1);
    ih = h; iw = w;
}

__global__ void cossin_kernel()
{
    int idx = blockIdx.x * blockDim.x + threadIdx.x;
    if (idx >= NTOK * 36) return;
    int n = idx / 36, d = idx % 36;
    int row, col, ih, iw;
    token_pos(n, row, col, ih, iw);
    int j = (d < 18) ? d : d - 18;
    double p = (d < 18) ? (double)row : (double)col;
    double inv = 1.0 / pow(10000.0, (2.0 * (double)j) / 36.0);
    double ang = p * inv;
    g_cos[idx] = (float)cos(ang);
    g_sin[idx] = (float)sin(ang);
}

__global__ void posadd_kernel(const float* __restrict__ pos_table)
{
    int n = blockIdx.x;
    int row, col, ih, iw;
    token_pos(n, row, col, ih, iw);
    double hi = 47.0 * (double)row / (double)(ih - 1);
    double wi = 47.0 * (double)col / (double)(iw - 1);
    int hf = (int)floor(hi), wf = (int)floor(wi);
    float dh = (float)(hi - (double)hf), dw = (float)(wi - (double)wf);
    int hc = min(hf + 1, 47), wc = min(wf + 1, 47);
    float w00 = (1.f - dh) * (1.f - dw);
    float w01 = (1.f - dh) * dw;
    float w10 = dh * (1.f - dw);
    float w11 = dh * dw;
    const float* p00 = pos_table + (size_t)(hf * 48 + wf) * DMODEL;
    const float* p01 = pos_table + (size_t)(hf * 48 + wc) * DMODEL;
    const float* p10 = pos_table + (size_t)(hc * 48 + wf) * DMODEL;
    const float* p11 = pos_table + (size_t)(hc * 48 + wc) * DMODEL;
    float* xr = g_x + (size_t)n * DMODEL;
    for (int d = threadIdx.x; d < DMODEL; d += blockDim.x)
        xr[d] += p00[d] * w00 + p01[d] * w01 + p10[d] * w10 + p11[d] * w11;
}

// fp32 -> fp16 streaming convert (vectorized 4/thread)
__global__ void conv_h4(const float* __restrict__ in, __half* __restrict__ out, int n4)
{
    int i = blockIdx.x * blockDim.x + threadIdx.x;
    if (i >= n4) return;
    float4 v = reinterpret_cast<const float4*>(in)[i];
    __half2 lo = __floats2half2_rn(v.x, v.y);
    __half2 hi = __floats2half2_rn(v.z, v.w);
    reinterpret_cast<uint2*>(out)[i] =
        make_uint2(*reinterpret_cast<uint32_t*>(&lo), *reinterpret_cast<uint32_t*>(&hi));
}

__device__ __forceinline__ float warp_sum(float v)
{
#pragma unroll
    for (int o = 16; o > 0; o >>= 1) v += __shfl_xor_sync(0xffffffffu, v, o);
    return v;
}

// LayerNorm fp32 in -> fp16 out
__global__ void ln_h(const float* __restrict__ in, __half* __restrict__ out,
                     const float* __restrict__ s, const float* __restrict__ b)
{
    __shared__ float sh[9];
    __shared__ float stat[2];
    int n = blockIdx.x;
    const float* xr = in + (size_t)n * DMODEL;
    int t = threadIdx.x, wid = t >> 5, lane = t & 31;

    float vals[4];
    float lsum = 0.f;
#pragma unroll
    for (int i = 0; i < 4; i++) { vals[i] = xr[t + i * 288]; lsum += vals[i]; }
    float ws = warp_sum(lsum);
    if (lane == 0) sh[wid] = ws;
    __syncthreads();
    if (t == 0) {
        float tot = 0.f;
#pragma unroll
        for (int i = 0; i < 9; i++) tot += sh[i];
        stat[0] = tot * (1.0f / DMODEL);
    }
    __syncthreads();
    float mu = stat[0];
    float lvar = 0.f;
#pragma unroll
    for (int i = 0; i < 4; i++) { float d = vals[i] - mu; lvar += d * d; }
    ws = warp_sum(lvar);
    __syncthreads();
    if (lane == 0) sh[wid] = ws;
    __syncthreads();
    if (t == 0) {
        float tot = 0.f;
#pragma unroll
        for (int i = 0; i < 9; i++) tot += sh[i];
        stat[1] = rsqrtf(tot * (1.0f / DMODEL) + 1e-6f);
    }
    __syncthreads();
    float r = stat[1];
    __half* orow = out + (size_t)n * DMODEL;
#pragma unroll
    for (int i = 0; i < 4; i++) {
        int d = t + i * 288;
        orow[d] = __float2half_rn((vals[i] - mu) * r * s[d] + b[d]);
    }
}

// RoPE in-place on fp16 qkv
__global__ void rope_h()
{
    int n = blockIdx.x;
    int t = threadIdx.x;
    int h = t / 36, d = t % 36;
    float c = g_cos[n * 36 + d];
    float s = g_sin[n * 36 + d];
    __half* q = g_qkvh + (size_t)n * QKVW + h * HDIM;
    __half* k = q + DMODEL;
    float q0 = __half2float(q[d]), q1 = __half2float(q[d + 36]);
    q[d]      = __float2half_rn(q0 * c - q1 * s);
    q[d + 36] = __float2half_rn(q1 * c + q0 * s);
    float k0 = __half2float(k[d]), k1 = __half2float(k[d + 36]);
    k[d]      = __float2half_rn(k0 * c - k1 * s);
    k[d + 36] = __float2half_rn(k1 * c + k0 * s);
}

// ---------------------------------------------------------------------------
// mma / misc helpers
// ---------------------------------------------------------------------------
__device__ __forceinline__ void mma_f16(float c[4],
                                        uint32_t a0, uint32_t a1, uint32_t a2, uint32_t a3,
                                        uint32_t b0, uint32_t b1)
{
    asm volatile(
        "mma.sync.aligned.m16n8k16.row.col.f32.f16.f16.f32 "
        "{%0,%1,%2,%3}, {%4,%5,%6,%7}, {%8,%9}, {%0,%1,%2,%3};\n"
        : "+f"(c[0]), "+f"(c[1]), "+f"(c[2]), "+f"(c[3])
        : "r"(a0), "r"(a1), "r"(a2), "r"(a3), "r"(b0), "r"(b1));
}

// fast gelu: HW tanh approx (MUFU.TANH)
__device__ __forceinline__ float gelu_tanh(float x)
{
    float u = 0.7978845608028654f * (x + 0.044715f * x * x * x);
    float t;
    asm("tanh.approx.f32 %0, %1;" : "=f"(t) : "f"(u));
    return 0.5f * x * (1.f + t);
}

__device__ __forceinline__ uint32_t pack_h2(float lo, float hi)
{
    __half2 h = __floats2half2_rn(lo, hi);
    return *reinterpret_cast<uint32_t*>(&h);
}

// ---------------------------------------------------------------------------
// GEMM v3t: A fp16 [M,K] row-major, B fp16 [K,N] row-major, C fp32 or fp16.
//   (unchanged from R10 — verified)
// ---------------------------------------------------------------------------
#define EPI_BIAS      1
#define EPI_BIAS_GELU 2
#define EPI_BIAS_RES  3

#define G3_STG  2624            // words per stage
#define G3_BOFF 1536            // B offset within stage (words)

template<int EPI, bool OUTH>
__global__ void __launch_bounds__(256, 2)
gemm3(const __half* __restrict__ A, int lda,
      const __half* __restrict__ B, int ldb,
      void* __restrict__ Cv, int ldc,
      const float* __restrict__ bias,
      const float* __restrict__ Res, int ldr,
      int Md, int Nd, int Kd)
{
    __shared__ uint32_t smbuf[4 * G3_STG];

    const int tid  = threadIdx.x;
    const int brow = blockIdx.y * 128;
    const int bcol = blockIdx.x * 128;
    const int w    = tid >> 5;
    const int lane = tid & 31;
    const int g    = lane >> 2;
    const int q    = lane & 3;
    const int wm   = w & 1;
    const int wn   = w >> 1;

    uint32_t smbase = (uint32_t)__cvta_generic_to_shared(smbuf);

    const int acrow = tid >> 1;
    const int ack8  = (tid & 1) * 8;
    const long long ar = brow + acrow;
    const int aval = (ar < Md) ? 16 : 0;
    const uint32_t sa = smbase + (uint32_t)(acrow * 12 + (ack8 >> 1)) * 4;
    const __half* ga = A + ar * lda + ack8;

    const int bk   = tid >> 4;
    const int bn16 = (tid & 15) * 8;
    const int bval = ((bcol + bn16) < Nd) ? 16 : 0;
    const uint32_t sb = smbase + (uint32_t)G3_BOFF * 4 + (uint32_t)(bk * 272 + bn16 * 2);
    const __half* gb = B + (long long)bk * ldb + bcol + bn16;

    float acc[4][4][4];
#pragma unroll
    for (int i = 0; i < 4; i++)
#pragma unroll
        for (int j = 0; j < 4; j++)
#pragma unroll
            for (int r = 0; r < 4; r++) acc[i][j][r] = 0.f;

    const int nt = Kd >> 4;

#pragma unroll
    for (int s = 0; s < 3; s++) {
        uint32_t off = (uint32_t)(s * G3_STG) * 4;
        int k0 = s * 16;
        asm volatile("cp.async.cg.shared.global [%0], [%1], 16, %2;"
                     :: "r"(sa + off), "l"(ga + k0), "r"(aval));
        asm volatile("cp.async.cg.shared.global [%0], [%1], 16, %2;"
                     :: "r"(sb + off), "l"(gb + (long long)k0 * ldb), "r"(bval));
        asm volatile("cp.async.commit_group;");
    }

    const int a_row = wm * 64 + (lane & 15);
    const int a_kw  = (lane >> 4) * 4;
    const uint32_t abase = smbase + (uint32_t)(a_row * 12 + a_kw) * 4;
    const uint32_t bbase = smbase + (uint32_t)G3_BOFF * 4 +
        (uint32_t)((lane & 15) * 272 + (wn * 32 + (lane >> 4) * 8) * 2);

    for (int kt = 0; kt < nt; kt++) {
        asm volatile("cp.async.wait_group 2;");
        __syncthreads();
        uint32_t soff = (uint32_t)((kt & 3) * G3_STG) * 4;

        uint32_t af[4][4], bf[2][4];
#pragma unroll
        for (int mt = 0; mt < 4; mt++)
            asm volatile("ldmatrix.sync.aligned.m8n8.x4.shared.b16 {%0,%1,%2,%3}, [%4];"
                         : "=r"(af[mt][0]), "=r"(af[mt][1]), "=r"(af[mt][2]), "=r"(af[mt][3])
                         : "r"(abase + soff + (uint32_t)(mt * 16 * 12) * 4));
#pragma unroll
        for (int ng = 0; ng < 2; ng++)
            asm volatile("ldmatrix.sync.aligned.m8n8.x4.trans.shared.b16 {%0,%1,%2,%3}, [%4];"
                         : "=r"(bf[ng][0]), "=r"(bf[ng][1]), "=r"(bf[ng][2]), "=r"(bf[ng][3])
                         : "r"(bbase + soff + (uint32_t)(ng * 32)));

#pragma unroll
        for (int mt = 0; mt < 4; mt++)
#pragma unroll
            for (int j = 0; j < 4; j++)
                mma_f16(acc[mt][j],
                        af[mt][0], af[mt][1], af[mt][2], af[mt][3],
                        bf[j >> 1][(j & 1) * 2], bf[j >> 1][(j & 1) * 2 + 1]);

        int ktn = kt + 3;
        if (ktn < nt) {
            uint32_t doff = (uint32_t)((ktn & 3) * G3_STG) * 4;
            int k0 = ktn * 16;
            asm volatile("cp.async.cg.shared.global [%0], [%1], 16, %2;"
                         :: "r"(sa + doff), "l"(ga + k0), "r"(aval));
            asm volatile("cp.async.cg.shared.global [%0], [%1], 16, %2;"
                         :: "r"(sb + doff), "l"(gb + (long long)k0 * ldb), "r"(bval));
        }
        asm volatile("cp.async.commit_group;");
    }

    float*  Cf = (float*)Cv;
    __half* Ch = (__half*)Cv;
#pragma unroll
    for (int mt = 0; mt < 4; mt++) {
#pragma unroll
        for (int hh = 0; hh < 2; hh++) {
            int r = brow + wm * 64 + mt * 16 + g + 8 * hh;
            if (r >= Md) continue;
#pragma unroll
            for (int j = 0; j < 4; j++) {
                int c = bcol + wn * 32 + j * 8 + 2 * q;
                if (c >= Nd) continue;
                float v0 = acc[mt][j][hh * 2];
                float v1 = acc[mt][j][hh * 2 + 1];
                v0 += bias[c]; v1 += bias[c + 1];
                if (EPI == EPI_BIAS_GELU) { v0 = gelu_tanh(v0); v1 = gelu_tanh(v1); }
                if (EPI == EPI_BIAS_RES)  {
                    v0 += Res[(long long)r * ldr + c];
                    v1 += Res[(long long)r * ldr + c + 1];
                }
                if (OUTH) {
                    __half2 hv = __floats2half2_rn(v0, v1);
                    *reinterpret_cast<__half2*>(Ch + (long long)r * ldc + c) = hv;
                } else {
                    *reinterpret_cast<float2*>(Cf + (long long)r * ldc + c) = make_float2(v0, v1);
                }
            }
        }
    }
}

// ---------------------------------------------------------------------------
// Fused flash attention v2: warp-row ownership, register P, 2 syncs/iter.
//   8 warps x 16 q-rows each; KV tiles of 64; hdim padded 72->80.
//   Qs [128 rows][44 words], Ks/Vs [64 rows][44 words] (natural [kv][hd]).
//   QK B: non-trans ldmatrix (verified recipe); PV B: trans ldmatrix (verified).
//   P: QK C-fragment == PV A-fragment (m16n8k16 identity) -> pure registers.
// ---------------------------------------------------------------------------
#define FROW 44      // words per smem row

__global__ void __launch_bounds__(256, 2)
flash_h(const __half* __restrict__ qkv, __half* __restrict__ attn)
{
    __shared__ uint32_t Qs[128 * FROW];
    __shared__ uint32_t Ks[64 * FROW];
    __shared__ uint32_t Vs[64 * FROW];

    int t = blockIdx.x;
    int head = blockIdx.y;
    int st, S, q0;
    if (t < 18)      { st = 0;    S = 2304; q0 = t * 128; }
    else if (t < 34) { st = 2304; S = 2048; q0 = (t - 18) * 128; }
    else if (t < 42) { st = 4352; S = 960;  q0 = (t - 34) * 128; }
    else             { st = 5312; S = 960;  q0 = (t - 42) * 128; }

    const int tid  = threadIdx.x;
    const int w    = tid >> 5;
    const int lane = tid & 31;
    const int g    = lane >> 2;
    const int q    = lane & 3;
    const int rowbase = w * 16;

    const float scale = 0.11785113019775793f;

    // ---- Q tile (9 x uint4 per row = 72 halfs); pad words 36..43 zeroed
    for (int s = tid; s < 128 * 9; s += 256) {
        int row = s / 9, c = s % 9;
        uint4 v = make_uint4(0, 0, 0, 0);
        if (q0 + row < S)
            v = *reinterpret_cast<const uint4*>(
                qkv + (size_t)(st + q0 + row) * QKVW + head * HDIM + c * 8);
        *reinterpret_cast<uint4*>(&Qs[row * FROW + c * 4]) = v;
    }
    for (int s = tid; s < 128 * 8; s += 256) Qs[(s >> 3) * FROW + 36 + (s & 7)] = 0;
    for (int s = tid; s < 64 * 8; s += 256) {
        Ks[(s >> 3) * FROW + 36 + (s & 7)] = 0;
        Vs[(s >> 3) * FROW + 36 + (s & 7)] = 0;
    }

    float m0 = -1e30f, m1 = -1e30f, l0 = 0.f, l1 = 0.f;
    float O[10][4];
#pragma unroll
    for (int i = 0; i < 10; i++)
#pragma unroll
        for (int r = 0; r < 4; r++) O[i][r] = 0.f;

    uint32_t smQ = (uint32_t)__cvta_generic_to_shared(Qs);
    uint32_t smK = (uint32_t)__cvta_generic_to_shared(Ks);
    uint32_t smV = (uint32_t)__cvta_generic_to_shared(Vs);
    // A (Q): row = rowbase + (lane&15), word = (lane>>4)*4  (+ 8/kstep)
    const uint32_t qsb = smQ + (uint32_t)((rowbase + (lane & 15)) * FROW + (lane >> 4) * 4) * 4;
    // B of QK (Ks non-trans): row = (lane&7) + ((lane>>4)<<3), word = ((lane>>3)&1)*4
    const uint32_t ksb = smK + (uint32_t)((((lane & 7) + ((lane >> 4) << 3)) * FROW) +
                                          ((lane >> 3) & 1) * 4) * 4;
    // B of PV (Vs trans): row = (lane&15), word = (lane>>4)*4
    const uint32_t vsb = smV + (uint32_t)(((lane & 15) * FROW) + (lane >> 4) * 4) * 4;

    const int nkv = S >> 6;
    for (int j = 0; j < nkv; j++) {
        __syncthreads();
        const int kv0 = j * 64;
        for (int s = tid; s < 64 * 9; s += 256) {
            int row = s / 9, c = s % 9;
            *reinterpret_cast<uint4*>(&Ks[row * FROW + c * 4]) =
                *reinterpret_cast<const uint4*>(
                    qkv + (size_t)(st + kv0 + row) * QKVW + DMODEL + head * HDIM + c * 8);
        }
        for (int s = tid; s < 64 * 9; s += 256) {
            int row = s / 9, c = s % 9;
            *reinterpret_cast<uint4*>(&Vs[row * FROW + c * 4]) =
                *reinterpret_cast<const uint4*>(
                    qkv + (size_t)(st + kv0 + row) * QKVW + 2 * DMODEL + head * HDIM + c * 8);
        }
        __syncthreads();

        // ---- S = scale * Q @ K^T : acc[8 n-tiles][4]
        float acc[8][4];
#pragma unroll
        for (int i = 0; i < 8; i++)
#pragma unroll
            for (int r = 0; r < 4; r++) acc[i][r] = 0.f;

#pragma unroll
        for (int kb = 0; kb < 5; kb++) {
            uint32_t af[4];
            asm volatile("ldmatrix.sync.aligned.m8n8.x4.shared.b16 {%0,%1,%2,%3}, [%4];"
                         : "=r"(af[0]), "=r"(af[1]), "=r"(af[2]), "=r"(af[3])
                         : "r"(qsb + (uint32_t)(kb * 8) * 4));
#pragma unroll
            for (int nt4 = 0; nt4 < 4; nt4++) {
                uint32_t bf[4];
                asm volatile("ldmatrix.sync.aligned.m8n8.x4.shared.b16 {%0,%1,%2,%3}, [%4];"
                             : "=r"(bf[0]), "=r"(bf[1]), "=r"(bf[2]), "=r"(bf[3])
                             : "r"(ksb + (uint32_t)(nt4 * 16 * FROW + kb * 8) * 4));
                mma_f16(acc[2 * nt4    ], af[0], af[1], af[2], af[3], bf[0], bf[1]);
                mma_f16(acc[2 * nt4 + 1], af[0], af[1], af[2], af[3], bf[2], bf[3]);
            }
        }
#pragma unroll
        for (int i = 0; i < 8; i++)
#pragma unroll
            for (int r = 0; r < 4; r++) acc[i][r] *= scale;

        // ---- online softmax (rows g / g+8, stats in registers)
        float mx0 = -1e30f, mx1 = -1e30f;
#pragma unroll
        for (int i = 0; i < 8; i++) {
            mx0 = fmaxf(mx0, fmaxf(acc[i][0], acc[i][1]));
            mx1 = fmaxf(mx1, fmaxf(acc[i][2], acc[i][3]));
        }
        mx0 = fmaxf(mx0, __shfl_xor_sync(0xffffffffu, mx0, 1));
        mx0 = fmaxf(mx0, __shfl_xor_sync(0xffffffffu, mx0, 2));
        mx1 = fmaxf(mx1, __shfl_xor_sync(0xffffffffu, mx1, 1));
        mx1 = fmaxf(mx1, __shfl_xor_sync(0xffffffffu, mx1, 2));
        float mn0 = fmaxf(m0, mx0), mn1 = fmaxf(m1, mx1);
        float al0 = __expf(m0 - mn0), al1 = __expf(m1 - mn1);
        m0 = mn0; m1 = mn1;

        float rs0 = 0.f, rs1 = 0.f;
#pragma unroll
        for (int i = 0; i < 8; i++) {
            acc[i][0] = __expf(acc[i][0] - mn0);
            acc[i][1] = __expf(acc[i][1] - mn0);
            acc[i][2] = __expf(acc[i][2] - mn1);
            acc[i][3] = __expf(acc[i][3] - mn1);
            rs0 += acc[i][0] + acc[i][1];
            rs1 += acc[i][2] + acc[i][3];
        }
        rs0 += __shfl_xor_sync(0xffffffffu, rs0, 1);
        rs0 += __shfl_xor_sync(0xffffffffu, rs0, 2);
        rs1 += __shfl_xor_sync(0xffffffffu, rs1, 1);
        rs1 += __shfl_xor_sync(0xffffffffu, rs1, 2);
        l0 = l0 * al0 + rs0;
        l1 = l1 * al1 + rs1;

#pragma unroll
        for (int i = 0; i < 10; i++) {
            O[i][0] *= al0; O[i][1] *= al0;
            O[i][2] *= al1; O[i][3] *= al1;
        }

        // ---- pack P into PV A-fragments (C-layout == A-layout identity)
        uint32_t pa[4][4];
#pragma unroll
        for (int kb = 0; kb < 4; kb++) {
            pa[kb][0] = pack_h2(acc[2 * kb][0],     acc[2 * kb][1]);
            pa[kb][1] = pack_h2(acc[2 * kb][2],     acc[2 * kb][3]);
            pa[kb][2] = pack_h2(acc[2 * kb + 1][0], acc[2 * kb + 1][1]);
            pa[kb][3] = pack_h2(acc[2 * kb + 1][2], acc[2 * kb + 1][3]);
        }

        // ---- O += P @ V
#pragma unroll
        for (int kb = 0; kb < 4; kb++) {
#pragma unroll
            for (int vt = 0; vt < 5; vt++) {
                uint32_t bf[4];
                asm volatile("ldmatrix.sync.aligned.m8n8.x4.trans.shared.b16 {%0,%1,%2,%3}, [%4];"
                             : "=r"(bf[0]), "=r"(bf[1]), "=r"(bf[2]), "=r"(bf[3])
                             : "r"(vsb + (uint32_t)(kb * 16 * FROW + vt * 8) * 4));
                mma_f16(O[2 * vt    ], pa[kb][0], pa[kb][1], pa[kb][2], pa[kb][3], bf[0], bf[1]);
                mma_f16(O[2 * vt + 1], pa[kb][0], pa[kb][1], pa[kb][2], pa[kb][3], bf[2], bf[3]);
            }
        }
    }

    // ---- epilogue: O / l -> attn
#pragma unroll
    for (int h = 0; h < 2; h++) {
        int r = rowbase + g + 8 * h;
        if (q0 + r >= S) continue;
        float inv = 1.0f / (h == 0 ? l0 : l1);
#pragma unroll
        for (int ntl = 0; ntl < 9; ntl++) {
            int c = ntl * 8 + 2 * q;          // < 72 always
            __half2 hv = __floats2half2_rn(O[ntl][2 * h] * inv, O[ntl][2 * h + 1] * inv);
            *reinterpret_cast<__half2*>(
                attn + (size_t)(st + q0 + r) * DMODEL + head * HDIM + c) = hv;
        }
    }
}

// ---------------------------------------------------------------------------
// Host launcher
// ---------------------------------------------------------------------------
#define SYMF(p, s) do { void* _t; cudaGetSymbolAddress(&_t, s); p = (float*)_t; } while (0)
#define SYMH(p, s) do { void* _t; cudaGetSymbolAddress(&_t, s); p = (__half*)_t; } while (0)

static inline dim3 ggrid3(int Md, int Nd) {
    return dim3((Nd + 127) / 128, (Md + 127) / 128);
}
static inline int cgrid4(long long n) {
    return (int)((n / 4 + 255) / 256);
}

extern "C" void kernel_launch(void* const* d_in, const int* in_sizes, int n_in,
                              void* d_out, int out_size)
{
    (void)in_sizes; (void)n_in; (void)out_size;
    const float* pixel    = (const float*)d_in[0];
    const float* patch_w  = (const float*)d_in[2];
    const float* patch_b  = (const float*)d_in[3];
    const float* pos_tab  = (const float*)d_in[4];
    const float* ln1_s    = (const float*)d_in[5];
    const float* ln1_b    = (const float*)d_in[6];
    const float* qkv_w    = (const float*)d_in[7];
    const float* qkv_b    = (const float*)d_in[8];
    const float* proj_w   = (const float*)d_in[9];
    const float* proj_b   = (const float*)d_in[10];
    const float* ln2_s    = (const float*)d_in[11];
    const float* ln2_b    = (const float*)d_in[12];
    const float* fc1_w    = (const float*)d_in[13];
    const float* fc1_b    = (const float*)d_in[14];
    const float* fc2_w    = (const float*)d_in[15];
    const float* fc2_b    = (const float*)d_in[16];
    const float* m_ln_s   = (const float*)d_in[17];
    const float* m_ln_b   = (const float*)d_in[18];
    const float* m_fc1_w  = (const float*)d_in[19];
    const float* m_fc1_b  = (const float*)d_in[20];
    const float* m_fc2_w  = (const float*)d_in[21];
    const float* m_fc2_b  = (const float*)d_in[22];
    float* out = (float*)d_out;

    float *x;
    __half *pix, *hh, *qkvh, *attnh, *mlph, *wt;
    SYMF(x, g_x);
    SYMH(pix, g_pix); SYMH(hh, g_hh); SYMH(qkvh, g_qkvh);
    SYMH(attnh, g_attnh); SYMH(mlph, g_mlph); SYMH(wt, g_wt);

    // ---- streaming fp32->fp16 weight conversion (no transpose)
    conv_h4<<<cgrid4((long long)NTOK * CIN), 256>>>(pixel, pix, NTOK * CIN / 4);
    conv_h4<<<cgrid4((long long)SZ_PATCH), 256>>>(patch_w, wt + OFF_PATCH, (int)(SZ_PATCH / 4));
    for (int l = 0; l < 2; l++) {
        conv_h4<<<cgrid4((long long)SZ_QKV), 256>>>(
            qkv_w + (size_t)l * SZ_QKV, wt + OFF_QKV + l * SZ_QKV, (int)(SZ_QKV / 4));
        conv_h4<<<cgrid4((long long)SZ_PROJ), 256>>>(
            proj_w + (size_t)l * SZ_PROJ, wt + OFF_PROJ + l * SZ_PROJ, (int)(SZ_PROJ / 4));
        conv_h4<<<cgrid4((long long)SZ_FC1), 256>>>(
            fc1_w + (size_t)l * SZ_FC1, wt + OFF_FC1 + l * SZ_FC1, (int)(SZ_FC1 / 4));
        conv_h4<<<cgrid4((long long)SZ_FC2), 256>>>(
            fc2_w + (size_t)l * SZ_FC2, wt + OFF_FC2 + l * SZ_FC2, (int)(SZ_FC2 / 4));
    }
    conv_h4<<<cgrid4((long long)SZ_MFC1), 256>>>(m_fc1_w, wt + OFF_MFC1, (int)(SZ_MFC1 / 4));
    conv_h4<<<cgrid4((long long)SZ_MFC2), 256>>>(m_fc2_w, wt + OFF_MFC2, (int)(SZ_MFC2 / 4));

    cossin_kernel<<<(NTOK * 36 + 255) / 256, 256>>>();

    // Patch embed -> x (fp32)
    gemm3<EPI_BIAS, false><<<ggrid3(NTOK, DMODEL), 256>>>(
        pix, CIN, wt + OFF_PATCH, DMODEL, x, DMODEL,
        patch_b, nullptr, 0, NTOK, DMODEL, CIN);

    posadd_kernel<<<NTOK, 288>>>(pos_tab);

    for (int l = 0; l < 2; l++) {
        ln_h<<<NTOK, 288>>>(x, hh, ln1_s + l * DMODEL, ln1_b + l * DMODEL);

        gemm3<EPI_BIAS, true><<<ggrid3(NTOK, QKVW), 256>>>(
            hh, DMODEL, wt + OFF_QKV + l * SZ_QKV, QKVW, qkvh, QKVW,
            qkv_b + (size_t)l * QKVW, nullptr, 0, NTOK, QKVW, DMODEL);

        rope_h<<<NTOK, 576>>>();

        flash_h<<<dim3(50, HEADS), 256>>>(qkvh, attnh);

        gemm3<EPI_BIAS_RES, false><<<ggrid3(NTOK, DMODEL), 256>>>(
            attnh, DMODEL, wt + OFF_PROJ + l * SZ_PROJ, DMODEL, x, DMODEL,
            proj_b + (size_t)l * DMODEL, x, DMODEL, NTOK, DMODEL, DMODEL);

        ln_h<<<NTOK, 288>>>(x, hh, ln2_s + l * DMODEL, ln2_b + l * DMODEL);

        gemm3<EPI_BIAS_GELU, true><<<ggrid3(NTOK, IDIM), 256>>>(
            hh, DMODEL, wt + OFF_FC1 + l * SZ_FC1, IDIM, mlph, IDIM,
            fc1_b + (size_t)l * IDIM, nullptr, 0, NTOK, IDIM, DMODEL);

        gemm3<EPI_BIAS_RES, false><<<ggrid3(NTOK, DMODEL), 256>>>(
            mlph, IDIM, wt + OFF_FC2 + l * SZ_FC2, DMODEL, x, DMODEL,
            fc2_b + (size_t)l * DMODEL, x, DMODEL, NTOK, DMODEL, IDIM);
    }

    // merger
    ln_h<<<NTOK, 288>>>(x, hh, m_ln_s, m_ln_b);   // hh viewed as [1568][4608]

    gemm3<EPI_BIAS_GELU, true><<<ggrid3(MROWS, MD4), 256>>>(
        hh, MD4, wt + OFF_MFC1, MD4, mlph, MD4,
        m_fc1_b, nullptr, 0, MROWS, MD4, MD4);

    gemm3<EPI_BIAS, false><<<ggrid3(MROWS, DOUT), 256>>>(
        mlph, MD4, wt + OFF_MFC2, DOUT, out, DOUT,
        m_fc2_b, nullptr, 0, MROWS, DOUT, MD4);
}

// round 12
// speedup vs baseline: 1.7875x; 1.0312x over previous
#include <cuda_runtime.h>
#include <cuda_fp16.h>
#include <math.h>
#include <stdint.h>

// ---------------------------------------------------------------------------
// Problem constants (GRID fixed: [[1,48,48],[1,32,64],[2,24,40]])
// ---------------------------------------------------------------------------
#define NTOK    6272
#define DMODEL  1152
#define HEADS   16
#define HDIM    72
#define IDIM    4304
#define DOUT    2048
#define MROWS   1568
#define MD4     4608
#define QKVW    3456
#define CIN     1536

// ---------------------------------------------------------------------------
// Scratch buffers
// ---------------------------------------------------------------------------
__device__ float  g_x    [NTOK * DMODEL];        // residual (fp32)
__device__ __half g_pix  [NTOK * CIN];           // pixel fp16
__device__ __half g_hh   [NTOK * DMODEL];        // LN out fp16
__device__ __half g_qkvh [NTOK * QKVW];          // qkv fp16
__device__ __half g_attnh[NTOK * DMODEL];        // attn out fp16
__device__ __half g_mlph [NTOK * IDIM];          // mlp hidden fp16
__device__ float  g_cos  [NTOK * 36];
__device__ float  g_sin  [NTOK * 36];

// fp16 weights, natural [K,N] layout (no transpose)
#define SZ_PATCH (1536ULL * 1152)
#define SZ_QKV   (1152ULL * 3456)
#define SZ_PROJ  (1152ULL * 1152)
#define SZ_FC1   (1152ULL * 4304)
#define SZ_FC2   (4304ULL * 1152)
#define SZ_MFC1  (4608ULL * 4608)
#define SZ_MFC2  (4608ULL * 2048)
#define OFF_PATCH 0ULL
#define OFF_QKV   (OFF_PATCH + SZ_PATCH)
#define OFF_PROJ  (OFF_QKV + 2 * SZ_QKV)
#define OFF_FC1   (OFF_PROJ + 2 * SZ_PROJ)
#define OFF_FC2   (OFF_FC1 + 2 * SZ_FC1)
#define OFF_MFC1  (OFF_FC2 + 2 * SZ_FC2)
#define OFF_MFC2  (OFF_MFC1 + SZ_MFC1)
#define WT_TOTAL  (OFF_MFC2 + SZ_MFC2)
__device__ __half g_wt[WT_TOTAL];

// ---------------------------------------------------------------------------
__device__ __forceinline__ void token_pos(int n, int& row, int& col, int& ih, int& iw)
{
    int local, h, w;
    if (n < 2304)      { local = n;          h = 48; w = 48; }
    else if (n < 4352) { local = n - 2304;   h = 32; w = 64; }
    else               { local = n - 4352;   h = 24; w = 40; }
    int rem = local % (h * w);
    int wb_cnt = w >> 1;
    int blk = rem >> 2, within = rem & 3;
    int hb = blk / wb_cnt, wb = blk % wb_cnt;
    row = hb * 2 + (within >> 1);
    col = wb * 2 + (within & 1);
    ih = h; iw = w;
}

__global__ void cossin_kernel()
{
    int idx = blockIdx.x * blockDim.x + threadIdx.x;
    if (idx >= NTOK * 36) return;
    int n = idx / 36, d = idx % 36;
    int row, col, ih, iw;
    token_pos(n, row, col, ih, iw);
    int j = (d < 18) ? d : d - 18;
    double p = (d < 18) ? (double)row : (double)col;
    double inv = 1.0 / pow(10000.0, (2.0 * (double)j) / 36.0);
    double ang = p * inv;
    g_cos[idx] = (float)cos(ang);
    g_sin[idx] = (float)sin(ang);
}

__global__ void posadd_kernel(const float* __restrict__ pos_table)
{
    int n = blockIdx.x;
    int row, col, ih, iw;
    token_pos(n, row, col, ih, iw);
    double hi = 47.0 * (double)row / (double)(ih - 1);
    double wi = 47.0 * (double)col / (double)(iw - 1);
    int hf = (int)floor(hi), wf = (int)floor(wi);
    float dh = (float)(hi - (double)hf), dw = (float)(wi - (double)wf);
    int hc = min(hf + 1, 47), wc = min(wf + 1, 47);
    float w00 = (1.f - dh) * (1.f - dw);
    float w01 = (1.f - dh) * dw;
    float w10 = dh * (1.f - dw);
    float w11 = dh * dw;
    const float* p00 = pos_table + (size_t)(hf * 48 + wf) * DMODEL;
    const float* p01 = pos_table + (size_t)(hf * 48 + wc) * DMODEL;
    const float* p10 = pos_table + (size_t)(hc * 48 + wf) * DMODEL;
    const float* p11 = pos_table + (size_t)(hc * 48 + wc) * DMODEL;
    float* xr = g_x + (size_t)n * DMODEL;
    for (int d = threadIdx.x; d < DMODEL; d += blockDim.x)
        xr[d] += p00[d] * w00 + p01[d] * w01 + p10[d] * w10 + p11[d] * w11;
}

// fp32 -> fp16 streaming convert, 4 coalesced float4s per thread (MLP=4)
__global__ void conv4x(const float* __restrict__ in, __half* __restrict__ out, int n4)
{
    int base = blockIdx.x * (blockDim.x * 4) + threadIdx.x;
    float4 v[4];
    int   ok[4];
#pragma unroll
    for (int k = 0; k < 4; k++) {
        int i = base + k * blockDim.x;
        ok[k] = (i < n4);
        if (ok[k]) v[k] = reinterpret_cast<const float4*>(in)[i];
    }
#pragma unroll
    for (int k = 0; k < 4; k++) {
        int i = base + k * blockDim.x;
        if (ok[k]) {
            __half2 lo = __floats2half2_rn(v[k].x, v[k].y);
            __half2 hi = __floats2half2_rn(v[k].z, v[k].w);
            reinterpret_cast<uint2*>(out)[i] =
                make_uint2(*reinterpret_cast<uint32_t*>(&lo), *reinterpret_cast<uint32_t*>(&hi));
        }
    }
}

__device__ __forceinline__ float warp_sum(float v)
{
#pragma unroll
    for (int o = 16; o > 0; o >>= 1) v += __shfl_xor_sync(0xffffffffu, v, o);
    return v;
}

// LayerNorm fp32 in -> fp16 out
__global__ void ln_h(const float* __restrict__ in, __half* __restrict__ out,
                     const float* __restrict__ s, const float* __restrict__ b)
{
    __shared__ float sh[9];
    __shared__ float stat[2];
    int n = blockIdx.x;
    const float* xr = in + (size_t)n * DMODEL;
    int t = threadIdx.x, wid = t >> 5, lane = t & 31;

    float vals[4];
    float lsum = 0.f;
#pragma unroll
    for (int i = 0; i < 4; i++) { vals[i] = xr[t + i * 288]; lsum += vals[i]; }
    float ws = warp_sum(lsum);
    if (lane == 0) sh[wid] = ws;
    __syncthreads();
    if (t == 0) {
        float tot = 0.f;
#pragma unroll
        for (int i = 0; i < 9; i++) tot += sh[i];
        stat[0] = tot * (1.0f / DMODEL);
    }
    __syncthreads();
    float mu = stat[0];
    float lvar = 0.f;
#pragma unroll
    for (int i = 0; i < 4; i++) { float d = vals[i] - mu; lvar += d * d; }
    ws = warp_sum(lvar);
    __syncthreads();
    if (lane == 0) sh[wid] = ws;
    __syncthreads();
    if (t == 0) {
        float tot = 0.f;
#pragma unroll
        for (int i = 0; i < 9; i++) tot += sh[i];
        stat[1] = rsqrtf(tot * (1.0f / DMODEL) + 1e-6f);
    }
    __syncthreads();
    float r = stat[1];
    __half* orow = out + (size_t)n * DMODEL;
#pragma unroll
    for (int i = 0; i < 4; i++) {
        int d = t + i * 288;
        orow[d] = __float2half_rn((vals[i] - mu) * r * s[d] + b[d]);
    }
}

// RoPE in-place on fp16 qkv
__global__ void rope_h()
{
    int n = blockIdx.x;
    int t = threadIdx.x;
    int h = t / 36, d = t % 36;
    float c = g_cos[n * 36 + d];
    float s = g_sin[n * 36 + d];
    __half* q = g_qkvh + (size_t)n * QKVW + h * HDIM;
    __half* k = q + DMODEL;
    float q0 = __half2float(q[d]), q1 = __half2float(q[d + 36]);
    q[d]      = __float2half_rn(q0 * c - q1 * s);
    q[d + 36] = __float2half_rn(q1 * c + q0 * s);
    float k0 = __half2float(k[d]), k1 = __half2float(k[d + 36]);
    k[d]      = __float2half_rn(k0 * c - k1 * s);
    k[d + 36] = __float2half_rn(k1 * c + k0 * s);
}

// ---------------------------------------------------------------------------
// mma / misc helpers
// ---------------------------------------------------------------------------
__device__ __forceinline__ void mma_f16(float c[4],
                                        uint32_t a0, uint32_t a1, uint32_t a2, uint32_t a3,
                                        uint32_t b0, uint32_t b1)
{
    asm volatile(
        "mma.sync.aligned.m16n8k16.row.col.f32.f16.f16.f32 "
        "{%0,%1,%2,%3}, {%4,%5,%6,%7}, {%8,%9}, {%0,%1,%2,%3};\n"
        : "+f"(c[0]), "+f"(c[1]), "+f"(c[2]), "+f"(c[3])
        : "r"(a0), "r"(a1), "r"(a2), "r"(a3), "r"(b0), "r"(b1));
}

// fast gelu: HW tanh approx (MUFU.TANH)
__device__ __forceinline__ float gelu_tanh(float x)
{
    float u = 0.7978845608028654f * (x + 0.044715f * x * x * x);
    float t;
    asm("tanh.approx.f32 %0, %1;" : "=f"(t) : "f"(u));
    return 0.5f * x * (1.f + t);
}

__device__ __forceinline__ uint32_t pack_h2(float lo, float hi)
{
    __half2 h = __floats2half2_rn(lo, hi);
    return *reinterpret_cast<uint32_t*>(&h);
}

// ---------------------------------------------------------------------------
// GEMM v4: A fp16 [M,K] row-major, B fp16 [K,N] row-major, C fp32 or fp16.
//   Block 128x128, BK=32, 3 stages (dynamic smem), cp.async.
//   8 warps 2(M) x 4(N), warp tile 64x32.
//   A rows padded to 40 halfs (20 words): ldmatrix phases bank-disjoint
//     (20r mod 32 = {0,20,8,28,16,4,24,12}).
//   B [32 k][128 n] rows padded to 136 halfs (68 words): trans phases 4k+c.
//   Stage: A 2560 w + B 2176 w = 4736 w.  3 stages = 56832 B.
// ---------------------------------------------------------------------------
#define EPI_BIAS      1
#define EPI_BIAS_GELU 2
#define EPI_BIAS_RES  3

#define G4_AST  20              // A row stride (words)
#define G4_BST  68              // B row stride (words)
#define G4_BOFF 2560            // B offset within stage (words)
#define G4_STG  4736            // words per stage
#define G4_SMEM (3 * G4_STG * 4)

template<int EPI, bool OUTH>
__global__ void __launch_bounds__(256, 2)
gemm3(const __half* __restrict__ A, int lda,
      const __half* __restrict__ B, int ldb,
      void* __restrict__ Cv, int ldc,
      const float* __restrict__ bias,
      const float* __restrict__ Res, int ldr,
      int Md, int Nd, int Kd)
{
    extern __shared__ uint32_t smbuf[];

    const int tid  = threadIdx.x;
    const int brow = blockIdx.y * 128;
    const int bcol = blockIdx.x * 128;
    const int w    = tid >> 5;
    const int lane = tid & 31;
    const int g    = lane >> 2;
    const int q    = lane & 3;
    const int wm   = w & 1;
    const int wn   = w >> 1;

    uint32_t smbase = (uint32_t)__cvta_generic_to_shared(smbuf);

    // A loader: 2 chunks/thread/stage.  c = tid + i*256; row = c>>2; k8 = (c&3)*8
    int aok[2], ak8[2];
    uint32_t sa[2];
    const __half* ga[2];
#pragma unroll
    for (int i = 0; i < 2; i++) {
        int c = tid + i * 256;
        int row = c >> 2;
        ak8[i] = (c & 3) * 8;
        aok[i] = (brow + row) < Md;
        sa[i] = smbase + (uint32_t)(row * G4_AST + (c & 3) * 4) * 4;
        ga[i] = A + (long long)(brow + row) * lda + ak8[i];
    }
    // B loader: 2 chunks/thread/stage.  c = tid + i*256; krow = c>>4; n8 = (c&15)*8
    int bkr[2], bok[2];
    uint32_t sb[2];
    const __half* gb[2];
#pragma unroll
    for (int i = 0; i < 2; i++) {
        int c = tid + i * 256;
        bkr[i] = c >> 4;
        int n8 = (c & 15) * 8;
        bok[i] = (bcol + n8) < Nd;
        sb[i] = smbase + (uint32_t)(G4_BOFF + bkr[i] * G4_BST + (c & 15) * 4) * 4;
        gb[i] = B + (long long)bkr[i] * ldb + bcol + n8;
    }

    float acc[4][4][4];
#pragma unroll
    for (int i = 0; i < 4; i++)
#pragma unroll
        for (int j = 0; j < 4; j++)
#pragma unroll
            for (int r = 0; r < 4; r++) acc[i][j][r] = 0.f;

    const int ntk = (Kd + 31) >> 5;

    // stage loader
    auto load_stage = [&](int k0, int st) {
        uint32_t off = (uint32_t)(st * G4_STG) * 4;
#pragma unroll
        for (int i = 0; i < 2; i++) {
            int va = (aok[i] && (k0 + ak8[i]) < Kd) ? 16 : 0;
            asm volatile("cp.async.cg.shared.global [%0], [%1], 16, %2;"
                         :: "r"(sa[i] + off), "l"(ga[i] + k0), "r"(va));
        }
#pragma unroll
        for (int i = 0; i < 2; i++) {
            int vb = (bok[i] && (k0 + bkr[i]) < Kd) ? 16 : 0;
            asm volatile("cp.async.cg.shared.global [%0], [%1], 16, %2;"
                         :: "r"(sb[i] + off), "l"(gb[i] + (long long)k0 * ldb), "r"(vb));
        }
    };

    load_stage(0, 0);
    asm volatile("cp.async.commit_group;");
    if (ntk > 1) load_stage(32, 1);
    asm volatile("cp.async.commit_group;");

    // ldmatrix addressing
    const int a_row = wm * 64 + (lane & 15);
    const uint32_t abase = smbase + (uint32_t)(a_row * G4_AST + (lane >> 4) * 4) * 4;
    const uint32_t bbase = smbase + (uint32_t)G4_BOFF * 4 +
        (uint32_t)((lane & 15) * G4_BST * 4 + (wn * 32 + (lane >> 4) * 8) * 2);

    for (int kt = 0; kt < ntk; kt++) {
        asm volatile("cp.async.wait_group 1;");
        __syncthreads();
        uint32_t soff = (uint32_t)((kt % 3) * G4_STG) * 4;

#pragma unroll
        for (int kg = 0; kg < 2; kg++) {
            uint32_t akg = soff + (uint32_t)(kg * 8) * 4;            // +8 words
            uint32_t bkg = soff + (uint32_t)(kg * 16 * G4_BST) * 4;  // +16 rows

            uint32_t af[4][4], bf[2][4];
#pragma unroll
            for (int mt = 0; mt < 4; mt++)
                asm volatile("ldmatrix.sync.aligned.m8n8.x4.shared.b16 {%0,%1,%2,%3}, [%4];"
                             : "=r"(af[mt][0]), "=r"(af[mt][1]), "=r"(af[mt][2]), "=r"(af[mt][3])
                             : "r"(abase + akg + (uint32_t)(mt * 16 * G4_AST) * 4));
#pragma unroll
            for (int ng = 0; ng < 2; ng++)
                asm volatile("ldmatrix.sync.aligned.m8n8.x4.trans.shared.b16 {%0,%1,%2,%3}, [%4];"
                             : "=r"(bf[ng][0]), "=r"(bf[ng][1]), "=r"(bf[ng][2]), "=r"(bf[ng][3])
                             : "r"(bbase + bkg + (uint32_t)(ng * 32)));

#pragma unroll
            for (int mt = 0; mt < 4; mt++)
#pragma unroll
                for (int j = 0; j < 4; j++)
                    mma_f16(acc[mt][j],
                            af[mt][0], af[mt][1], af[mt][2], af[mt][3],
                            bf[j >> 1][(j & 1) * 2], bf[j >> 1][(j & 1) * 2 + 1]);
        }

        int ktn = kt + 2;
        if (ktn < ntk)
            load_stage(ktn * 32, ktn % 3);
        asm volatile("cp.async.commit_group;");
    }

    // epilogue (Nd is even; c always even -> pair stores safe)
    float*  Cf = (float*)Cv;
    __half* Ch = (__half*)Cv;
#pragma unroll
    for (int mt = 0; mt < 4; mt++) {
#pragma unroll
        for (int hh = 0; hh < 2; hh++) {
            int r = brow + wm * 64 + mt * 16 + g + 8 * hh;
            if (r >= Md) continue;
#pragma unroll
            for (int j = 0; j < 4; j++) {
                int c = bcol + wn * 32 + j * 8 + 2 * q;
                if (c >= Nd) continue;
                float v0 = acc[mt][j][hh * 2];
                float v1 = acc[mt][j][hh * 2 + 1];
                v0 += bias[c]; v1 += bias[c + 1];
                if (EPI == EPI_BIAS_GELU) { v0 = gelu_tanh(v0); v1 = gelu_tanh(v1); }
                if (EPI == EPI_BIAS_RES)  {
                    v0 += Res[(long long)r * ldr + c];
                    v1 += Res[(long long)r * ldr + c + 1];
                }
                if (OUTH) {
                    __half2 hv = __floats2half2_rn(v0, v1);
                    *reinterpret_cast<__half2*>(Ch + (long long)r * ldc + c) = hv;
                } else {
                    *reinterpret_cast<float2*>(Cf + (long long)r * ldc + c) = make_float2(v0, v1);
                }
            }
        }
    }
}

// ---------------------------------------------------------------------------
// Fused flash attention v2 (unchanged from R11 — verified).
// ---------------------------------------------------------------------------
#define FROW 44

__global__ void __launch_bounds__(256, 2)
flash_h(const __half* __restrict__ qkv, __half* __restrict__ attn)
{
    __shared__ uint32_t Qs[128 * FROW];
    __shared__ uint32_t Ks[64 * FROW];
    __shared__ uint32_t Vs[64 * FROW];

    int t = blockIdx.x;
    int head = blockIdx.y;
    int st, S, q0;
    if (t < 18)      { st = 0;    S = 2304; q0 = t * 128; }
    else if (t < 34) { st = 2304; S = 2048; q0 = (t - 18) * 128; }
    else if (t < 42) { st = 4352; S = 960;  q0 = (t - 34) * 128; }
    else             { st = 5312; S = 960;  q0 = (t - 42) * 128; }

    const int tid  = threadIdx.x;
    const int w    = tid >> 5;
    const int lane = tid & 31;
    const int g    = lane >> 2;
    const int q    = lane & 3;
    const int rowbase = w * 16;

    const float scale = 0.11785113019775793f;

    for (int s = tid; s < 128 * 9; s += 256) {
        int row = s / 9, c = s % 9;
        uint4 v = make_uint4(0, 0, 0, 0);
        if (q0 + row < S)
            v = *reinterpret_cast<const uint4*>(
                qkv + (size_t)(st + q0 + row) * QKVW + head * HDIM + c * 8);
        *reinterpret_cast<uint4*>(&Qs[row * FROW + c * 4]) = v;
    }
    for (int s = tid; s < 128 * 8; s += 256) Qs[(s >> 3) * FROW + 36 + (s & 7)] = 0;
    for (int s = tid; s < 64 * 8; s += 256) {
        Ks[(s >> 3) * FROW + 36 + (s & 7)] = 0;
        Vs[(s >> 3) * FROW + 36 + (s & 7)] = 0;
    }

    float m0 = -1e30f, m1 = -1e30f, l0 = 0.f, l1 = 0.f;
    float O[10][4];
#pragma unroll
    for (int i = 0; i < 10; i++)
#pragma unroll
        for (int r = 0; r < 4; r++) O[i][r] = 0.f;

    uint32_t smQ = (uint32_t)__cvta_generic_to_shared(Qs);
    uint32_t smK = (uint32_t)__cvta_generic_to_shared(Ks);
    uint32_t smV = (uint32_t)__cvta_generic_to_shared(Vs);
    const uint32_t qsb = smQ + (uint32_t)((rowbase + (lane & 15)) * FROW + (lane >> 4) * 4) * 4;
    const uint32_t ksb = smK + (uint32_t)((((lane & 7) + ((lane >> 4) << 3)) * FROW) +
                                          ((lane >> 3) & 1) * 4) * 4;
    const uint32_t vsb = smV + (uint32_t)(((lane & 15) * FROW) + (lane >> 4) * 4) * 4;

    const int nkv = S >> 6;
    for (int j = 0; j < nkv; j++) {
        __syncthreads();
        const int kv0 = j * 64;
        for (int s = tid; s < 64 * 9; s += 256) {
            int row = s / 9, c = s % 9;
            *reinterpret_cast<uint4*>(&Ks[row * FROW + c * 4]) =
                *reinterpret_cast<const uint4*>(
                    qkv + (size_t)(st + kv0 + row) * QKVW + DMODEL + head * HDIM + c * 8);
        }
        for (int s = tid; s < 64 * 9; s += 256) {
            int row = s / 9, c = s % 9;
            *reinterpret_cast<uint4*>(&Vs[row * FROW + c * 4]) =
                *reinterpret_cast<const uint4*>(
                    qkv + (size_t)(st + kv0 + row) * QKVW + 2 * DMODEL + head * HDIM + c * 8);
        }
        __syncthreads();

        float acc[8][4];
#pragma unroll
        for (int i = 0; i < 8; i++)
#pragma unroll
            for (int r = 0; r < 4; r++) acc[i][r] = 0.f;

#pragma unroll
        for (int kb = 0; kb < 5; kb++) {
            uint32_t af[4];
            asm volatile("ldmatrix.sync.aligned.m8n8.x4.shared.b16 {%0,%1,%2,%3}, [%4];"
                         : "=r"(af[0]), "=r"(af[1]), "=r"(af[2]), "=r"(af[3])
                         : "r"(qsb + (uint32_t)(kb * 8) * 4));
#pragma unroll
            for (int nt4 = 0; nt4 < 4; nt4++) {
                uint32_t bf[4];
                asm volatile("ldmatrix.sync.aligned.m8n8.x4.shared.b16 {%0,%1,%2,%3}, [%4];"
                             : "=r"(bf[0]), "=r"(bf[1]), "=r"(bf[2]), "=r"(bf[3])
                             : "r"(ksb + (uint32_t)(nt4 * 16 * FROW + kb * 8) * 4));
                mma_f16(acc[2 * nt4    ], af[0], af[1], af[2], af[3], bf[0], bf[1]);
                mma_f16(acc[2 * nt4 + 1], af[0], af[1], af[2], af[3], bf[2], bf[3]);
            }
        }
#pragma unroll
        for (int i = 0; i < 8; i++)
#pragma unroll
            for (int r = 0; r < 4; r++) acc[i][r] *= scale;

        float mx0 = -1e30f, mx1 = -1e30f;
#pragma unroll
        for (int i = 0; i < 8; i++) {
            mx0 = fmaxf(mx0, fmaxf(acc[i][0], acc[i][1]));
            mx1 = fmaxf(mx1, fmaxf(acc[i][2], acc[i][3]));
        }
        mx0 = fmaxf(mx0, __shfl_xor_sync(0xffffffffu, mx0, 1));
        mx0 = fmaxf(mx0, __shfl_xor_sync(0xffffffffu, mx0, 2));
        mx1 = fmaxf(mx1, __shfl_xor_sync(0xffffffffu, mx1, 1));
        mx1 = fmaxf(mx1, __shfl_xor_sync(0xffffffffu, mx1, 2));
        float mn0 = fmaxf(m0, mx0), mn1 = fmaxf(m1, mx1);
        float al0 = __expf(m0 - mn0), al1 = __expf(m1 - mn1);
        m0 = mn0; m1 = mn1;

        float rs0 = 0.f, rs1 = 0.f;
#pragma unroll
        for (int i = 0; i < 8; i++) {
            acc[i][0] = __expf(acc[i][0] - mn0);
            acc[i][1] = __expf(acc[i][1] - mn0);
            acc[i][2] = __expf(acc[i][2] - mn1);
            acc[i][3] = __expf(acc[i][3] - mn1);
            rs0 += acc[i][0] + acc[i][1];
            rs1 += acc[i][2] + acc[i][3];
        }
        rs0 += __shfl_xor_sync(0xffffffffu, rs0, 1);
        rs0 += __shfl_xor_sync(0xffffffffu, rs0, 2);
        rs1 += __shfl_xor_sync(0xffffffffu, rs1, 1);
        rs1 += __shfl_xor_sync(0xffffffffu, rs1, 2);
        l0 = l0 * al0 + rs0;
        l1 = l1 * al1 + rs1;

#pragma unroll
        for (int i = 0; i < 10; i++) {
            O[i][0] *= al0; O[i][1] *= al0;
            O[i][2] *= al1; O[i][3] *= al1;
        }

        uint32_t pa[4][4];
#pragma unroll
        for (int kb = 0; kb < 4; kb++) {
            pa[kb][0] = pack_h2(acc[2 * kb][0],     acc[2 * kb][1]);
            pa[kb][1] = pack_h2(acc[2 * kb][2],     acc[2 * kb][3]);
            pa[kb][2] = pack_h2(acc[2 * kb + 1][0], acc[2 * kb + 1][1]);
            pa[kb][3] = pack_h2(acc[2 * kb + 1][2], acc[2 * kb + 1][3]);
        }

#pragma unroll
        for (int kb = 0; kb < 4; kb++) {
#pragma unroll
            for (int vt = 0; vt < 5; vt++) {
                uint32_t bf[4];
                asm volatile("ldmatrix.sync.aligned.m8n8.x4.trans.shared.b16 {%0,%1,%2,%3}, [%4];"
                             : "=r"(bf[0]), "=r"(bf[1]), "=r"(bf[2]), "=r"(bf[3])
                             : "r"(vsb + (uint32_t)(kb * 16 * FROW + vt * 8) * 4));
                mma_f16(O[2 * vt    ], pa[kb][0], pa[kb][1], pa[kb][2], pa[kb][3], bf[0], bf[1]);
                mma_f16(O[2 * vt + 1], pa[kb][0], pa[kb][1], pa[kb][2], pa[kb][3], bf[2], bf[3]);
            }
        }
    }

#pragma unroll
    for (int h = 0; h < 2; h++) {
        int r = rowbase + g + 8 * h;
        if (q0 + r >= S) continue;
        float inv = 1.0f / (h == 0 ? l0 : l1);
#pragma unroll
        for (int ntl = 0; ntl < 9; ntl++) {
            int c = ntl * 8 + 2 * q;
            __half2 hv = __floats2half2_rn(O[ntl][2 * h] * inv, O[ntl][2 * h + 1] * inv);
            *reinterpret_cast<__half2*>(
                attn + (size_t)(st + q0 + r) * DMODEL + head * HDIM + c) = hv;
        }
    }
}

// ---------------------------------------------------------------------------
// Host launcher
// ---------------------------------------------------------------------------
#define SYMF(p, s) do { void* _t; cudaGetSymbolAddress(&_t, s); p = (float*)_t; } while (0)
#define SYMH(p, s) do { void* _t; cudaGetSymbolAddress(&_t, s); p = (__half*)_t; } while (0)

static inline dim3 ggrid3(int Md, int Nd) {
    return dim3((Nd + 127) / 128, (Md + 127) / 128);
}
static inline int cgrid16(long long n) {        // n elems; 16 per thread
    return (int)((n / 4 + 1023) / 1024);
}

extern "C" void kernel_launch(void* const* d_in, const int* in_sizes, int n_in,
                              void* d_out, int out_size)
{
    (void)in_sizes; (void)n_in; (void)out_size;
    const float* pixel    = (const float*)d_in[0];
    const float* patch_w  = (const float*)d_in[2];
    const float* patch_b  = (const float*)d_in[3];
    const float* pos_tab  = (const float*)d_in[4];
    const float* ln1_s    = (const float*)d_in[5];
    const float* ln1_b    = (const float*)d_in[6];
    const float* qkv_w    = (const float*)d_in[7];
    const float* qkv_b    = (const float*)d_in[8];
    const float* proj_w   = (const float*)d_in[9];
    const float* proj_b   = (const float*)d_in[10];
    const float* ln2_s    = (const float*)d_in[11];
    const float* ln2_b    = (const float*)d_in[12];
    const float* fc1_w    = (const float*)d_in[13];
    const float* fc1_b    = (const float*)d_in[14];
    const float* fc2_w    = (const float*)d_in[15];
    const float* fc2_b    = (const float*)d_in[16];
    const float* m_ln_s   = (const float*)d_in[17];
    const float* m_ln_b   = (const float*)d_in[18];
    const float* m_fc1_w  = (const float*)d_in[19];
    const float* m_fc1_b  = (const float*)d_in[20];
    const float* m_fc2_w  = (const float*)d_in[21];
    const float* m_fc2_b  = (const float*)d_in[22];
    float* out = (float*)d_out;

    float *x;
    __half *pix, *hh, *qkvh, *attnh, *mlph, *wt;
    SYMF(x, g_x);
    SYMH(pix, g_pix); SYMH(hh, g_hh); SYMH(qkvh, g_qkvh);
    SYMH(attnh, g_attnh); SYMH(mlph, g_mlph); SYMH(wt, g_wt);

    static bool attr_set = false;
    if (!attr_set) {
        cudaFuncSetAttribute(gemm3<EPI_BIAS, false>,
                             cudaFuncAttributeMaxDynamicSharedMemorySize, G4_SMEM);
        cudaFuncSetAttribute(gemm3<EPI_BIAS, true>,
                             cudaFuncAttributeMaxDynamicSharedMemorySize, G4_SMEM);
        cudaFuncSetAttribute(gemm3<EPI_BIAS_GELU, true>,
                             cudaFuncAttributeMaxDynamicSharedMemorySize, G4_SMEM);
        cudaFuncSetAttribute(gemm3<EPI_BIAS_RES, false>,
                             cudaFuncAttributeMaxDynamicSharedMemorySize, G4_SMEM);
        attr_set = true;
    }

    // ---- streaming fp32->fp16 conversion (no transpose), MLP=4
    conv4x<<<cgrid16((long long)NTOK * CIN), 256>>>(pixel, pix, NTOK * CIN / 4);
    conv4x<<<cgrid16((long long)SZ_PATCH), 256>>>(patch_w, wt + OFF_PATCH, (int)(SZ_PATCH / 4));
    for (int l = 0; l < 2; l++) {
        conv4x<<<cgrid16((long long)SZ_QKV), 256>>>(
            qkv_w + (size_t)l * SZ_QKV, wt + OFF_QKV + l * SZ_QKV, (int)(SZ_QKV / 4));
        conv4x<<<cgrid16((long long)SZ_PROJ), 256>>>(
            proj_w + (size_t)l * SZ_PROJ, wt + OFF_PROJ + l * SZ_PROJ, (int)(SZ_PROJ / 4));
        conv4x<<<cgrid16((long long)SZ_FC1), 256>>>(
            fc1_w + (size_t)l * SZ_FC1, wt + OFF_FC1 + l * SZ_FC1, (int)(SZ_FC1 / 4));
        conv4x<<<cgrid16((long long)SZ_FC2), 256>>>(
            fc2_w + (size_t)l * SZ_FC2, wt + OFF_FC2 + l * SZ_FC2, (int)(SZ_FC2 / 4));
    }
    conv4x<<<cgrid16((long long)SZ_MFC1), 256>>>(m_fc1_w, wt + OFF_MFC1, (int)(SZ_MFC1 / 4));
    conv4x<<<cgrid16((long long)SZ_MFC2), 256>>>(m_fc2_w, wt + OFF_MFC2, (int)(SZ_MFC2 / 4));

    cossin_kernel<<<(NTOK * 36 + 255) / 256, 256>>>();

    // Patch embed -> x (fp32)
    gemm3<EPI_BIAS, false><<<ggrid3(NTOK, DMODEL), 256, G4_SMEM>>>(
        pix, CIN, wt + OFF_PATCH, DMODEL, x, DMODEL,
        patch_b, nullptr, 0, NTOK, DMODEL, CIN);

    posadd_kernel<<<NTOK, 288>>>(pos_tab);

    for (int l = 0; l < 2; l++) {
        ln_h<<<NTOK, 288>>>(x, hh, ln1_s + l * DMODEL, ln1_b + l * DMODEL);

        gemm3<EPI_BIAS, true><<<ggrid3(NTOK, QKVW), 256, G4_SMEM>>>(
            hh, DMODEL, wt + OFF_QKV + l * SZ_QKV, QKVW, qkvh, QKVW,
            qkv_b + (size_t)l * QKVW, nullptr, 0, NTOK, QKVW, DMODEL);

        rope_h<<<NTOK, 576>>>();

        flash_h<<<dim3(50, HEADS), 256>>>(qkvh, attnh);

        gemm3<EPI_BIAS_RES, false><<<ggrid3(NTOK, DMODEL), 256, G4_SMEM>>>(
            attnh, DMODEL, wt + OFF_PROJ + l * SZ_PROJ, DMODEL, x, DMODEL,
            proj_b + (size_t)l * DMODEL, x, DMODEL, NTOK, DMODEL, DMODEL);

        ln_h<<<NTOK, 288>>>(x, hh, ln2_s + l * DMODEL, ln2_b + l * DMODEL);

        gemm3<EPI_BIAS_GELU, true><<<ggrid3(NTOK, IDIM), 256, G4_SMEM>>>(
            hh, DMODEL, wt + OFF_FC1 + l * SZ_FC1, IDIM, mlph, IDIM,
            fc1_b + (size_t)l * IDIM, nullptr, 0, NTOK, IDIM, DMODEL);

        gemm3<EPI_BIAS_RES, false><<<ggrid3(NTOK, DMODEL), 256, G4_SMEM>>>(
            mlph, IDIM, wt + OFF_FC2 + l * SZ_FC2, DMODEL, x, DMODEL,
            fc2_b + (size_t)l * DMODEL, x, DMODEL, NTOK, DMODEL, IDIM);
    }

    // merger
    ln_h<<<NTOK, 288>>>(x, hh, m_ln_s, m_ln_b);   // hh viewed as [1568][4608]

    gemm3<EPI_BIAS_GELU, true><<<ggrid3(MROWS, MD4), 256, G4_SMEM>>>(
        hh, MD4, wt + OFF_MFC1, MD4, mlph, MD4,
        m_fc1_b, nullptr, 0, MROWS, MD4, MD4);

    gemm3<EPI_BIAS, false><<<ggrid3(MROWS, DOUT), 256, G4_SMEM>>>(
        mlph, MD4, wt + OFF_MFC2, DOUT, out, DOUT,
        m_fc2_b, nullptr, 0, MROWS, DOUT, MD4);
}

// round 13
// speedup vs baseline: 1.8122x; 1.0138x over previous
#include <cuda_runtime.h>
#include <cuda_fp16.h>
#include <math.h>
#include <stdint.h>

// ---------------------------------------------------------------------------
// Problem constants (GRID fixed: [[1,48,48],[1,32,64],[2,24,40]])
// ---------------------------------------------------------------------------
#define NTOK    6272
#define DMODEL  1152
#define HEADS   16
#define HDIM    72
#define IDIM    4304
#define DOUT    2048
#define MROWS   1568
#define MD4     4608
#define QKVW    3456
#define CIN     1536

// ---------------------------------------------------------------------------
// Scratch buffers
// ---------------------------------------------------------------------------
__device__ float  g_x    [NTOK * DMODEL];        // residual (fp32)
__device__ __half g_pix  [NTOK * CIN];           // pixel fp16
__device__ __half g_hh   [NTOK * DMODEL];        // LN out fp16
__device__ __half g_qkvh [NTOK * QKVW];          // qkv fp16
__device__ __half g_attnh[NTOK * DMODEL];        // attn out fp16
__device__ __half g_mlph [NTOK * IDIM];          // mlp hidden fp16
__device__ float  g_cos  [NTOK * 36];
__device__ float  g_sin  [NTOK * 36];

// fp16 weights, natural [K,N] layout (no transpose)
#define SZ_PATCH (1536ULL * 1152)
#define SZ_QKV   (1152ULL * 3456)
#define SZ_PROJ  (1152ULL * 1152)
#define SZ_FC1   (1152ULL * 4304)
#define SZ_FC2   (4304ULL * 1152)
#define SZ_MFC1  (4608ULL * 4608)
#define SZ_MFC2  (4608ULL * 2048)
#define OFF_PATCH 0ULL
#define OFF_QKV   (OFF_PATCH + SZ_PATCH)
#define OFF_PROJ  (OFF_QKV + 2 * SZ_QKV)
#define OFF_FC1   (OFF_PROJ + 2 * SZ_PROJ)
#define OFF_FC2   (OFF_FC1 + 2 * SZ_FC1)
#define OFF_MFC1  (OFF_FC2 + 2 * SZ_FC2)
#define OFF_MFC2  (OFF_MFC1 + SZ_MFC1)
#define WT_TOTAL  (OFF_MFC2 + SZ_MFC2)
__device__ __half g_wt[WT_TOTAL];

// ---------------------------------------------------------------------------
__device__ __forceinline__ void token_pos(int n, int& row, int& col, int& ih, int& iw)
{
    int local, h, w;
    if (n < 2304)      { local = n;          h = 48; w = 48; }
    else if (n < 4352) { local = n - 2304;   h = 32; w = 64; }
    else               { local = n - 4352;   h = 24; w = 40; }
    int rem = local % (h * w);
    int wb_cnt = w >> 1;
    int blk = rem >> 2, within = rem & 3;
    int hb = blk / wb_cnt, wb = blk % wb_cnt;
    row = hb * 2 + (within >> 1);
    col = wb * 2 + (within & 1);
    ih = h; iw = w;
}

__global__ void cossin_kernel()
{
    int idx = blockIdx.x * blockDim.x + threadIdx.x;
    if (idx >= NTOK * 36) return;
    int n = idx / 36, d = idx % 36;
    int row, col, ih, iw;
    token_pos(n, row, col, ih, iw);
    int j = (d < 18) ? d : d - 18;
    double p = (d < 18) ? (double)row : (double)col;
    double inv = 1.0 / pow(10000.0, (2.0 * (double)j) / 36.0);
    double ang = p * inv;
    g_cos[idx] = (float)cos(ang);
    g_sin[idx] = (float)sin(ang);
}

__global__ void posadd_kernel(const float* __restrict__ pos_table)
{
    int n = blockIdx.x;
    int row, col, ih, iw;
    token_pos(n, row, col, ih, iw);
    double hi = 47.0 * (double)row / (double)(ih - 1);
    double wi = 47.0 * (double)col / (double)(iw - 1);
    int hf = (int)floor(hi), wf = (int)floor(wi);
    float dh = (float)(hi - (double)hf), dw = (float)(wi - (double)wf);
    int hc = min(hf + 1, 47), wc = min(wf + 1, 47);
    float w00 = (1.f - dh) * (1.f - dw);
    float w01 = (1.f - dh) * dw;
    float w10 = dh * (1.f - dw);
    float w11 = dh * dw;
    const float* p00 = pos_table + (size_t)(hf * 48 + wf) * DMODEL;
    const float* p01 = pos_table + (size_t)(hf * 48 + wc) * DMODEL;
    const float* p10 = pos_table + (size_t)(hc * 48 + wf) * DMODEL;
    const float* p11 = pos_table + (size_t)(hc * 48 + wc) * DMODEL;
    float* xr = g_x + (size_t)n * DMODEL;
    for (int d = threadIdx.x; d < DMODEL; d += blockDim.x)
        xr[d] += p00[d] * w00 + p01[d] * w01 + p10[d] * w10 + p11[d] * w11;
}

// ---------------------------------------------------------------------------
// Fused fp32->fp16 convert for ALL prep streams in one launch.
// ---------------------------------------------------------------------------
#define NSEG 13
struct ConvJobs {
    const float4* src[NSEG];
    uint2*        dst[NSEG];
    int           off[NSEG + 1];   // cumulative float4 offsets
};

__global__ void convall(ConvJobs J, int total)
{
    int i = blockIdx.x * blockDim.x + threadIdx.x;
    if (i >= total) return;
    int s = 0;
#pragma unroll
    for (int k = 1; k < NSEG; k++) s += (i >= J.off[k]) ? 1 : 0;
    int local = i - J.off[s];
    float4 v = J.src[s][local];
    __half2 lo = __floats2half2_rn(v.x, v.y);
    __half2 hi = __floats2half2_rn(v.z, v.w);
    J.dst[s][local] =
        make_uint2(*reinterpret_cast<uint32_t*>(&lo), *reinterpret_cast<uint32_t*>(&hi));
}

__device__ __forceinline__ float warp_sum(float v)
{
#pragma unroll
    for (int o = 16; o > 0; o >>= 1) v += __shfl_xor_sync(0xffffffffu, v, o);
    return v;
}

// LayerNorm fp32 in -> fp16 out
__global__ void ln_h(const float* __restrict__ in, __half* __restrict__ out,
                     const float* __restrict__ s, const float* __restrict__ b)
{
    __shared__ float sh[9];
    __shared__ float stat[2];
    int n = blockIdx.x;
    const float* xr = in + (size_t)n * DMODEL;
    int t = threadIdx.x, wid = t >> 5, lane = t & 31;

    float vals[4];
    float lsum = 0.f;
#pragma unroll
    for (int i = 0; i < 4; i++) { vals[i] = xr[t + i * 288]; lsum += vals[i]; }
    float ws = warp_sum(lsum);
    if (lane == 0) sh[wid] = ws;
    __syncthreads();
    if (t == 0) {
        float tot = 0.f;
#pragma unroll
        for (int i = 0; i < 9; i++) tot += sh[i];
        stat[0] = tot * (1.0f / DMODEL);
    }
    __syncthreads();
    float mu = stat[0];
    float lvar = 0.f;
#pragma unroll
    for (int i = 0; i < 4; i++) { float d = vals[i] - mu; lvar += d * d; }
    ws = warp_sum(lvar);
    __syncthreads();
    if (lane == 0) sh[wid] = ws;
    __syncthreads();
    if (t == 0) {
        float tot = 0.f;
#pragma unroll
        for (int i = 0; i < 9; i++) tot += sh[i];
        stat[1] = rsqrtf(tot * (1.0f / DMODEL) + 1e-6f);
    }
    __syncthreads();
    float r = stat[1];
    __half* orow = out + (size_t)n * DMODEL;
#pragma unroll
    for (int i = 0; i < 4; i++) {
        int d = t + i * 288;
        orow[d] = __float2half_rn((vals[i] - mu) * r * s[d] + b[d]);
    }
}

// RoPE in-place on fp16 qkv
__global__ void rope_h()
{
    int n = blockIdx.x;
    int t = threadIdx.x;
    int h = t / 36, d = t % 36;
    float c = g_cos[n * 36 + d];
    float s = g_sin[n * 36 + d];
    __half* q = g_qkvh + (size_t)n * QKVW + h * HDIM;
    __half* k = q + DMODEL;
    float q0 = __half2float(q[d]), q1 = __half2float(q[d + 36]);
    q[d]      = __float2half_rn(q0 * c - q1 * s);
    q[d + 36] = __float2half_rn(q1 * c + q0 * s);
    float k0 = __half2float(k[d]), k1 = __half2float(k[d + 36]);
    k[d]      = __float2half_rn(k0 * c - k1 * s);
    k[d + 36] = __float2half_rn(k1 * c + k0 * s);
}

// ---------------------------------------------------------------------------
// mma / misc helpers
// ---------------------------------------------------------------------------
__device__ __forceinline__ void mma_f16(float c[4],
                                        uint32_t a0, uint32_t a1, uint32_t a2, uint32_t a3,
                                        uint32_t b0, uint32_t b1)
{
    asm volatile(
        "mma.sync.aligned.m16n8k16.row.col.f32.f16.f16.f32 "
        "{%0,%1,%2,%3}, {%4,%5,%6,%7}, {%8,%9}, {%0,%1,%2,%3};\n"
        : "+f"(c[0]), "+f"(c[1]), "+f"(c[2]), "+f"(c[3])
        : "r"(a0), "r"(a1), "r"(a2), "r"(a3), "r"(b0), "r"(b1));
}

// fast gelu: HW tanh approx (MUFU.TANH)
__device__ __forceinline__ float gelu_tanh(float x)
{
    float u = 0.7978845608028654f * (x + 0.044715f * x * x * x);
    float t;
    asm("tanh.approx.f32 %0, %1;" : "=f"(t) : "f"(u));
    return 0.5f * x * (1.f + t);
}

__device__ __forceinline__ uint32_t pack_h2(float lo, float hi)
{
    __half2 h = __floats2half2_rn(lo, hi);
    return *reinterpret_cast<uint32_t*>(&h);
}

// ---------------------------------------------------------------------------
// GEMM v4: A fp16 [M,K] row-major, B fp16 [K,N] row-major, C fp32 or fp16.
//   Block 128x128, BK=32, 4 stages (dynamic smem), cp.async wait_group 2.
//   8 warps 2(M) x 4(N), warp tile 64x32.
// ---------------------------------------------------------------------------
#define EPI_BIAS      1
#define EPI_BIAS_GELU 2
#define EPI_BIAS_RES  3

#define G4_AST  20              // A row stride (words)
#define G4_BST  68              // B row stride (words)
#define G4_BOFF 2560            // B offset within stage (words)
#define G4_STG  4736            // words per stage
#define G4_NSTG 4
#define G4_SMEM (G4_NSTG * G4_STG * 4)

template<int EPI, bool OUTH>
__global__ void __launch_bounds__(256, 2)
gemm3(const __half* __restrict__ A, int lda,
      const __half* __restrict__ B, int ldb,
      void* __restrict__ Cv, int ldc,
      const float* __restrict__ bias,
      const float* __restrict__ Res, int ldr,
      int Md, int Nd, int Kd)
{
    extern __shared__ uint32_t smbuf[];

    const int tid  = threadIdx.x;
    const int brow = blockIdx.y * 128;
    const int bcol = blockIdx.x * 128;
    const int w    = tid >> 5;
    const int lane = tid & 31;
    const int g    = lane >> 2;
    const int q    = lane & 3;
    const int wm   = w & 1;
    const int wn   = w >> 1;

    uint32_t smbase = (uint32_t)__cvta_generic_to_shared(smbuf);

    int aok[2], ak8[2];
    uint32_t sa[2];
    const __half* ga[2];
#pragma unroll
    for (int i = 0; i < 2; i++) {
        int c = tid + i * 256;
        int row = c >> 2;
        ak8[i] = (c & 3) * 8;
        aok[i] = (brow + row) < Md;
        sa[i] = smbase + (uint32_t)(row * G4_AST + (c & 3) * 4) * 4;
        ga[i] = A + (long long)(brow + row) * lda + ak8[i];
    }
    int bkr[2], bok[2];
    uint32_t sb[2];
    const __half* gb[2];
#pragma unroll
    for (int i = 0; i < 2; i++) {
        int c = tid + i * 256;
        bkr[i] = c >> 4;
        int n8 = (c & 15) * 8;
        bok[i] = (bcol + n8) < Nd;
        sb[i] = smbase + (uint32_t)(G4_BOFF + bkr[i] * G4_BST + (c & 15) * 4) * 4;
        gb[i] = B + (long long)bkr[i] * ldb + bcol + n8;
    }

    float acc[4][4][4];
#pragma unroll
    for (int i = 0; i < 4; i++)
#pragma unroll
        for (int j = 0; j < 4; j++)
#pragma unroll
            for (int r = 0; r < 4; r++) acc[i][j][r] = 0.f;

    const int ntk = (Kd + 31) >> 5;

    auto load_stage = [&](int k0, int st) {
        uint32_t off = (uint32_t)(st * G4_STG) * 4;
#pragma unroll
        for (int i = 0; i < 2; i++) {
            int va = (aok[i] && (k0 + ak8[i]) < Kd) ? 16 : 0;
            asm volatile("cp.async.cg.shared.global [%0], [%1], 16, %2;"
                         :: "r"(sa[i] + off), "l"(ga[i] + k0), "r"(va));
        }
#pragma unroll
        for (int i = 0; i < 2; i++) {
            int vb = (bok[i] && (k0 + bkr[i]) < Kd) ? 16 : 0;
            asm volatile("cp.async.cg.shared.global [%0], [%1], 16, %2;"
                         :: "r"(sb[i] + off), "l"(gb[i] + (long long)k0 * ldb), "r"(vb));
        }
    };

    load_stage(0, 0);
    asm volatile("cp.async.commit_group;");
    if (ntk > 1) load_stage(32, 1);
    asm volatile("cp.async.commit_group;");
    if (ntk > 2) load_stage(64, 2);
    asm volatile("cp.async.commit_group;");

    const int a_row = wm * 64 + (lane & 15);
    const uint32_t abase = smbase + (uint32_t)(a_row * G4_AST + (lane >> 4) * 4) * 4;
    const uint32_t bbase = smbase + (uint32_t)G4_BOFF * 4 +
        (uint32_t)((lane & 15) * G4_BST * 4 + (wn * 32 + (lane >> 4) * 8) * 2);

    for (int kt = 0; kt < ntk; kt++) {
        asm volatile("cp.async.wait_group 2;");
        __syncthreads();
        uint32_t soff = (uint32_t)((kt & 3) * G4_STG) * 4;

#pragma unroll
        for (int kg = 0; kg < 2; kg++) {
            uint32_t akg = soff + (uint32_t)(kg * 8) * 4;
            uint32_t bkg = soff + (uint32_t)(kg * 16 * G4_BST) * 4;

            uint32_t af[4][4], bf[2][4];
#pragma unroll
            for (int mt = 0; mt < 4; mt++)
                asm volatile("ldmatrix.sync.aligned.m8n8.x4.shared.b16 {%0,%1,%2,%3}, [%4];"
                             : "=r"(af[mt][0]), "=r"(af[mt][1]), "=r"(af[mt][2]), "=r"(af[mt][3])
                             : "r"(abase + akg + (uint32_t)(mt * 16 * G4_AST) * 4));
#pragma unroll
            for (int ng = 0; ng < 2; ng++)
                asm volatile("ldmatrix.sync.aligned.m8n8.x4.trans.shared.b16 {%0,%1,%2,%3}, [%4];"
                             : "=r"(bf[ng][0]), "=r"(bf[ng][1]), "=r"(bf[ng][2]), "=r"(bf[ng][3])
                             : "r"(bbase + bkg + (uint32_t)(ng * 32)));

#pragma unroll
            for (int mt = 0; mt < 4; mt++)
#pragma unroll
                for (int j = 0; j < 4; j++)
                    mma_f16(acc[mt][j],
                            af[mt][0], af[mt][1], af[mt][2], af[mt][3],
                            bf[j >> 1][(j & 1) * 2], bf[j >> 1][(j & 1) * 2 + 1]);
        }

        int ktn = kt + 3;
        if (ktn < ntk)
            load_stage(ktn * 32, ktn & 3);
        asm volatile("cp.async.commit_group;");
    }

    float*  Cf = (float*)Cv;
    __half* Ch = (__half*)Cv;
#pragma unroll
    for (int mt = 0; mt < 4; mt++) {
#pragma unroll
        for (int hh = 0; hh < 2; hh++) {
            int r = brow + wm * 64 + mt * 16 + g + 8 * hh;
            if (r >= Md) continue;
#pragma unroll
            for (int j = 0; j < 4; j++) {
                int c = bcol + wn * 32 + j * 8 + 2 * q;
                if (c >= Nd) continue;
                float v0 = acc[mt][j][hh * 2];
                float v1 = acc[mt][j][hh * 2 + 1];
                v0 += bias[c]; v1 += bias[c + 1];
                if (EPI == EPI_BIAS_GELU) { v0 = gelu_tanh(v0); v1 = gelu_tanh(v1); }
                if (EPI == EPI_BIAS_RES)  {
                    v0 += Res[(long long)r * ldr + c];
                    v1 += Res[(long long)r * ldr + c + 1];
                }
                if (OUTH) {
                    __half2 hv = __floats2half2_rn(v0, v1);
                    *reinterpret_cast<__half2*>(Ch + (long long)r * ldc + c) = hv;
                } else {
                    *reinterpret_cast<float2*>(Cf + (long long)r * ldc + c) = make_float2(v0, v1);
                }
            }
        }
    }
}

// ---------------------------------------------------------------------------
// Fused flash attention v2 (unchanged — verified).
// ---------------------------------------------------------------------------
#define FROW 44

__global__ void __launch_bounds__(256, 2)
flash_h(const __half* __restrict__ qkv, __half* __restrict__ attn)
{
    __shared__ uint32_t Qs[128 * FROW];
    __shared__ uint32_t Ks[64 * FROW];
    __shared__ uint32_t Vs[64 * FROW];

    int t = blockIdx.x;
    int head = blockIdx.y;
    int st, S, q0;
    if (t < 18)      { st = 0;    S = 2304; q0 = t * 128; }
    else if (t < 34) { st = 2304; S = 2048; q0 = (t - 18) * 128; }
    else if (t < 42) { st = 4352; S = 960;  q0 = (t - 34) * 128; }
    else             { st = 5312; S = 960;  q0 = (t - 42) * 128; }

    const int tid  = threadIdx.x;
    const int w    = tid >> 5;
    const int lane = tid & 31;
    const int g    = lane >> 2;
    const int q    = lane & 3;
    const int rowbase = w * 16;

    const float scale = 0.11785113019775793f;

    for (int s = tid; s < 128 * 9; s += 256) {
        int row = s / 9, c = s % 9;
        uint4 v = make_uint4(0, 0, 0, 0);
        if (q0 + row < S)
            v = *reinterpret_cast<const uint4*>(
                qkv + (size_t)(st + q0 + row) * QKVW + head * HDIM + c * 8);
        *reinterpret_cast<uint4*>(&Qs[row * FROW + c * 4]) = v;
    }
    for (int s = tid; s < 128 * 8; s += 256) Qs[(s >> 3) * FROW + 36 + (s & 7)] = 0;
    for (int s = tid; s < 64 * 8; s += 256) {
        Ks[(s >> 3) * FROW + 36 + (s & 7)] = 0;
        Vs[(s >> 3) * FROW + 36 + (s & 7)] = 0;
    }

    float m0 = -1e30f, m1 = -1e30f, l0 = 0.f, l1 = 0.f;
    float O[10][4];
#pragma unroll
    for (int i = 0; i < 10; i++)
#pragma unroll
        for (int r = 0; r < 4; r++) O[i][r] = 0.f;

    uint32_t smQ = (uint32_t)__cvta_generic_to_shared(Qs);
    uint32_t smK = (uint32_t)__cvta_generic_to_shared(Ks);
    uint32_t smV = (uint32_t)__cvta_generic_to_shared(Vs);
    const uint32_t qsb = smQ + (uint32_t)((rowbase + (lane & 15)) * FROW + (lane >> 4) * 4) * 4;
    const uint32_t ksb = smK + (uint32_t)((((lane & 7) + ((lane >> 4) << 3)) * FROW) +
                                          ((lane >> 3) & 1) * 4) * 4;
    const uint32_t vsb = smV + (uint32_t)(((lane & 15) * FROW) + (lane >> 4) * 4) * 4;

    const int nkv = S >> 6;
    for (int j = 0; j < nkv; j++) {
        __syncthreads();
        const int kv0 = j * 64;
        for (int s = tid; s < 64 * 9; s += 256) {
            int row = s / 9, c = s % 9;
            *reinterpret_cast<uint4*>(&Ks[row * FROW + c * 4]) =
                *reinterpret_cast<const uint4*>(
                    qkv + (size_t)(st + kv0 + row) * QKVW + DMODEL + head * HDIM + c * 8);
        }
        for (int s = tid; s < 64 * 9; s += 256) {
            int row = s / 9, c = s % 9;
            *reinterpret_cast<uint4*>(&Vs[row * FROW + c * 4]) =
                *reinterpret_cast<const uint4*>(
                    qkv + (size_t)(st + kv0 + row) * QKVW + 2 * DMODEL + head * HDIM + c * 8);
        }
        __syncthreads();

        float acc[8][4];
#pragma unroll
        for (int i = 0; i < 8; i++)
#pragma unroll
            for (int r = 0; r < 4; r++) acc[i][r] = 0.f;

#pragma unroll
        for (int kb = 0; kb < 5; kb++) {
            uint32_t af[4];
            asm volatile("ldmatrix.sync.aligned.m8n8.x4.shared.b16 {%0,%1,%2,%3}, [%4];"
                         : "=r"(af[0]), "=r"(af[1]), "=r"(af[2]), "=r"(af[3])
                         : "r"(qsb + (uint32_t)(kb * 8) * 4));
#pragma unroll
            for (int nt4 = 0; nt4 < 4; nt4++) {
                uint32_t bf[4];
                asm volatile("ldmatrix.sync.aligned.m8n8.x4.shared.b16 {%0,%1,%2,%3}, [%4];"
                             : "=r"(bf[0]), "=r"(bf[1]), "=r"(bf[2]), "=r"(bf[3])
                             : "r"(ksb + (uint32_t)(nt4 * 16 * FROW + kb * 8) * 4));
                mma_f16(acc[2 * nt4    ], af[0], af[1], af[2], af[3], bf[0], bf[1]);
                mma_f16(acc[2 * nt4 + 1], af[0], af[1], af[2], af[3], bf[2], bf[3]);
            }
        }
#pragma unroll
        for (int i = 0; i < 8; i++)
#pragma unroll
            for (int r = 0; r < 4; r++) acc[i][r] *= scale;

        float mx0 = -1e30f, mx1 = -1e30f;
#pragma unroll
        for (int i = 0; i < 8; i++) {
            mx0 = fmaxf(mx0, fmaxf(acc[i][0], acc[i][1]));
            mx1 = fmaxf(mx1, fmaxf(acc[i][2], acc[i][3]));
        }
        mx0 = fmaxf(mx0, __shfl_xor_sync(0xffffffffu, mx0, 1));
        mx0 = fmaxf(mx0, __shfl_xor_sync(0xffffffffu, mx0, 2));
        mx1 = fmaxf(mx1, __shfl_xor_sync(0xffffffffu, mx1, 1));
        mx1 = fmaxf(mx1, __shfl_xor_sync(0xffffffffu, mx1, 2));
        float mn0 = fmaxf(m0, mx0), mn1 = fmaxf(m1, mx1);
        float al0 = __expf(m0 - mn0), al1 = __expf(m1 - mn1);
        m0 = mn0; m1 = mn1;

        float rs0 = 0.f, rs1 = 0.f;
#pragma unroll
        for (int i = 0; i < 8; i++) {
            acc[i][0] = __expf(acc[i][0] - mn0);
            acc[i][1] = __expf(acc[i][1] - mn0);
            acc[i][2] = __expf(acc[i][2] - mn1);
            acc[i][3] = __expf(acc[i][3] - mn1);
            rs0 += acc[i][0] + acc[i][1];
            rs1 += acc[i][2] + acc[i][3];
        }
        rs0 += __shfl_xor_sync(0xffffffffu, rs0, 1);
        rs0 += __shfl_xor_sync(0xffffffffu, rs0, 2);
        rs1 += __shfl_xor_sync(0xffffffffu, rs1, 1);
        rs1 += __shfl_xor_sync(0xffffffffu, rs1, 2);
        l0 = l0 * al0 + rs0;
        l1 = l1 * al1 + rs1;

#pragma unroll
        for (int i = 0; i < 10; i++) {
            O[i][0] *= al0; O[i][1] *= al0;
            O[i][2] *= al1; O[i][3] *= al1;
        }

        uint32_t pa[4][4];
#pragma unroll
        for (int kb = 0; kb < 4; kb++) {
            pa[kb][0] = pack_h2(acc[2 * kb][0],     acc[2 * kb][1]);
            pa[kb][1] = pack_h2(acc[2 * kb][2],     acc[2 * kb][3]);
            pa[kb][2] = pack_h2(acc[2 * kb + 1][0], acc[2 * kb + 1][1]);
            pa[kb][3] = pack_h2(acc[2 * kb + 1][2], acc[2 * kb + 1][3]);
        }

#pragma unroll
        for (int kb = 0; kb < 4; kb++) {
#pragma unroll
            for (int vt = 0; vt < 5; vt++) {
                uint32_t bf[4];
                asm volatile("ldmatrix.sync.aligned.m8n8.x4.trans.shared.b16 {%0,%1,%2,%3}, [%4];"
                             : "=r"(bf[0]), "=r"(bf[1]), "=r"(bf[2]), "=r"(bf[3])
                             : "r"(vsb + (uint32_t)(kb * 16 * FROW + vt * 8) * 4));
                mma_f16(O[2 * vt    ], pa[kb][0], pa[kb][1], pa[kb][2], pa[kb][3], bf[0], bf[1]);
                mma_f16(O[2 * vt + 1], pa[kb][0], pa[kb][1], pa[kb][2], pa[kb][3], bf[2], bf[3]);
            }
        }
    }

#pragma unroll
    for (int h = 0; h < 2; h++) {
        int r = rowbase + g + 8 * h;
        if (q0 + r >= S) continue;
        float inv = 1.0f / (h == 0 ? l0 : l1);
#pragma unroll
        for (int ntl = 0; ntl < 9; ntl++) {
            int c = ntl * 8 + 2 * q;
            __half2 hv = __floats2half2_rn(O[ntl][2 * h] * inv, O[ntl][2 * h + 1] * inv);
            *reinterpret_cast<__half2*>(
                attn + (size_t)(st + q0 + r) * DMODEL + head * HDIM + c) = hv;
        }
    }
}

// ---------------------------------------------------------------------------
// Host launcher
// ---------------------------------------------------------------------------
#define SYMF(p, s) do { void* _t; cudaGetSymbolAddress(&_t, s); p = (float*)_t; } while (0)
#define SYMH(p, s) do { void* _t; cudaGetSymbolAddress(&_t, s); p = (__half*)_t; } while (0)

static inline dim3 ggrid3(int Md, int Nd) {
    return dim3((Nd + 127) / 128, (Md + 127) / 128);
}

extern "C" void kernel_launch(void* const* d_in, const int* in_sizes, int n_in,
                              void* d_out, int out_size)
{
    (void)in_sizes; (void)n_in; (void)out_size;
    const float* pixel    = (const float*)d_in[0];
    const float* patch_w  = (const float*)d_in[2];
    const float* patch_b  = (const float*)d_in[3];
    const float* pos_tab  = (const float*)d_in[4];
    const float* ln1_s    = (const float*)d_in[5];
    const float* ln1_b    = (const float*)d_in[6];
    const float* qkv_w    = (const float*)d_in[7];
    const float* qkv_b    = (const float*)d_in[8];
    const float* proj_w   = (const float*)d_in[9];
    const float* proj_b   = (const float*)d_in[10];
    const float* ln2_s    = (const float*)d_in[11];
    const float* ln2_b    = (const float*)d_in[12];
    const float* fc1_w    = (const float*)d_in[13];
    const float* fc1_b    = (const float*)d_in[14];
    const float* fc2_w    = (const float*)d_in[15];
    const float* fc2_b    = (const float*)d_in[16];
    const float* m_ln_s   = (const float*)d_in[17];
    const float* m_ln_b   = (const float*)d_in[18];
    const float* m_fc1_w  = (const float*)d_in[19];
    const float* m_fc1_b  = (const float*)d_in[20];
    const float* m_fc2_w  = (const float*)d_in[21];
    const float* m_fc2_b  = (const float*)d_in[22];
    float* out = (float*)d_out;

    float *x;
    __half *pix, *hh, *qkvh, *attnh, *mlph, *wt;
    SYMF(x, g_x);
    SYMH(pix, g_pix); SYMH(hh, g_hh); SYMH(qkvh, g_qkvh);
    SYMH(attnh, g_attnh); SYMH(mlph, g_mlph); SYMH(wt, g_wt);

    static bool attr_set = false;
    if (!attr_set) {
        cudaFuncSetAttribute(gemm3<EPI_BIAS, false>,
                             cudaFuncAttributeMaxDynamicSharedMemorySize, G4_SMEM);
        cudaFuncSetAttribute(gemm3<EPI_BIAS, true>,
                             cudaFuncAttributeMaxDynamicSharedMemorySize, G4_SMEM);
        cudaFuncSetAttribute(gemm3<EPI_BIAS_GELU, true>,
                             cudaFuncAttributeMaxDynamicSharedMemorySize, G4_SMEM);
        cudaFuncSetAttribute(gemm3<EPI_BIAS_RES, false>,
                             cudaFuncAttributeMaxDynamicSharedMemorySize, G4_SMEM);
        attr_set = true;
    }

    // ---- fused fp32->fp16 conversion (single launch, all streams)
    {
        ConvJobs J;
        const float* srcs[NSEG] = {
            pixel, patch_w,
            qkv_w,  qkv_w  + SZ_QKV,
            proj_w, proj_w + SZ_PROJ,
            fc1_w,  fc1_w  + SZ_FC1,
            fc2_w,  fc2_w  + SZ_FC2,
            m_fc1_w, m_fc2_w, nullptr };
        __half* dsts[NSEG] = {
            pix, wt + OFF_PATCH,
            wt + OFF_QKV,  wt + OFF_QKV + SZ_QKV,
            wt + OFF_PROJ, wt + OFF_PROJ + SZ_PROJ,
            wt + OFF_FC1,  wt + OFF_FC1 + SZ_FC1,
            wt + OFF_FC2,  wt + OFF_FC2 + SZ_FC2,
            wt + OFF_MFC1, wt + OFF_MFC2, nullptr };
        long long sizes[NSEG] = {
            (long long)NTOK * CIN, (long long)SZ_PATCH,
            (long long)SZ_QKV, (long long)SZ_QKV,
            (long long)SZ_PROJ, (long long)SZ_PROJ,
            (long long)SZ_FC1, (long long)SZ_FC1,
            (long long)SZ_FC2, (long long)SZ_FC2,
            (long long)SZ_MFC1, (long long)SZ_MFC2, 0 };
        // NSEG = 13 but we have 12 real streams + pixel = 13 total? pixel + 12 = 13.
        // srcs/dsts above list exactly 13 entries with last unused (sizes[12]=0).
        srcs[12]  = m_fc2_w;      // dummy (size 0, never touched)
        dsts[12]  = wt + OFF_MFC2;
        int off = 0;
        for (int s = 0; s < NSEG; s++) {
            J.src[s] = (const float4*)srcs[s];
            J.dst[s] = (uint2*)dsts[s];
            J.off[s] = off;
            off += (int)(sizes[s] / 4);
        }
        J.off[NSEG] = off;
        convall<<<(off + 255) / 256, 256>>>(J, off);
    }

    cossin_kernel<<<(NTOK * 36 + 255) / 256, 256>>>();

    // Patch embed -> x (fp32)
    gemm3<EPI_BIAS, false><<<ggrid3(NTOK, DMODEL), 256, G4_SMEM>>>(
        pix, CIN, wt + OFF_PATCH, DMODEL, x, DMODEL,
        patch_b, nullptr, 0, NTOK, DMODEL, CIN);

    posadd_kernel<<<NTOK, 288>>>(pos_tab);

    for (int l = 0; l < 2; l++) {
        ln_h<<<NTOK, 288>>>(x, hh, ln1_s + l * DMODEL, ln1_b + l * DMODEL);

        gemm3<EPI_BIAS, true><<<ggrid3(NTOK, QKVW), 256, G4_SMEM>>>(
            hh, DMODEL, wt + OFF_QKV + l * SZ_QKV, QKVW, qkvh, QKVW,
            qkv_b + (size_t)l * QKVW, nullptr, 0, NTOK, QKVW, DMODEL);

        rope_h<<<NTOK, 576>>>();

        flash_h<<<dim3(50, HEADS), 256>>>(qkvh, attnh);

        gemm3<EPI_BIAS_RES, false><<<ggrid3(NTOK, DMODEL), 256, G4_SMEM>>>(
            attnh, DMODEL, wt + OFF_PROJ + l * SZ_PROJ, DMODEL, x, DMODEL,
            proj_b + (size_t)l * DMODEL, x, DMODEL, NTOK, DMODEL, DMODEL);

        ln_h<<<NTOK, 288>>>(x, hh, ln2_s + l * DMODEL, ln2_b + l * DMODEL);

        gemm3<EPI_BIAS_GELU, true><<<ggrid3(NTOK, IDIM), 256, G4_SMEM>>>(
            hh, DMODEL, wt + OFF_FC1 + l * SZ_FC1, IDIM, mlph, IDIM,
            fc1_b + (size_t)l * IDIM, nullptr, 0, NTOK, IDIM, DMODEL);

        gemm3<EPI_BIAS_RES, false><<<ggrid3(NTOK, DMODEL), 256, G4_SMEM>>>(
            mlph, IDIM, wt + OFF_FC2 + l * SZ_FC2, DMODEL, x, DMODEL,
            fc2_b + (size_t)l * DMODEL, x, DMODEL, NTOK, DMODEL, IDIM);
    }

    // merger
    ln_h<<<NTOK, 288>>>(x, hh, m_ln_s, m_ln_b);   // hh viewed as [1568][4608]

    gemm3<EPI_BIAS_GELU, true><<<ggrid3(MROWS, MD4), 256, G4_SMEM>>>(
        hh, MD4, wt + OFF_MFC1, MD4, mlph, MD4,
        m_fc1_b, nullptr, 0, MROWS, MD4, MD4);

    gemm3<EPI_BIAS, false><<<ggrid3(MROWS, DOUT), 256, G4_SMEM>>>(
        mlph, MD4, wt + OFF_MFC2, DOUT, out, DOUT,
        m_fc2_b, nullptr, 0, MROWS, DOUT, MD4);
}

// round 14
// speedup vs baseline: 1.9093x; 1.0536x over previous
#include <cuda_runtime.h>
#include <cuda_fp16.h>
#include <math.h>
#include <stdint.h>

// ---------------------------------------------------------------------------
// Problem constants (GRID fixed: [[1,48,48],[1,32,64],[2,24,40]])
// ---------------------------------------------------------------------------
#define NTOK    6272
#define DMODEL  1152
#define HEADS   16
#define HDIM    72
#define IDIM    4304
#define DOUT    2048
#define MROWS   1568
#define MD4     4608
#define QKVW    3456
#define CIN     1536

// ---------------------------------------------------------------------------
// Scratch buffers
// ---------------------------------------------------------------------------
__device__ float  g_x    [NTOK * DMODEL];        // residual (fp32)
__device__ __half g_pix  [NTOK * CIN];           // pixel fp16
__device__ __half g_hh   [NTOK * DMODEL];        // LN out fp16
__device__ __half g_qkvh [NTOK * QKVW];          // qkv fp16
__device__ __half g_attnh[NTOK * DMODEL];        // attn out fp16
__device__ __half g_mlph [NTOK * IDIM];          // mlp hidden fp16
__device__ float  g_cos  [NTOK * 36];
__device__ float  g_sin  [NTOK * 36];

// fp16 weights, natural [K,N] layout (no transpose)
#define SZ_PATCH (1536ULL * 1152)
#define SZ_QKV   (1152ULL * 3456)
#define SZ_PROJ  (1152ULL * 1152)
#define SZ_FC1   (1152ULL * 4304)
#define SZ_FC2   (4304ULL * 1152)
#define SZ_MFC1  (4608ULL * 4608)
#define SZ_MFC2  (4608ULL * 2048)
#define OFF_PATCH 0ULL
#define OFF_QKV   (OFF_PATCH + SZ_PATCH)
#define OFF_PROJ  (OFF_QKV + 2 * SZ_QKV)
#define OFF_FC1   (OFF_PROJ + 2 * SZ_PROJ)
#define OFF_FC2   (OFF_FC1 + 2 * SZ_FC1)
#define OFF_MFC1  (OFF_FC2 + 2 * SZ_FC2)
#define OFF_MFC2  (OFF_MFC1 + SZ_MFC1)
#define WT_TOTAL  (OFF_MFC2 + SZ_MFC2)
__device__ __half g_wt[WT_TOTAL];

// ---------------------------------------------------------------------------
__device__ __forceinline__ void token_pos(int n, int& row, int& col, int& ih, int& iw)
{
    int local, h, w;
    if (n < 2304)      { local = n;          h = 48; w = 48; }
    else if (n < 4352) { local = n - 2304;   h = 32; w = 64; }
    else               { local = n - 4352;   h = 24; w = 40; }
    int rem = local % (h * w);
    int wb_cnt = w >> 1;
    int blk = rem >> 2, within = rem & 3;
    int hb = blk / wb_cnt, wb = blk % wb_cnt;
    row = hb * 2 + (within >> 1);
    col = wb * 2 + (within & 1);
    ih = h; iw = w;
}

// RoPE tables, fp32 math only (angle <= 47 rad; sinf/cosf abs err ~5e-6)
__global__ void cossin_kernel()
{
    int idx = blockIdx.x * blockDim.x + threadIdx.x;
    if (idx >= NTOK * 36) return;
    int n = idx / 36, d = idx % 36;
    int row, col, ih, iw;
    token_pos(n, row, col, ih, iw);
    int j = (d < 18) ? d : d - 18;
    float p = (d < 18) ? (float)row : (float)col;
    // inv = 10000^{-j/18} = exp(-j * ln(10000)/18)
    float inv = __expf(-(float)j * 0.5117865387079628f);
    float ang = p * inv;
    g_cos[idx] = cosf(ang);
    g_sin[idx] = sinf(ang);
}

// Bilinear pos-embed add; integer-exact bilerp setup (no FP64)
__global__ void posadd_kernel(const float* __restrict__ pos_table)
{
    int n = blockIdx.x;
    int row, col, ih, iw;
    token_pos(n, row, col, ih, iw);
    int hd = ih - 1, wd = iw - 1;
    int hnum = 47 * row, wnum = 47 * col;
    int hf = hnum / hd, wf = wnum / wd;
    float dh = (float)(hnum - hf * hd) / (float)hd;
    float dw = (float)(wnum - wf * wd) / (float)wd;
    int hc = min(hf + 1, 47), wc = min(wf + 1, 47);
    float w00 = (1.f - dh) * (1.f - dw);
    float w01 = (1.f - dh) * dw;
    float w10 = dh * (1.f - dw);
    float w11 = dh * dw;
    const float* p00 = pos_table + (size_t)(hf * 48 + wf) * DMODEL;
    const float* p01 = pos_table + (size_t)(hf * 48 + wc) * DMODEL;
    const float* p10 = pos_table + (size_t)(hc * 48 + wf) * DMODEL;
    const float* p11 = pos_table + (size_t)(hc * 48 + wc) * DMODEL;
    float* xr = g_x + (size_t)n * DMODEL;
    for (int d = threadIdx.x; d < DMODEL; d += blockDim.x)
        xr[d] += p00[d] * w00 + p01[d] * w01 + p10[d] * w10 + p11[d] * w11;
}

// ---------------------------------------------------------------------------
// Fused fp32->fp16 convert for ALL prep streams in one launch.
// ---------------------------------------------------------------------------
#define NSEG 13
struct ConvJobs {
    const float4* src[NSEG];
    uint2*        dst[NSEG];
    int           off[NSEG + 1];
};

__global__ void convall(ConvJobs J, int total)
{
    int i = blockIdx.x * blockDim.x + threadIdx.x;
    if (i >= total) return;
    int s = 0;
#pragma unroll
    for (int k = 1; k < NSEG; k++) s += (i >= J.off[k]) ? 1 : 0;
    int local = i - J.off[s];
    float4 v = J.src[s][local];
    __half2 lo = __floats2half2_rn(v.x, v.y);
    __half2 hi = __floats2half2_rn(v.z, v.w);
    J.dst[s][local] =
        make_uint2(*reinterpret_cast<uint32_t*>(&lo), *reinterpret_cast<uint32_t*>(&hi));
}

__device__ __forceinline__ float warp_sum(float v)
{
#pragma unroll
    for (int o = 16; o > 0; o >>= 1) v += __shfl_xor_sync(0xffffffffu, v, o);
    return v;
}

// LayerNorm fp32 in -> fp16 out
__global__ void ln_h(const float* __restrict__ in, __half* __restrict__ out,
                     const float* __restrict__ s, const float* __restrict__ b)
{
    __shared__ float sh[9];
    __shared__ float stat[2];
    int n = blockIdx.x;
    const float* xr = in + (size_t)n * DMODEL;
    int t = threadIdx.x, wid = t >> 5, lane = t & 31;

    float vals[4];
    float lsum = 0.f;
#pragma unroll
    for (int i = 0; i < 4; i++) { vals[i] = xr[t + i * 288]; lsum += vals[i]; }
    float ws = warp_sum(lsum);
    if (lane == 0) sh[wid] = ws;
    __syncthreads();
    if (t == 0) {
        float tot = 0.f;
#pragma unroll
        for (int i = 0; i < 9; i++) tot += sh[i];
        stat[0] = tot * (1.0f / DMODEL);
    }
    __syncthreads();
    float mu = stat[0];
    float lvar = 0.f;
#pragma unroll
    for (int i = 0; i < 4; i++) { float d = vals[i] - mu; lvar += d * d; }
    ws = warp_sum(lvar);
    __syncthreads();
    if (lane == 0) sh[wid] = ws;
    __syncthreads();
    if (t == 0) {
        float tot = 0.f;
#pragma unroll
        for (int i = 0; i < 9; i++) tot += sh[i];
        stat[1] = rsqrtf(tot * (1.0f / DMODEL) + 1e-6f);
    }
    __syncthreads();
    float r = stat[1];
    __half* orow = out + (size_t)n * DMODEL;
#pragma unroll
    for (int i = 0; i < 4; i++) {
        int d = t + i * 288;
        orow[d] = __float2half_rn((vals[i] - mu) * r * s[d] + b[d]);
    }
}

// RoPE in-place on fp16 qkv
__global__ void rope_h()
{
    int n = blockIdx.x;
    int t = threadIdx.x;
    int h = t / 36, d = t % 36;
    float c = g_cos[n * 36 + d];
    float s = g_sin[n * 36 + d];
    __half* q = g_qkvh + (size_t)n * QKVW + h * HDIM;
    __half* k = q + DMODEL;
    float q0 = __half2float(q[d]), q1 = __half2float(q[d + 36]);
    q[d]      = __float2half_rn(q0 * c - q1 * s);
    q[d + 36] = __float2half_rn(q1 * c + q0 * s);
    float k0 = __half2float(k[d]), k1 = __half2float(k[d + 36]);
    k[d]      = __float2half_rn(k0 * c - k1 * s);
    k[d + 36] = __float2half_rn(k1 * c + k0 * s);
}

// ---------------------------------------------------------------------------
// mma / misc helpers
// ---------------------------------------------------------------------------
__device__ __forceinline__ void mma_f16(float c[4],
                                        uint32_t a0, uint32_t a1, uint32_t a2, uint32_t a3,
                                        uint32_t b0, uint32_t b1)
{
    asm volatile(
        "mma.sync.aligned.m16n8k16.row.col.f32.f16.f16.f32 "
        "{%0,%1,%2,%3}, {%4,%5,%6,%7}, {%8,%9}, {%0,%1,%2,%3};\n"
        : "+f"(c[0]), "+f"(c[1]), "+f"(c[2]), "+f"(c[3])
        : "r"(a0), "r"(a1), "r"(a2), "r"(a3), "r"(b0), "r"(b1));
}

// fast gelu: HW tanh approx (MUFU.TANH)
__device__ __forceinline__ float gelu_tanh(float x)
{
    float u = 0.7978845608028654f * (x + 0.044715f * x * x * x);
    float t;
    asm("tanh.approx.f32 %0, %1;" : "=f"(t) : "f"(u));
    return 0.5f * x * (1.f + t);
}

__device__ __forceinline__ uint32_t pack_h2(float lo, float hi)
{
    __half2 h = __floats2half2_rn(lo, hi);
    return *reinterpret_cast<uint32_t*>(&h);
}

// ---------------------------------------------------------------------------
// GEMM v4: A fp16 [M,K] row-major, B fp16 [K,N] row-major, C fp32 or fp16.
//   Block 128x128, BK=32, 4 stages (dynamic smem), cp.async wait_group 2.
//   8 warps 2(M) x 4(N), warp tile 64x32.  (unchanged from R13 — verified)
// ---------------------------------------------------------------------------
#define EPI_BIAS      1
#define EPI_BIAS_GELU 2
#define EPI_BIAS_RES  3

#define G4_AST  20
#define G4_BST  68
#define G4_BOFF 2560
#define G4_STG  4736
#define G4_NSTG 4
#define G4_SMEM (G4_NSTG * G4_STG * 4)

template<int EPI, bool OUTH>
__global__ void __launch_bounds__(256, 2)
gemm3(const __half* __restrict__ A, int lda,
      const __half* __restrict__ B, int ldb,
      void* __restrict__ Cv, int ldc,
      const float* __restrict__ bias,
      const float* __restrict__ Res, int ldr,
      int Md, int Nd, int Kd)
{
    extern __shared__ uint32_t smbuf[];

    const int tid  = threadIdx.x;
    const int brow = blockIdx.y * 128;
    const int bcol = blockIdx.x * 128;
    const int w    = tid >> 5;
    const int lane = tid & 31;
    const int g    = lane >> 2;
    const int q    = lane & 3;
    const int wm   = w & 1;
    const int wn   = w >> 1;

    uint32_t smbase = (uint32_t)__cvta_generic_to_shared(smbuf);

    int aok[2], ak8[2];
    uint32_t sa[2];
    const __half* ga[2];
#pragma unroll
    for (int i = 0; i < 2; i++) {
        int c = tid + i * 256;
        int row = c >> 2;
        ak8[i] = (c & 3) * 8;
        aok[i] = (brow + row) < Md;
        sa[i] = smbase + (uint32_t)(row * G4_AST + (c & 3) * 4) * 4;
        ga[i] = A + (long long)(brow + row) * lda + ak8[i];
    }
    int bkr[2], bok[2];
    uint32_t sb[2];
    const __half* gb[2];
#pragma unroll
    for (int i = 0; i < 2; i++) {
        int c = tid + i * 256;
        bkr[i] = c >> 4;
        int n8 = (c & 15) * 8;
        bok[i] = (bcol + n8) < Nd;
        sb[i] = smbase + (uint32_t)(G4_BOFF + bkr[i] * G4_BST + (c & 15) * 4) * 4;
        gb[i] = B + (long long)bkr[i] * ldb + bcol + n8;
    }

    float acc[4][4][4];
#pragma unroll
    for (int i = 0; i < 4; i++)
#pragma unroll
        for (int j = 0; j < 4; j++)
#pragma unroll
            for (int r = 0; r < 4; r++) acc[i][j][r] = 0.f;

    const int ntk = (Kd + 31) >> 5;

    auto load_stage = [&](int k0, int st) {
        uint32_t off = (uint32_t)(st * G4_STG) * 4;
#pragma unroll
        for (int i = 0; i < 2; i++) {
            int va = (aok[i] && (k0 + ak8[i]) < Kd) ? 16 : 0;
            asm volatile("cp.async.cg.shared.global [%0], [%1], 16, %2;"
                         :: "r"(sa[i] + off), "l"(ga[i] + k0), "r"(va));
        }
#pragma unroll
        for (int i = 0; i < 2; i++) {
            int vb = (bok[i] && (k0 + bkr[i]) < Kd) ? 16 : 0;
            asm volatile("cp.async.cg.shared.global [%0], [%1], 16, %2;"
                         :: "r"(sb[i] + off), "l"(gb[i] + (long long)k0 * ldb), "r"(vb));
        }
    };

    load_stage(0, 0);
    asm volatile("cp.async.commit_group;");
    if (ntk > 1) load_stage(32, 1);
    asm volatile("cp.async.commit_group;");
    if (ntk > 2) load_stage(64, 2);
    asm volatile("cp.async.commit_group;");

    const int a_row = wm * 64 + (lane & 15);
    const uint32_t abase = smbase + (uint32_t)(a_row * G4_AST + (lane >> 4) * 4) * 4;
    const uint32_t bbase = smbase + (uint32_t)G4_BOFF * 4 +
        (uint32_t)((lane & 15) * G4_BST * 4 + (wn * 32 + (lane >> 4) * 8) * 2);

    for (int kt = 0; kt < ntk; kt++) {
        asm volatile("cp.async.wait_group 2;");
        __syncthreads();
        uint32_t soff = (uint32_t)((kt & 3) * G4_STG) * 4;

#pragma unroll
        for (int kg = 0; kg < 2; kg++) {
            uint32_t akg = soff + (uint32_t)(kg * 8) * 4;
            uint32_t bkg = soff + (uint32_t)(kg * 16 * G4_BST) * 4;

            uint32_t af[4][4], bf[2][4];
#pragma unroll
            for (int mt = 0; mt < 4; mt++)
                asm volatile("ldmatrix.sync.aligned.m8n8.x4.shared.b16 {%0,%1,%2,%3}, [%4];"
                             : "=r"(af[mt][0]), "=r"(af[mt][1]), "=r"(af[mt][2]), "=r"(af[mt][3])
                             : "r"(abase + akg + (uint32_t)(mt * 16 * G4_AST) * 4));
#pragma unroll
            for (int ng = 0; ng < 2; ng++)
                asm volatile("ldmatrix.sync.aligned.m8n8.x4.trans.shared.b16 {%0,%1,%2,%3}, [%4];"
                             : "=r"(bf[ng][0]), "=r"(bf[ng][1]), "=r"(bf[ng][2]), "=r"(bf[ng][3])
                             : "r"(bbase + bkg + (uint32_t)(ng * 32)));

#pragma unroll
            for (int mt = 0; mt < 4; mt++)
#pragma unroll
                for (int j = 0; j < 4; j++)
                    mma_f16(acc[mt][j],
                            af[mt][0], af[mt][1], af[mt][2], af[mt][3],
                            bf[j >> 1][(j & 1) * 2], bf[j >> 1][(j & 1) * 2 + 1]);
        }

        int ktn = kt + 3;
        if (ktn < ntk)
            load_stage(ktn * 32, ktn & 3);
        asm volatile("cp.async.commit_group;");
    }

    float*  Cf = (float*)Cv;
    __half* Ch = (__half*)Cv;
#pragma unroll
    for (int mt = 0; mt < 4; mt++) {
#pragma unroll
        for (int hh = 0; hh < 2; hh++) {
            int r = brow + wm * 64 + mt * 16 + g + 8 * hh;
            if (r >= Md) continue;
#pragma unroll
            for (int j = 0; j < 4; j++) {
                int c = bcol + wn * 32 + j * 8 + 2 * q;
                if (c >= Nd) continue;
                float v0 = acc[mt][j][hh * 2];
                float v1 = acc[mt][j][hh * 2 + 1];
                v0 += bias[c]; v1 += bias[c + 1];
                if (EPI == EPI_BIAS_GELU) { v0 = gelu_tanh(v0); v1 = gelu_tanh(v1); }
                if (EPI == EPI_BIAS_RES)  {
                    v0 += Res[(long long)r * ldr + c];
                    v1 += Res[(long long)r * ldr + c + 1];
                }
                if (OUTH) {
                    __half2 hv = __floats2half2_rn(v0, v1);
                    *reinterpret_cast<__half2*>(Ch + (long long)r * ldc + c) = hv;
                } else {
                    *reinterpret_cast<float2*>(Cf + (long long)r * ldc + c) = make_float2(v0, v1);
                }
            }
        }
    }
}

// ---------------------------------------------------------------------------
// Fused flash attention v2 (unchanged — verified).
// ---------------------------------------------------------------------------
#define FROW 44

__global__ void __launch_bounds__(256, 2)
flash_h(const __half* __restrict__ qkv, __half* __restrict__ attn)
{
    __shared__ uint32_t Qs[128 * FROW];
    __shared__ uint32_t Ks[64 * FROW];
    __shared__ uint32_t Vs[64 * FROW];

    int t = blockIdx.x;
    int head = blockIdx.y;
    int st, S, q0;
    if (t < 18)      { st = 0;    S = 2304; q0 = t * 128; }
    else if (t < 34) { st = 2304; S = 2048; q0 = (t - 18) * 128; }
    else if (t < 42) { st = 4352; S = 960;  q0 = (t - 34) * 128; }
    else             { st = 5312; S = 960;  q0 = (t - 42) * 128; }

    const int tid  = threadIdx.x;
    const int w    = tid >> 5;
    const int lane = tid & 31;
    const int g    = lane >> 2;
    const int q    = lane & 3;
    const int rowbase = w * 16;

    const float scale = 0.11785113019775793f;

    for (int s = tid; s < 128 * 9; s += 256) {
        int row = s / 9, c = s % 9;
        uint4 v = make_uint4(0, 0, 0, 0);
        if (q0 + row < S)
            v = *reinterpret_cast<const uint4*>(
                qkv + (size_t)(st + q0 + row) * QKVW + head * HDIM + c * 8);
        *reinterpret_cast<uint4*>(&Qs[row * FROW + c * 4]) = v;
    }
    for (int s = tid; s < 128 * 8; s += 256) Qs[(s >> 3) * FROW + 36 + (s & 7)] = 0;
    for (int s = tid; s < 64 * 8; s += 256) {
        Ks[(s >> 3) * FROW + 36 + (s & 7)] = 0;
        Vs[(s >> 3) * FROW + 36 + (s & 7)] = 0;
    }

    float m0 = -1e30f, m1 = -1e30f, l0 = 0.f, l1 = 0.f;
    float O[10][4];
#pragma unroll
    for (int i = 0; i < 10; i++)
#pragma unroll
        for (int r = 0; r < 4; r++) O[i][r] = 0.f;

    uint32_t smQ = (uint32_t)__cvta_generic_to_shared(Qs);
    uint32_t smK = (uint32_t)__cvta_generic_to_shared(Ks);
    uint32_t smV = (uint32_t)__cvta_generic_to_shared(Vs);
    const uint32_t qsb = smQ + (uint32_t)((rowbase + (lane & 15)) * FROW + (lane >> 4) * 4) * 4;
    const uint32_t ksb = smK + (uint32_t)((((lane & 7) + ((lane >> 4) << 3)) * FROW) +
                                          ((lane >> 3) & 1) * 4) * 4;
    const uint32_t vsb = smV + (uint32_t)(((lane & 15) * FROW) + (lane >> 4) * 4) * 4;

    const int nkv = S >> 6;
    for (int j = 0; j < nkv; j++) {
        __syncthreads();
        const int kv0 = j * 64;
        for (int s = tid; s < 64 * 9; s += 256) {
            int row = s / 9, c = s % 9;
            *reinterpret_cast<uint4*>(&Ks[row * FROW + c * 4]) =
                *reinterpret_cast<const uint4*>(
                    qkv + (size_t)(st + kv0 + row) * QKVW + DMODEL + head * HDIM + c * 8);
        }
        for (int s = tid; s < 64 * 9; s += 256) {
            int row = s / 9, c = s % 9;
            *reinterpret_cast<uint4*>(&Vs[row * FROW + c * 4]) =
                *reinterpret_cast<const uint4*>(
                    qkv + (size_t)(st + kv0 + row) * QKVW + 2 * DMODEL + head * HDIM + c * 8);
        }
        __syncthreads();

        float acc[8][4];
#pragma unroll
        for (int i = 0; i < 8; i++)
#pragma unroll
            for (int r = 0; r < 4; r++) acc[i][r] = 0.f;

#pragma unroll
        for (int kb = 0; kb < 5; kb++) {
            uint32_t af[4];
            asm volatile("ldmatrix.sync.aligned.m8n8.x4.shared.b16 {%0,%1,%2,%3}, [%4];"
                         : "=r"(af[0]), "=r"(af[1]), "=r"(af[2]), "=r"(af[3])
                         : "r"(qsb + (uint32_t)(kb * 8) * 4));
#pragma unroll
            for (int nt4 = 0; nt4 < 4; nt4++) {
                uint32_t bf[4];
                asm volatile("ldmatrix.sync.aligned.m8n8.x4.shared.b16 {%0,%1,%2,%3}, [%4];"
                             : "=r"(bf[0]), "=r"(bf[1]), "=r"(bf[2]), "=r"(bf[3])
                             : "r"(ksb + (uint32_t)(nt4 * 16 * FROW + kb * 8) * 4));
                mma_f16(acc[2 * nt4    ], af[0], af[1], af[2], af[3], bf[0], bf[1]);
                mma_f16(acc[2 * nt4 + 1], af[0], af[1], af[2], af[3], bf[2], bf[3]);
            }
        }
#pragma unroll
        for (int i = 0; i < 8; i++)
#pragma unroll
            for (int r = 0; r < 4; r++) acc[i][r] *= scale;

        float mx0 = -1e30f, mx1 = -1e30f;
#pragma unroll
        for (int i = 0; i < 8; i++) {
            mx0 = fmaxf(mx0, fmaxf(acc[i][0], acc[i][1]));
            mx1 = fmaxf(mx1, fmaxf(acc[i][2], acc[i][3]));
        }
        mx0 = fmaxf(mx0, __shfl_xor_sync(0xffffffffu, mx0, 1));
        mx0 = fmaxf(mx0, __shfl_xor_sync(0xffffffffu, mx0, 2));
        mx1 = fmaxf(mx1, __shfl_xor_sync(0xffffffffu, mx1, 1));
        mx1 = fmaxf(mx1, __shfl_xor_sync(0xffffffffu, mx1, 2));
        float mn0 = fmaxf(m0, mx0), mn1 = fmaxf(m1, mx1);
        float al0 = __expf(m0 - mn0), al1 = __expf(m1 - mn1);
        m0 = mn0; m1 = mn1;

        float rs0 = 0.f, rs1 = 0.f;
#pragma unroll
        for (int i = 0; i < 8; i++) {
            acc[i][0] = __expf(acc[i][0] - mn0);
            acc[i][1] = __expf(acc[i][1] - mn0);
            acc[i][2] = __expf(acc[i][2] - mn1);
            acc[i][3] = __expf(acc[i][3] - mn1);
            rs0 += acc[i][0] + acc[i][1];
            rs1 += acc[i][2] + acc[i][3];
        }
        rs0 += __shfl_xor_sync(0xffffffffu, rs0, 1);
        rs0 += __shfl_xor_sync(0xffffffffu, rs0, 2);
        rs1 += __shfl_xor_sync(0xffffffffu, rs1, 1);
        rs1 += __shfl_xor_sync(0xffffffffu, rs1, 2);
        l0 = l0 * al0 + rs0;
        l1 = l1 * al1 + rs1;

#pragma unroll
        for (int i = 0; i < 10; i++) {
            O[i][0] *= al0; O[i][1] *= al0;
            O[i][2] *= al1; O[i][3] *= al1;
        }

        uint32_t pa[4][4];
#pragma unroll
        for (int kb = 0; kb < 4; kb++) {
            pa[kb][0] = pack_h2(acc[2 * kb][0],     acc[2 * kb][1]);
            pa[kb][1] = pack_h2(acc[2 * kb][2],     acc[2 * kb][3]);
            pa[kb][2] = pack_h2(acc[2 * kb + 1][0], acc[2 * kb + 1][1]);
            pa[kb][3] = pack_h2(acc[2 * kb + 1][2], acc[2 * kb + 1][3]);
        }

#pragma unroll
        for (int kb = 0; kb < 4; kb++) {
#pragma unroll
            for (int vt = 0; vt < 5; vt++) {
                uint32_t bf[4];
                asm volatile("ldmatrix.sync.aligned.m8n8.x4.trans.shared.b16 {%0,%1,%2,%3}, [%4];"
                             : "=r"(bf[0]), "=r"(bf[1]), "=r"(bf[2]), "=r"(bf[3])
                             : "r"(vsb + (uint32_t)(kb * 16 * FROW + vt * 8) * 4));
                mma_f16(O[2 * vt    ], pa[kb][0], pa[kb][1], pa[kb][2], pa[kb][3], bf[0], bf[1]);
                mma_f16(O[2 * vt + 1], pa[kb][0], pa[kb][1], pa[kb][2], pa[kb][3], bf[2], bf[3]);
            }
        }
    }

#pragma unroll
    for (int h = 0; h < 2; h++) {
        int r = rowbase + g + 8 * h;
        if (q0 + r >= S) continue;
        float inv = 1.0f / (h == 0 ? l0 : l1);
#pragma unroll
        for (int ntl = 0; ntl < 9; ntl++) {
            int c = ntl * 8 + 2 * q;
            __half2 hv = __floats2half2_rn(O[ntl][2 * h] * inv, O[ntl][2 * h + 1] * inv);
            *reinterpret_cast<__half2*>(
                attn + (size_t)(st + q0 + r) * DMODEL + head * HDIM + c) = hv;
        }
    }
}

// ---------------------------------------------------------------------------
// Host launcher
// ---------------------------------------------------------------------------
#define SYMF(p, s) do { void* _t; cudaGetSymbolAddress(&_t, s); p = (float*)_t; } while (0)
#define SYMH(p, s) do { void* _t; cudaGetSymbolAddress(&_t, s); p = (__half*)_t; } while (0)

static inline dim3 ggrid3(int Md, int Nd) {
    return dim3((Nd + 127) / 128, (Md + 127) / 128);
}

extern "C" void kernel_launch(void* const* d_in, const int* in_sizes, int n_in,
                              void* d_out, int out_size)
{
    (void)in_sizes; (void)n_in; (void)out_size;
    const float* pixel    = (const float*)d_in[0];
    const float* patch_w  = (const float*)d_in[2];
    const float* patch_b  = (const float*)d_in[3];
    const float* pos_tab  = (const float*)d_in[4];
    const float* ln1_s    = (const float*)d_in[5];
    const float* ln1_b    = (const float*)d_in[6];
    const float* qkv_w    = (const float*)d_in[7];
    const float* qkv_b    = (const float*)d_in[8];
    const float* proj_w   = (const float*)d_in[9];
    const float* proj_b   = (const float*)d_in[10];
    const float* ln2_s    = (const float*)d_in[11];
    const float* ln2_b    = (const float*)d_in[12];
    const float* fc1_w    = (const float*)d_in[13];
    const float* fc1_b    = (const float*)d_in[14];
    const float* fc2_w    = (const float*)d_in[15];
    const float* fc2_b    = (const float*)d_in[16];
    const float* m_ln_s   = (const float*)d_in[17];
    const float* m_ln_b   = (const float*)d_in[18];
    const float* m_fc1_w  = (const float*)d_in[19];
    const float* m_fc1_b  = (const float*)d_in[20];
    const float* m_fc2_w  = (const float*)d_in[21];
    const float* m_fc2_b  = (const float*)d_in[22];
    float* out = (float*)d_out;

    float *x;
    __half *pix, *hh, *qkvh, *attnh, *mlph, *wt;
    SYMF(x, g_x);
    SYMH(pix, g_pix); SYMH(hh, g_hh); SYMH(qkvh, g_qkvh);
    SYMH(attnh, g_attnh); SYMH(mlph, g_mlph); SYMH(wt, g_wt);

    static bool attr_set = false;
    if (!attr_set) {
        cudaFuncSetAttribute(gemm3<EPI_BIAS, false>,
                             cudaFuncAttributeMaxDynamicSharedMemorySize, G4_SMEM);
        cudaFuncSetAttribute(gemm3<EPI_BIAS, true>,
                             cudaFuncAttributeMaxDynamicSharedMemorySize, G4_SMEM);
        cudaFuncSetAttribute(gemm3<EPI_BIAS_GELU, true>,
                             cudaFuncAttributeMaxDynamicSharedMemorySize, G4_SMEM);
        cudaFuncSetAttribute(gemm3<EPI_BIAS_RES, false>,
                             cudaFuncAttributeMaxDynamicSharedMemorySize, G4_SMEM);
        attr_set = true;
    }

    // ---- fused fp32->fp16 conversion (single launch, all streams)
    {
        ConvJobs J;
        const float* srcs[NSEG] = {
            pixel, patch_w,
            qkv_w,  qkv_w  + SZ_QKV,
            proj_w, proj_w + SZ_PROJ,
            fc1_w,  fc1_w  + SZ_FC1,
            fc2_w,  fc2_w  + SZ_FC2,
            m_fc1_w, m_fc2_w, nullptr };
        __half* dsts[NSEG] = {
            pix, wt + OFF_PATCH,
            wt + OFF_QKV,  wt + OFF_QKV + SZ_QKV,
            wt + OFF_PROJ, wt + OFF_PROJ + SZ_PROJ,
            wt + OFF_FC1,  wt + OFF_FC1 + SZ_FC1,
            wt + OFF_FC2,  wt + OFF_FC2 + SZ_FC2,
            wt + OFF_MFC1, wt + OFF_MFC2, nullptr };
        long long sizes[NSEG] = {
            (long long)NTOK * CIN, (long long)SZ_PATCH,
            (long long)SZ_QKV, (long long)SZ_QKV,
            (long long)SZ_PROJ, (long long)SZ_PROJ,
            (long long)SZ_FC1, (long long)SZ_FC1,
            (long long)SZ_FC2, (long long)SZ_FC2,
            (long long)SZ_MFC1, (long long)SZ_MFC2, 0 };
        srcs[12]  = m_fc2_w;      // dummy (size 0, never touched)
        dsts[12]  = wt + OFF_MFC2;
        int off = 0;
        for (int s = 0; s < NSEG; s++) {
            J.src[s] = (const float4*)srcs[s];
            J.dst[s] = (uint2*)dsts[s];
            J.off[s] = off;
            off += (int)(sizes[s] / 4);
        }
        J.off[NSEG] = off;
        convall<<<(off + 255) / 256, 256>>>(J, off);
    }

    cossin_kernel<<<(NTOK * 36 + 255) / 256, 256>>>();

    // Patch embed -> x (fp32)
    gemm3<EPI_BIAS, false><<<ggrid3(NTOK, DMODEL), 256, G4_SMEM>>>(
        pix, CIN, wt + OFF_PATCH, DMODEL, x, DMODEL,
        patch_b, nullptr, 0, NTOK, DMODEL, CIN);

    posadd_kernel<<<NTOK, 288>>>(pos_tab);

    for (int l = 0; l < 2; l++) {
        ln_h<<<NTOK, 288>>>(x, hh, ln1_s + l * DMODEL, ln1_b + l * DMODEL);

        gemm3<EPI_BIAS, true><<<ggrid3(NTOK, QKVW), 256, G4_SMEM>>>(
            hh, DMODEL, wt + OFF_QKV + l * SZ_QKV, QKVW, qkvh, QKVW,
            qkv_b + (size_t)l * QKVW, nullptr, 0, NTOK, QKVW, DMODEL);

        rope_h<<<NTOK, 576>>>();

        flash_h<<<dim3(50, HEADS), 256>>>(qkvh, attnh);

        gemm3<EPI_BIAS_RES, false><<<ggrid3(NTOK, DMODEL), 256, G4_SMEM>>>(
            attnh, DMODEL, wt + OFF_PROJ + l * SZ_PROJ, DMODEL, x, DMODEL,
            proj_b + (size_t)l * DMODEL, x, DMODEL, NTOK, DMODEL, DMODEL);

        ln_h<<<NTOK, 288>>>(x, hh, ln2_s + l * DMODEL, ln2_b + l * DMODEL);

        gemm3<EPI_BIAS_GELU, true><<<ggrid3(NTOK, IDIM), 256, G4_SMEM>>>(
            hh, DMODEL, wt + OFF_FC1 + l * SZ_FC1, IDIM, mlph, IDIM,
            fc1_b + (size_t)l * IDIM, nullptr, 0, NTOK, IDIM, DMODEL);

        gemm3<EPI_BIAS_RES, false><<<ggrid3(NTOK, DMODEL), 256, G4_SMEM>>>(
            mlph, IDIM, wt + OFF_FC2 + l * SZ_FC2, DMODEL, x, DMODEL,
            fc2_b + (size_t)l * DMODEL, x, DMODEL, NTOK, DMODEL, IDIM);
    }

    // merger
    ln_h<<<NTOK, 288>>>(x, hh, m_ln_s, m_ln_b);   // hh viewed as [1568][4608]

    gemm3<EPI_BIAS_GELU, true><<<ggrid3(MROWS, MD4), 256, G4_SMEM>>>(
        hh, MD4, wt + OFF_MFC1, MD4, mlph, MD4,
        m_fc1_b, nullptr, 0, MROWS, MD4, MD4);

    gemm3<EPI_BIAS, false><<<ggrid3(MROWS, DOUT), 256, G4_SMEM>>>(
        mlph, MD4, wt + OFF_MFC2, DOUT, out, DOUT,
        m_fc2_b, nullptr, 0, MROWS, DOUT, MD4);
}